// round 1
// baseline (speedup 1.0000x reference)
#include <cuda_runtime.h>
#include <cstddef>

#define BB   2
#define NN   2048
#define DIMX 2048
#define NH   32
#define NKV  8
#define HD   64
#define KVW  (2*NKV*HD)   // 1024

// Scratch (allocation-free rule: __device__ globals)
__device__ float g_q[(size_t)BB*NN*DIMX];      // 32 MB
__device__ float g_kv[(size_t)BB*NN*KVW];      // 16 MB
__device__ float g_attn[(size_t)BB*NN*DIMX];   // 32 MB

// ---------------- SGEMM: C[M,Nc] = A[M,K] @ W[K,Nc], fp32 ----------------
// 64x64 tile, BK=16, 256 threads, 4x4 micro-tile.
__global__ __launch_bounds__(256) void sgemm_kernel(
    const float* __restrict__ A, const float* __restrict__ W,
    float* __restrict__ C, int M, int Nc, int K)
{
    __shared__ float As[16][64];
    __shared__ float Bs[16][64];
    const int tid = threadIdx.x;
    const int tx = tid % 16, ty = tid / 16;
    const int bx = blockIdx.x, by = blockIdx.y;

    const int rowA  = by * 64 + (tid >> 2);   // 0..63
    const int colA4 = (tid & 3) * 4;          // 0,4,8,12
    const int rowB  = tid >> 4;               // 0..15
    const int colB4 = (tid & 15) * 4;         // 0..60

    float acc[4][4] = {};

    for (int k0 = 0; k0 < K; k0 += 16) {
        float4 a4 = *(const float4*)(A + (size_t)rowA * K + k0 + colA4);
        As[colA4 + 0][tid >> 2] = a4.x;
        As[colA4 + 1][tid >> 2] = a4.y;
        As[colA4 + 2][tid >> 2] = a4.z;
        As[colA4 + 3][tid >> 2] = a4.w;
        *(float4*)&Bs[rowB][colB4] =
            *(const float4*)(W + (size_t)(k0 + rowB) * Nc + bx * 64 + colB4);
        __syncthreads();

        #pragma unroll
        for (int k = 0; k < 16; k++) {
            float4 av = *(const float4*)&As[k][ty * 4];
            float4 bv = *(const float4*)&Bs[k][tx * 4];
            float a_[4] = {av.x, av.y, av.z, av.w};
            float b_[4] = {bv.x, bv.y, bv.z, bv.w};
            #pragma unroll
            for (int i = 0; i < 4; i++)
                #pragma unroll
                for (int j = 0; j < 4; j++)
                    acc[i][j] = fmaf(a_[i], b_[j], acc[i][j]);
        }
        __syncthreads();
    }

    #pragma unroll
    for (int i = 0; i < 4; i++) {
        float4 v = make_float4(acc[i][0], acc[i][1], acc[i][2], acc[i][3]);
        *(float4*)(C + (size_t)(by * 64 + ty * 4 + i) * Nc + bx * 64 + tx * 4) = v;
    }
}

// ---------------- RoPE (interleaved pairs) ----------------
// data[row][h][d], row = b*N+n, rowStride = nHeads-equivalent width.
__global__ void rope_kernel(float* __restrict__ data,
                            const float* __restrict__ cosT,
                            const float* __restrict__ sinT,
                            int nHeads, int rowStride, int total)
{
    int i = blockIdx.x * blockDim.x + threadIdx.x;
    if (i >= total) return;
    int p   = i & 31;                    // freq index 0..31
    int h   = (i >> 5) % nHeads;
    int row = i / (32 * nHeads);         // 0..B*N-1
    int n   = row % NN;
    float c = cosT[n * 32 + p];
    float s = sinT[n * 32 + p];
    float* ptr = data + (size_t)row * rowStride + h * HD + 2 * p;
    float e = ptr[0], o = ptr[1];
    ptr[0] = e * c - o * s;
    ptr[1] = e * s + o * c;
}

// ---------------- Flash attention (causal, GQA head%8) ----------------
// 1 thread = 1 query row. BM=128 rows/CTA, BN=64 keys/tile.
#define FBM 128
#define FBN 64
#define FLASH_SMEM ((4096 + 4096 + FBM*65) * 4)   // K + V + S(padded) = 66048 B

__global__ __launch_bounds__(FBM) void flash_kernel(
    const float* __restrict__ Q, const float* __restrict__ KV,
    float* __restrict__ O)
{
    extern __shared__ float sm[];
    float* Ks = sm;            // 64*64
    float* Vs = sm + 4096;     // 64*64
    float* Ss = sm + 8192;     // 128*65 (padded rows, conflict-free)

    const int t    = threadIdx.x;
    const int qb   = blockIdx.x;
    const int head = blockIdx.y;
    const int b    = blockIdx.z;
    const int kvh  = head & (NKV - 1);   // jnp.tile => head % 8
    const int qpos = qb * FBM + t;

    float4 q4[16], o4[16];
    const float4* qp = (const float4*)(Q + ((size_t)(b * NN) + qpos) * DIMX + head * HD);
    #pragma unroll
    for (int i = 0; i < 16; i++) { q4[i] = qp[i]; o4[i] = make_float4(0.f, 0.f, 0.f, 0.f); }

    float m = -1e30f, l = 0.f;
    const int kbmax = 2 * qb + 1;  // causal: last key block touching this q block

    for (int kb = 0; kb <= kbmax; kb++) {
        // cooperative K/V tile load (rows of kv: 1024 floats = 256 float4)
        const float4* kvbase = (const float4*)KV;
        #pragma unroll
        for (int i = 0; i < 8; i++) {
            int idx = t + i * FBM;               // 0..1023
            int r = idx >> 4, c = idx & 15;
            size_t g = ((size_t)(b * NN) + (size_t)kb * FBN + r) * 256 + kvh * 16 + c;
            ((float4*)Ks)[idx] = kvbase[g];
            ((float4*)Vs)[idx] = kvbase[g + 128];   // v half at +512 floats
        }
        __syncthreads();

        // pass 1: scores
        float bmax = -1e30f;
        const bool needMask = (kb * FBN + FBN - 1) > qpos;
        for (int j = 0; j < FBN; j++) {
            const float4* kr = (const float4*)(Ks + j * 64);
            float s = 0.f;
            #pragma unroll
            for (int i = 0; i < 16; i++) {
                float4 kv4 = kr[i];
                s = fmaf(q4[i].x, kv4.x, s);
                s = fmaf(q4[i].y, kv4.y, s);
                s = fmaf(q4[i].z, kv4.z, s);
                s = fmaf(q4[i].w, kv4.w, s);
            }
            s *= 0.125f;                          // HEAD_DIM^-0.5
            if (needMask && (kb * FBN + j > qpos)) s = -1e30f;
            bmax = fmaxf(bmax, s);
            Ss[t * 65 + j] = s;
        }

        const float newm = fmaxf(m, bmax);
        const float corr = __expf(m - newm);
        l *= corr;
        #pragma unroll
        for (int i = 0; i < 16; i++) {
            o4[i].x *= corr; o4[i].y *= corr; o4[i].z *= corr; o4[i].w *= corr;
        }

        // pass 2: softmax accumulate O
        for (int j = 0; j < FBN; j++) {
            float p = __expf(Ss[t * 65 + j] - newm);
            l += p;
            const float4* vr = (const float4*)(Vs + j * 64);
            #pragma unroll
            for (int i = 0; i < 16; i++) {
                float4 v4 = vr[i];
                o4[i].x = fmaf(p, v4.x, o4[i].x);
                o4[i].y = fmaf(p, v4.y, o4[i].y);
                o4[i].z = fmaf(p, v4.z, o4[i].z);
                o4[i].w = fmaf(p, v4.w, o4[i].w);
            }
        }
        m = newm;
        __syncthreads();
    }

    const float inv = 1.f / l;
    float4* op = (float4*)(O + ((size_t)(b * NN) + qpos) * DIMX + head * HD);
    #pragma unroll
    for (int i = 0; i < 16; i++) {
        o4[i].x *= inv; o4[i].y *= inv; o4[i].z *= inv; o4[i].w *= inv;
        op[i] = o4[i];
    }
}

// ---------------- launch ----------------
extern "C" void kernel_launch(void* const* d_in, const int* in_sizes, int n_in,
                              void* d_out, int out_size)
{
    const float* x   = (const float*)d_in[0];
    const float* Wq  = (const float*)d_in[1];
    const float* Wkv = (const float*)d_in[2];
    const float* Wo  = (const float*)d_in[3];
    const float* rc  = (const float*)d_in[4];
    const float* rs  = (const float*)d_in[5];
    // d_in[6] mask, d_in[7] start_pos: causal-from-0 implemented directly.
    float* out = (float*)d_out;

    float *q, *kv, *attn;
    cudaGetSymbolAddress((void**)&q,    g_q);
    cudaGetSymbolAddress((void**)&kv,   g_kv);
    cudaGetSymbolAddress((void**)&attn, g_attn);

    const int M = BB * NN;  // 4096 (batch folded)

    // q = x @ Wq
    sgemm_kernel<<<dim3(DIMX / 64, M / 64), 256>>>(x, Wq, q, M, DIMX, DIMX);
    // kv = x @ Wkv
    sgemm_kernel<<<dim3(KVW / 64, M / 64), 256>>>(x, Wkv, kv, M, KVW, DIMX);

    // RoPE on q (32 heads) and k (first half of kv row, 8 heads)
    int totalQ = BB * NN * NH * (HD / 2);
    rope_kernel<<<(totalQ + 255) / 256, 256>>>(q, rc, rs, NH, DIMX, totalQ);
    int totalK = BB * NN * NKV * (HD / 2);
    rope_kernel<<<(totalK + 255) / 256, 256>>>(kv, rc, rs, NKV, KVW, totalK);

    // flash attention
    cudaFuncSetAttribute(flash_kernel, cudaFuncAttributeMaxDynamicSharedMemorySize,
                         FLASH_SMEM);
    flash_kernel<<<dim3(NN / FBM, NH, BB), FBM, FLASH_SMEM>>>(q, kv, attn);

    // out = attn @ Wo
    sgemm_kernel<<<dim3(DIMX / 64, M / 64), 256>>>(attn, Wo, out, M, DIMX, DIMX);
}

// round 4
// speedup vs baseline: 1.5920x; 1.5920x over previous
#include <cuda_runtime.h>
#include <cuda_bf16.h>
#include <cstdint>
#include <cstddef>

#define BB   2
#define NN   2048
#define DIMX 2048
#define NH   32
#define NKV  8
#define HD   64
#define KVW  (2*NKV*HD)   // 1024
#define MM   (BB*NN)      // 4096

// ---------------- scratch (__device__ globals; allocation-free rule) ----------------
__device__ float g_q   [(size_t)MM*DIMX];   // 32 MB
__device__ float g_kv  [(size_t)MM*KVW];    // 16 MB
__device__ float g_attn[(size_t)MM*DIMX];   // 32 MB

__device__ __nv_bfloat16 g_xhi [(size_t)MM*DIMX];
__device__ __nv_bfloat16 g_xlo [(size_t)MM*DIMX];
__device__ __nv_bfloat16 g_wqh [(size_t)DIMX*DIMX];
__device__ __nv_bfloat16 g_wql [(size_t)DIMX*DIMX];
__device__ __nv_bfloat16 g_wkvh[(size_t)KVW*DIMX];
__device__ __nv_bfloat16 g_wkvl[(size_t)KVW*DIMX];
__device__ __nv_bfloat16 g_woh [(size_t)DIMX*DIMX];
__device__ __nv_bfloat16 g_wol [(size_t)DIMX*DIMX];
__device__ __nv_bfloat16 g_ahi [(size_t)MM*DIMX];
__device__ __nv_bfloat16 g_alo [(size_t)MM*DIMX];

// ---------------- helpers (baseline PTX ISA only: sm_80-level) ----------------
__device__ __forceinline__ uint32_t smem_u32(const void* p){
    uint32_t a;
    asm("{ .reg .u64 t; cvta.to.shared.u64 t, %1; cvt.u32.u64 %0, t; }" : "=r"(a) : "l"(p));
    return a;
}
__device__ __forceinline__ void cp16(uint32_t dst, const void* src){
    asm volatile("cp.async.cg.shared.global [%0], [%1], 16;" :: "r"(dst), "l"(src));
}

#define LDSM4(r, addr) \
    asm volatile("ldmatrix.sync.aligned.m8n8.x4.shared.b16 {%0,%1,%2,%3}, [%4];" \
        : "=r"((r)[0]), "=r"((r)[1]), "=r"((r)[2]), "=r"((r)[3]) : "r"(addr))

#define MMA16816(d, a, b0, b1) \
    asm volatile("mma.sync.aligned.m16n8k16.row.col.f32.bf16.bf16.f32 " \
        "{%0,%1,%2,%3}, {%4,%5,%6,%7}, {%8,%9}, {%0,%1,%2,%3};" \
        : "+f"((d)[0]), "+f"((d)[1]), "+f"((d)[2]), "+f"((d)[3]) \
        : "r"((a)[0]), "r"((a)[1]), "r"((a)[2]), "r"((a)[3]), "r"(b0), "r"(b1))

// ---------------- conversion passes ----------------
__global__ void split_kernel(const float4* __restrict__ src,
                             __nv_bfloat16* __restrict__ hi, __nv_bfloat16* __restrict__ lo, int n4)
{
    int i = blockIdx.x * blockDim.x + threadIdx.x;
    if (i >= n4) return;
    float4 v = src[i];
    float vv[4] = {v.x, v.y, v.z, v.w};
    #pragma unroll
    for (int j = 0; j < 4; j++) {
        __nv_bfloat16 h = __float2bfloat16(vv[j]);
        hi[4*i + j] = h;
        lo[4*i + j] = __float2bfloat16(vv[j] - __bfloat162float(h));
    }
}

// W [K, Nc] fp32 -> Wt [Nc, K] bf16 hi/lo (K-major rows for the "col" mma operand)
__global__ void transpose_split(const float* __restrict__ W,
                                __nv_bfloat16* __restrict__ hi, __nv_bfloat16* __restrict__ lo,
                                int K, int Nc)
{
    __shared__ float t[32][33];
    int x  = blockIdx.x * 32 + threadIdx.x;   // Nc index
    int y0 = blockIdx.y * 32;                 // K base
    #pragma unroll
    for (int j = 0; j < 32; j += 8)
        t[threadIdx.y + j][threadIdx.x] = W[(size_t)(y0 + threadIdx.y + j) * Nc + x];
    __syncthreads();
    int ox = y0 + threadIdx.x;                // K index (contiguous out)
    int oy = blockIdx.x * 32;                 // Nc base
    #pragma unroll
    for (int j = 0; j < 32; j += 8) {
        float v = t[threadIdx.x][threadIdx.y + j];
        __nv_bfloat16 h = __float2bfloat16(v);
        hi[(size_t)(oy + threadIdx.y + j) * K + ox] = h;
        lo[(size_t)(oy + threadIdx.y + j) * K + ox] = __float2bfloat16(v - __bfloat162float(h));
    }
}

// ---------------- mma.sync bf16-split GEMM ----------------
// C[M,Nc] = (Ahi+Alo)[M,K] @ (Bhi+Blo)^T, B stored [Nc,K] K-major.
// CTA tile 128x128, BK=32, 256 threads, 8 warps (4M x 2N), warp tile 32x64.
// Smem rows padded to 80B: 8 consecutive rows cover all 8 16B-phases mod 128,
// so ldmatrix is conflict-free with no swizzle.
#define TILE_B   10240u               // 128 rows * 80B
#define STAGE_B  (4u*TILE_B)          // Ahi, Alo, Bhi, Blo
#define GEMM_SMEM (2*STAGE_B)         // 81920 B double-buffered

__global__ __launch_bounds__(256) void mma_gemm(
    const __nv_bfloat16* __restrict__ Ahi, const __nv_bfloat16* __restrict__ Alo,
    const __nv_bfloat16* __restrict__ Bhi, const __nv_bfloat16* __restrict__ Blo,
    float* __restrict__ C, int Nc, int K)
{
    extern __shared__ __align__(128) char smem[];
    const uint32_t dbase = smem_u32(smem);
    const int tid   = threadIdx.x;
    const int lane  = tid & 31;
    const int wid   = tid >> 5;
    const int warpM = wid & 3;       // 0..3  -> rows warpM*32
    const int warpN = wid >> 2;      // 0..1  -> cols warpN*64

    const int rowBase = blockIdx.y * 128;
    const int colBase = blockIdx.x * 128;
    const int nChunks = K >> 5;      // BK = 32

    const __nv_bfloat16* srcs[4] = {Ahi, Alo, Bhi, Blo};

    auto load_chunk = [&](int chunk, int stage) {
        const uint32_t sbase = dbase + (uint32_t)stage * STAGE_B;
        const int k0 = chunk << 5;
        #pragma unroll
        for (int tile = 0; tile < 4; tile++) {
            const __nv_bfloat16* s = srcs[tile];
            const int gBase = (tile < 2) ? rowBase : colBase;
            const uint32_t tb = sbase + (uint32_t)tile * TILE_B;
            #pragma unroll
            for (int i = 0; i < 2; i++) {
                int idx = tid + (i << 8);            // 0..511
                int r = idx >> 2, c = idx & 3;       // row, 16B chunk
                cp16(tb + (uint32_t)(r * 80 + c * 16),
                     s + (size_t)(gBase + r) * K + k0 + c * 8);
            }
        }
        asm volatile("cp.async.commit_group;" ::: "memory");
    };

    // per-lane ldmatrix base offsets
    const uint32_t aoff = (uint32_t)((warpM * 32 + (lane & 15)) * 80 + (lane >> 4) * 16);
    const uint32_t boff = (uint32_t)((warpN * 64 + (lane & 7) + ((lane >> 4) << 3)) * 80
                                     + ((lane >> 3) & 1) * 16);

    float acc[2][8][4];
    #pragma unroll
    for (int mt = 0; mt < 2; mt++)
        #pragma unroll
        for (int nt = 0; nt < 8; nt++)
            #pragma unroll
            for (int e = 0; e < 4; e++) acc[mt][nt][e] = 0.f;

    load_chunk(0, 0);
    int buf = 0;
    for (int chunk = 0; chunk < nChunks; chunk++) {
        if (chunk + 1 < nChunks) {
            load_chunk(chunk + 1, buf ^ 1);
            asm volatile("cp.async.wait_group 1;" ::: "memory");
        } else {
            asm volatile("cp.async.wait_group 0;" ::: "memory");
        }
        __syncthreads();

        const uint32_t sbase = dbase + (uint32_t)buf * STAGE_B;
        const uint32_t sAh = sbase + aoff;
        const uint32_t sAl = sAh + TILE_B;
        const uint32_t sBh = sbase + 2u * TILE_B + boff;
        const uint32_t sBl = sBh + TILE_B;

        #pragma unroll
        for (int ks = 0; ks < 2; ks++) {
            uint32_t ah[2][4], al[2][4];
            LDSM4(ah[0], sAh + ks * 32);
            LDSM4(ah[1], sAh + 16 * 80 + ks * 32);
            LDSM4(al[0], sAl + ks * 32);
            LDSM4(al[1], sAl + 16 * 80 + ks * 32);
            #pragma unroll
            for (int ntp = 0; ntp < 4; ntp++) {
                uint32_t bh[4], bl[4];
                LDSM4(bh, sBh + ntp * 16 * 80 + ks * 32);
                LDSM4(bl, sBl + ntp * 16 * 80 + ks * 32);
                #pragma unroll
                for (int mt = 0; mt < 2; mt++) {
                    MMA16816(acc[mt][2*ntp],   ah[mt], bh[0], bh[1]);
                    MMA16816(acc[mt][2*ntp],   ah[mt], bl[0], bl[1]);
                    MMA16816(acc[mt][2*ntp],   al[mt], bh[0], bh[1]);
                    MMA16816(acc[mt][2*ntp+1], ah[mt], bh[2], bh[3]);
                    MMA16816(acc[mt][2*ntp+1], ah[mt], bl[2], bl[3]);
                    MMA16816(acc[mt][2*ntp+1], al[mt], bh[2], bh[3]);
                }
            }
        }
        buf ^= 1;
        __syncthreads();
    }

    // epilogue: fragment (mt,nt): rows warpM*32+mt*16+{lane/4, +8}, cols warpN*64+nt*8+(lane%4)*2
    #pragma unroll
    for (int mt = 0; mt < 2; mt++) {
        int row0 = rowBase + warpM * 32 + mt * 16 + (lane >> 2);
        #pragma unroll
        for (int nt = 0; nt < 8; nt++) {
            int col = colBase + warpN * 64 + nt * 8 + (lane & 3) * 2;
            *(float2*)(C + (size_t)row0 * Nc + col)       = make_float2(acc[mt][nt][0], acc[mt][nt][1]);
            *(float2*)(C + (size_t)(row0 + 8) * Nc + col) = make_float2(acc[mt][nt][2], acc[mt][nt][3]);
        }
    }
}

// ---------------- RoPE (fp32) ----------------
__global__ void rope_kernel(float* __restrict__ data,
                            const float* __restrict__ cosT,
                            const float* __restrict__ sinT,
                            int nHeads, int rowStride, int total)
{
    int i = blockIdx.x * blockDim.x + threadIdx.x;
    if (i >= total) return;
    int p   = i & 31;
    int h   = (i >> 5) % nHeads;
    int row = i / (32 * nHeads);
    int n   = row % NN;
    float c = cosT[n * 32 + p];
    float s = sinT[n * 32 + p];
    float* ptr = data + (size_t)row * rowStride + h * HD + 2 * p;
    float e = ptr[0], o = ptr[1];
    ptr[0] = e * c - o * s;
    ptr[1] = e * s + o * c;
}

// ---------------- Flash attention (fp32, proven in round 1) ----------------
#define FBM 128
#define FBN 64
#define FLASH_SMEM ((4096 + 4096 + FBM*65) * 4)

__global__ __launch_bounds__(FBM) void flash_kernel(
    const float* __restrict__ Q, const float* __restrict__ KV,
    float* __restrict__ O)
{
    extern __shared__ float sm[];
    float* Ks = sm;
    float* Vs = sm + 4096;
    float* Ss = sm + 8192;

    const int t    = threadIdx.x;
    const int qb   = blockIdx.x;
    const int head = blockIdx.y;
    const int b    = blockIdx.z;
    const int kvh  = head & (NKV - 1);
    const int qpos = qb * FBM + t;

    float4 q4[16], o4[16];
    const float4* qp = (const float4*)(Q + ((size_t)(b * NN) + qpos) * DIMX + head * HD);
    #pragma unroll
    for (int i = 0; i < 16; i++) { q4[i] = qp[i]; o4[i] = make_float4(0.f, 0.f, 0.f, 0.f); }

    float m = -1e30f, l = 0.f;
    const int kbmax = 2 * qb + 1;

    for (int kb = 0; kb <= kbmax; kb++) {
        const float4* kvbase = (const float4*)KV;
        #pragma unroll
        for (int i = 0; i < 8; i++) {
            int idx = t + i * FBM;
            int r = idx >> 4, c = idx & 15;
            size_t g = ((size_t)(b * NN) + (size_t)kb * FBN + r) * 256 + kvh * 16 + c;
            ((float4*)Ks)[idx] = kvbase[g];
            ((float4*)Vs)[idx] = kvbase[g + 128];
        }
        __syncthreads();

        float bmax = -1e30f;
        const bool needMask = (kb * FBN + FBN - 1) > qpos;
        for (int j = 0; j < FBN; j++) {
            const float4* kr = (const float4*)(Ks + j * 64);
            float s = 0.f;
            #pragma unroll
            for (int i = 0; i < 16; i++) {
                float4 kv4 = kr[i];
                s = fmaf(q4[i].x, kv4.x, s);
                s = fmaf(q4[i].y, kv4.y, s);
                s = fmaf(q4[i].z, kv4.z, s);
                s = fmaf(q4[i].w, kv4.w, s);
            }
            s *= 0.125f;
            if (needMask && (kb * FBN + j > qpos)) s = -1e30f;
            bmax = fmaxf(bmax, s);
            Ss[t * 65 + j] = s;
        }

        const float newm = fmaxf(m, bmax);
        const float corr = __expf(m - newm);
        l *= corr;
        #pragma unroll
        for (int i = 0; i < 16; i++) {
            o4[i].x *= corr; o4[i].y *= corr; o4[i].z *= corr; o4[i].w *= corr;
        }

        for (int j = 0; j < FBN; j++) {
            float p = __expf(Ss[t * 65 + j] - newm);
            l += p;
            const float4* vr = (const float4*)(Vs + j * 64);
            #pragma unroll
            for (int i = 0; i < 16; i++) {
                float4 v4 = vr[i];
                o4[i].x = fmaf(p, v4.x, o4[i].x);
                o4[i].y = fmaf(p, v4.y, o4[i].y);
                o4[i].z = fmaf(p, v4.z, o4[i].z);
                o4[i].w = fmaf(p, v4.w, o4[i].w);
            }
        }
        m = newm;
        __syncthreads();
    }

    const float inv = 1.f / l;
    float4* op = (float4*)(O + ((size_t)(b * NN) + qpos) * DIMX + head * HD);
    #pragma unroll
    for (int i = 0; i < 16; i++) {
        o4[i].x *= inv; o4[i].y *= inv; o4[i].z *= inv; o4[i].w *= inv;
        op[i] = o4[i];
    }
}

// ---------------- launch ----------------
extern "C" void kernel_launch(void* const* d_in, const int* in_sizes, int n_in,
                              void* d_out, int out_size)
{
    const float* x   = (const float*)d_in[0];
    const float* Wq  = (const float*)d_in[1];
    const float* Wkv = (const float*)d_in[2];
    const float* Wo  = (const float*)d_in[3];
    const float* rc  = (const float*)d_in[4];
    const float* rs  = (const float*)d_in[5];
    float* out = (float*)d_out;

    float *q, *kv, *attn;
    __nv_bfloat16 *xhi, *xlo, *wqh, *wql, *wkvh, *wkvl, *woh, *wol, *ahi, *alo;
    cudaGetSymbolAddress((void**)&q,    g_q);
    cudaGetSymbolAddress((void**)&kv,   g_kv);
    cudaGetSymbolAddress((void**)&attn, g_attn);
    cudaGetSymbolAddress((void**)&xhi,  g_xhi);
    cudaGetSymbolAddress((void**)&xlo,  g_xlo);
    cudaGetSymbolAddress((void**)&wqh,  g_wqh);
    cudaGetSymbolAddress((void**)&wql,  g_wql);
    cudaGetSymbolAddress((void**)&wkvh, g_wkvh);
    cudaGetSymbolAddress((void**)&wkvl, g_wkvl);
    cudaGetSymbolAddress((void**)&woh,  g_woh);
    cudaGetSymbolAddress((void**)&wol,  g_wol);
    cudaGetSymbolAddress((void**)&ahi,  g_ahi);
    cudaGetSymbolAddress((void**)&alo,  g_alo);

    cudaFuncSetAttribute(mma_gemm, cudaFuncAttributeMaxDynamicSharedMemorySize, GEMM_SMEM);
    cudaFuncSetAttribute(flash_kernel, cudaFuncAttributeMaxDynamicSharedMemorySize, FLASH_SMEM);

    // 1. split x into bf16 hi/lo
    int n4x = MM * DIMX / 4;
    split_kernel<<<(n4x + 255) / 256, 256>>>((const float4*)x, xhi, xlo, n4x);

    // 2. transpose+split weights: W[K,Nc] -> Wt[Nc,K]
    transpose_split<<<dim3(DIMX / 32, DIMX / 32), dim3(32, 8)>>>(Wq,  wqh,  wql,  DIMX, DIMX);
    transpose_split<<<dim3(KVW  / 32, DIMX / 32), dim3(32, 8)>>>(Wkv, wkvh, wkvl, DIMX, KVW);
    transpose_split<<<dim3(DIMX / 32, DIMX / 32), dim3(32, 8)>>>(Wo,  woh,  wol,  DIMX, DIMX);

    // 3. projections on tensor cores (mma.sync)
    mma_gemm<<<dim3(DIMX / 128, MM / 128), 256, GEMM_SMEM>>>(xhi, xlo, wqh,  wql,  q,  DIMX, DIMX);
    mma_gemm<<<dim3(KVW  / 128, MM / 128), 256, GEMM_SMEM>>>(xhi, xlo, wkvh, wkvl, kv, KVW,  DIMX);

    // 4. RoPE
    int totalQ = MM * NH * (HD / 2);
    rope_kernel<<<(totalQ + 255) / 256, 256>>>(q, rc, rs, NH, DIMX, totalQ);
    int totalK = MM * NKV * (HD / 2);
    rope_kernel<<<(totalK + 255) / 256, 256>>>(kv, rc, rs, NKV, KVW, totalK);

    // 5. flash attention (fp32)
    flash_kernel<<<dim3(NN / FBM, NH, BB), FBM, FLASH_SMEM>>>(q, kv, attn);

    // 6. split attn output, output projection
    split_kernel<<<(n4x + 255) / 256, 256>>>((const float4*)attn, ahi, alo, n4x);
    mma_gemm<<<dim3(DIMX / 128, MM / 128), 256, GEMM_SMEM>>>(ahi, alo, woh, wol, out, DIMX, DIMX);
}

// round 6
// speedup vs baseline: 3.0450x; 1.9127x over previous
#include <cuda_runtime.h>
#include <cuda_bf16.h>
#include <cstdint>
#include <cstddef>

#define BB   2
#define NN   2048
#define DIMX 2048
#define NH   32
#define NKV  8
#define HD   64
#define KVW  (2*NKV*HD)   // 1024
#define MM   (BB*NN)      // 4096

// ---------------- scratch (__device__ globals; allocation-free rule) ----------------
__device__ float g_q   [(size_t)MM*DIMX];
__device__ float g_kv  [(size_t)MM*KVW];
__device__ float g_attn[(size_t)MM*DIMX];

__device__ __nv_bfloat16 g_xhi [(size_t)MM*DIMX];
__device__ __nv_bfloat16 g_xlo [(size_t)MM*DIMX];
__device__ __nv_bfloat16 g_wqh [(size_t)DIMX*DIMX];
__device__ __nv_bfloat16 g_wql [(size_t)DIMX*DIMX];
__device__ __nv_bfloat16 g_wkvh[(size_t)KVW*DIMX];
__device__ __nv_bfloat16 g_wkvl[(size_t)KVW*DIMX];
__device__ __nv_bfloat16 g_woh [(size_t)DIMX*DIMX];
__device__ __nv_bfloat16 g_wol [(size_t)DIMX*DIMX];
__device__ __nv_bfloat16 g_ahi [(size_t)MM*DIMX];
__device__ __nv_bfloat16 g_alo [(size_t)MM*DIMX];

// attention-layout buffers
__device__ __nv_bfloat16 g_qbh [(size_t)BB*NH*NN*HD];   // [bh][n][d] hi
__device__ __nv_bfloat16 g_qbl [(size_t)BB*NH*NN*HD];
__device__ __nv_bfloat16 g_kbh [(size_t)BB*NKV*NN*HD];  // [bh][n][d] hi
__device__ __nv_bfloat16 g_kbl [(size_t)BB*NKV*NN*HD];
__device__ __nv_bfloat16 g_vth [(size_t)BB*NKV*HD*NN];  // [bh][d][n] hi (transposed)
__device__ __nv_bfloat16 g_vtl [(size_t)BB*NKV*HD*NN];

// ---------------- helpers (baseline PTX ISA only) ----------------
__device__ __forceinline__ uint32_t smem_u32(const void* p){
    uint32_t a;
    asm("{ .reg .u64 t; cvta.to.shared.u64 t, %1; cvt.u32.u64 %0, t; }" : "=r"(a) : "l"(p));
    return a;
}
__device__ __forceinline__ void cp16(uint32_t dst, const void* src){
    asm volatile("cp.async.cg.shared.global [%0], [%1], 16;" :: "r"(dst), "l"(src));
}

#define LDSM4(r, addr) \
    asm volatile("ldmatrix.sync.aligned.m8n8.x4.shared.b16 {%0,%1,%2,%3}, [%4];" \
        : "=r"((r)[0]), "=r"((r)[1]), "=r"((r)[2]), "=r"((r)[3]) : "r"(addr))

#define MMA16816(d, a, b0, b1) \
    asm volatile("mma.sync.aligned.m16n8k16.row.col.f32.bf16.bf16.f32 " \
        "{%0,%1,%2,%3}, {%4,%5,%6,%7}, {%8,%9}, {%0,%1,%2,%3};" \
        : "+f"((d)[0]), "+f"((d)[1]), "+f"((d)[2]), "+f"((d)[3]) \
        : "r"((a)[0]), "r"((a)[1]), "r"((a)[2]), "r"((a)[3]), "r"(b0), "r"(b1))

__device__ __forceinline__ uint32_t pack_bf16(float a, float b){
    __nv_bfloat162 p = __floats2bfloat162_rn(a, b);
    return *(uint32_t*)&p;
}

// ---------------- conversion passes ----------------
__global__ void split_kernel(const float4* __restrict__ src,
                             __nv_bfloat16* __restrict__ hi, __nv_bfloat16* __restrict__ lo, int n4)
{
    int i = blockIdx.x * blockDim.x + threadIdx.x;
    if (i >= n4) return;
    float4 v = src[i];
    float vv[4] = {v.x, v.y, v.z, v.w};
    #pragma unroll
    for (int j = 0; j < 4; j++) {
        __nv_bfloat16 h = __float2bfloat16(vv[j]);
        hi[4*i + j] = h;
        lo[4*i + j] = __float2bfloat16(vv[j] - __bfloat162float(h));
    }
}

__global__ void transpose_split(const float* __restrict__ W,
                                __nv_bfloat16* __restrict__ hi, __nv_bfloat16* __restrict__ lo,
                                int K, int Nc)
{
    __shared__ float t[32][33];
    int x  = blockIdx.x * 32 + threadIdx.x;
    int y0 = blockIdx.y * 32;
    #pragma unroll
    for (int j = 0; j < 32; j += 8)
        t[threadIdx.y + j][threadIdx.x] = W[(size_t)(y0 + threadIdx.y + j) * Nc + x];
    __syncthreads();
    int ox = y0 + threadIdx.x;
    int oy = blockIdx.x * 32;
    #pragma unroll
    for (int j = 0; j < 32; j += 8) {
        float v = t[threadIdx.x][threadIdx.y + j];
        __nv_bfloat16 h = __float2bfloat16(v);
        hi[(size_t)(oy + threadIdx.y + j) * K + ox] = h;
        lo[(size_t)(oy + threadIdx.y + j) * K + ox] = __float2bfloat16(v - __bfloat162float(h));
    }
}

// Q: [row=b*NN+n][DIMX] -> per-head [bh][n][64] bf16 hi/lo, scaled by 0.125
__global__ void qsplit_kernel(const float* __restrict__ Q,
                              __nv_bfloat16* __restrict__ hi, __nv_bfloat16* __restrict__ lo)
{
    int i = blockIdx.x * blockDim.x + threadIdx.x;   // one float4 along d
    // total = BB*NH*NN*16
    int d4 = i & 15;
    int n  = (i >> 4) & (NN - 1);
    int bh = i >> 15;                                 // 0..63
    if (bh >= BB * NH) return;
    int b = bh >> 5, h = bh & 31;
    float4 v = *(const float4*)(Q + ((size_t)(b * NN + n) * DIMX) + h * HD + d4 * 4);
    float vv[4] = {v.x * 0.125f, v.y * 0.125f, v.z * 0.125f, v.w * 0.125f};
    size_t o = ((size_t)bh * NN + n) * HD + d4 * 4;
    #pragma unroll
    for (int j = 0; j < 4; j++) {
        __nv_bfloat16 hh = __float2bfloat16(vv[j]);
        hi[o + j] = hh;
        lo[o + j] = __float2bfloat16(vv[j] - __bfloat162float(hh));
    }
}

// K half of kv: -> [bh][n][64] bf16 hi/lo
__global__ void ksplit_kernel(const float* __restrict__ KV,
                              __nv_bfloat16* __restrict__ hi, __nv_bfloat16* __restrict__ lo)
{
    int i = blockIdx.x * blockDim.x + threadIdx.x;
    int d4 = i & 15;
    int n  = (i >> 4) & (NN - 1);
    int bh = i >> 15;                                 // 0..15
    if (bh >= BB * NKV) return;
    int b = bh >> 3, h = bh & 7;
    float4 v = *(const float4*)(KV + ((size_t)(b * NN + n) * KVW) + h * HD + d4 * 4);
    float vv[4] = {v.x, v.y, v.z, v.w};
    size_t o = ((size_t)bh * NN + n) * HD + d4 * 4;
    #pragma unroll
    for (int j = 0; j < 4; j++) {
        __nv_bfloat16 hh = __float2bfloat16(vv[j]);
        hi[o + j] = hh;
        lo[o + j] = __float2bfloat16(vv[j] - __bfloat162float(hh));
    }
}

// V half of kv -> transposed [bh][d][n] bf16 hi/lo
__global__ void vtsplit_kernel(const float* __restrict__ KV,
                               __nv_bfloat16* __restrict__ hi, __nv_bfloat16* __restrict__ lo)
{
    __shared__ float t[32][33];
    int bh = blockIdx.z;              // 0..15
    int b = bh >> 3, h = bh & 7;
    int n0 = blockIdx.x * 32;
    int d0 = blockIdx.y * 32;
    #pragma unroll
    for (int j = 0; j < 32; j += 8)
        t[threadIdx.y + j][threadIdx.x] =
            KV[((size_t)(b * NN + n0 + threadIdx.y + j)) * KVW + NKV*HD + h * HD + d0 + threadIdx.x];
    __syncthreads();
    #pragma unroll
    for (int j = 0; j < 32; j += 8) {
        float v = t[threadIdx.x][threadIdx.y + j];  // (n = n0+tx, d = d0+ty+j)
        __nv_bfloat16 hh = __float2bfloat16(v);
        size_t o = ((size_t)bh * HD + d0 + threadIdx.y + j) * NN + n0 + threadIdx.x;
        hi[o] = hh;
        lo[o] = __float2bfloat16(v - __bfloat162float(hh));
    }
}

// ---------------- mma.sync bf16-split GEMM (unchanged from round 4, passing) ----------------
#define TILE_B   10240u
#define STAGE_B  (4u*TILE_B)
#define GEMM_SMEM (2*STAGE_B)

__global__ __launch_bounds__(256) void mma_gemm(
    const __nv_bfloat16* __restrict__ Ahi, const __nv_bfloat16* __restrict__ Alo,
    const __nv_bfloat16* __restrict__ Bhi, const __nv_bfloat16* __restrict__ Blo,
    float* __restrict__ C, int Nc, int K)
{
    extern __shared__ __align__(128) char smem[];
    const uint32_t dbase = smem_u32(smem);
    const int tid   = threadIdx.x;
    const int lane  = tid & 31;
    const int wid   = tid >> 5;
    const int warpM = wid & 3;
    const int warpN = wid >> 2;

    const int rowBase = blockIdx.y * 128;
    const int colBase = blockIdx.x * 128;
    const int nChunks = K >> 5;

    const __nv_bfloat16* srcs[4] = {Ahi, Alo, Bhi, Blo};

    auto load_chunk = [&](int chunk, int stage) {
        const uint32_t sbase = dbase + (uint32_t)stage * STAGE_B;
        const int k0 = chunk << 5;
        #pragma unroll
        for (int tile = 0; tile < 4; tile++) {
            const __nv_bfloat16* s = srcs[tile];
            const int gBase = (tile < 2) ? rowBase : colBase;
            const uint32_t tb = sbase + (uint32_t)tile * TILE_B;
            #pragma unroll
            for (int i = 0; i < 2; i++) {
                int idx = tid + (i << 8);
                int r = idx >> 2, c = idx & 3;
                cp16(tb + (uint32_t)(r * 80 + c * 16),
                     s + (size_t)(gBase + r) * K + k0 + c * 8);
            }
        }
        asm volatile("cp.async.commit_group;" ::: "memory");
    };

    const uint32_t aoff = (uint32_t)((warpM * 32 + (lane & 15)) * 80 + (lane >> 4) * 16);
    const uint32_t boff = (uint32_t)((warpN * 64 + (lane & 7) + ((lane >> 4) << 3)) * 80
                                     + ((lane >> 3) & 1) * 16);

    float acc[2][8][4];
    #pragma unroll
    for (int mt = 0; mt < 2; mt++)
        #pragma unroll
        for (int nt = 0; nt < 8; nt++)
            #pragma unroll
            for (int e = 0; e < 4; e++) acc[mt][nt][e] = 0.f;

    load_chunk(0, 0);
    int buf = 0;
    for (int chunk = 0; chunk < nChunks; chunk++) {
        if (chunk + 1 < nChunks) {
            load_chunk(chunk + 1, buf ^ 1);
            asm volatile("cp.async.wait_group 1;" ::: "memory");
        } else {
            asm volatile("cp.async.wait_group 0;" ::: "memory");
        }
        __syncthreads();

        const uint32_t sbase = dbase + (uint32_t)buf * STAGE_B;
        const uint32_t sAh = sbase + aoff;
        const uint32_t sAl = sAh + TILE_B;
        const uint32_t sBh = sbase + 2u * TILE_B + boff;
        const uint32_t sBl = sBh + TILE_B;

        #pragma unroll
        for (int ks = 0; ks < 2; ks++) {
            uint32_t ah[2][4], al[2][4];
            LDSM4(ah[0], sAh + ks * 32);
            LDSM4(ah[1], sAh + 16 * 80 + ks * 32);
            LDSM4(al[0], sAl + ks * 32);
            LDSM4(al[1], sAl + 16 * 80 + ks * 32);
            #pragma unroll
            for (int ntp = 0; ntp < 4; ntp++) {
                uint32_t bh[4], bl[4];
                LDSM4(bh, sBh + ntp * 16 * 80 + ks * 32);
                LDSM4(bl, sBl + ntp * 16 * 80 + ks * 32);
                #pragma unroll
                for (int mt = 0; mt < 2; mt++) {
                    MMA16816(acc[mt][2*ntp],   ah[mt], bh[0], bh[1]);
                    MMA16816(acc[mt][2*ntp],   ah[mt], bl[0], bl[1]);
                    MMA16816(acc[mt][2*ntp],   al[mt], bh[0], bh[1]);
                    MMA16816(acc[mt][2*ntp+1], ah[mt], bh[2], bh[3]);
                    MMA16816(acc[mt][2*ntp+1], ah[mt], bl[2], bl[3]);
                    MMA16816(acc[mt][2*ntp+1], al[mt], bh[2], bh[3]);
                }
            }
        }
        buf ^= 1;
        __syncthreads();
    }

    #pragma unroll
    for (int mt = 0; mt < 2; mt++) {
        int row0 = rowBase + warpM * 32 + mt * 16 + (lane >> 2);
        #pragma unroll
        for (int nt = 0; nt < 8; nt++) {
            int col = colBase + warpN * 64 + nt * 8 + (lane & 3) * 2;
            *(float2*)(C + (size_t)row0 * Nc + col)       = make_float2(acc[mt][nt][0], acc[mt][nt][1]);
            *(float2*)(C + (size_t)(row0 + 8) * Nc + col) = make_float2(acc[mt][nt][2], acc[mt][nt][3]);
        }
    }
}

// ---------------- RoPE (fp32) ----------------
__global__ void rope_kernel(float* __restrict__ data,
                            const float* __restrict__ cosT,
                            const float* __restrict__ sinT,
                            int nHeads, int rowStride, int total)
{
    int i = blockIdx.x * blockDim.x + threadIdx.x;
    if (i >= total) return;
    int p   = i & 31;
    int h   = (i >> 5) % nHeads;
    int row = i / (32 * nHeads);
    int n   = row % NN;
    float c = cosT[n * 32 + p];
    float s = sinT[n * 32 + p];
    float* ptr = data + (size_t)row * rowStride + h * HD + 2 * p;
    float e = ptr[0], o = ptr[1];
    ptr[0] = e * c - o * s;
    ptr[1] = e * s + o * c;
}

// ---------------- tensor-core flash attention ----------------
// CTA = 128 queries x 1 head. 8 warps x 16 q rows. 64-key tiles.
// Smem rows 144B stride (conflict-free ldmatrix). 3-term bf16 split both mmas.
#define AST 144u
#define AQ_B  (128u*AST)          // 18432 per q buffer
#define AK_B  (64u*AST)           // 9216 per k/v buffer
#define SM_QH 0u
#define SM_QL AQ_B
#define SM_KH (2u*AQ_B)
#define SM_KL (2u*AQ_B + AK_B)
#define SM_VH (2u*AQ_B + 2u*AK_B)
#define SM_VL (2u*AQ_B + 3u*AK_B)
#define FLASH_SMEM (2u*AQ_B + 4u*AK_B)   // 73728 B

__global__ __launch_bounds__(256) void flash_attn_mma(
    const __nv_bfloat16* __restrict__ Qh, const __nv_bfloat16* __restrict__ Ql,
    const __nv_bfloat16* __restrict__ Kh, const __nv_bfloat16* __restrict__ Kl,
    const __nv_bfloat16* __restrict__ Vh, const __nv_bfloat16* __restrict__ Vl,
    float* __restrict__ O)
{
    extern __shared__ __align__(128) char smem[];
    const uint32_t sb = smem_u32(smem);
    const int tid  = threadIdx.x;
    const int lane = tid & 31;
    const int wid  = tid >> 5;          // 0..7, rows wid*16
    const int qb   = blockIdx.x;
    const int head = blockIdx.y;
    const int b    = blockIdx.z;
    const int bhq  = b * NH + head;
    const int bhk  = b * NKV + (head & (NKV - 1));

    const __nv_bfloat16* qh = Qh + ((size_t)bhq * NN + qb * 128) * HD;
    const __nv_bfloat16* ql = Ql + ((size_t)bhq * NN + qb * 128) * HD;
    const __nv_bfloat16* kh = Kh + (size_t)bhk * NN * HD;
    const __nv_bfloat16* kl = Kl + (size_t)bhk * NN * HD;
    const __nv_bfloat16* vh = Vh + (size_t)bhk * HD * NN;
    const __nv_bfloat16* vl = Vl + (size_t)bhk * HD * NN;

    // ---- load Q (once), 128 rows x 64 bf16, both hi/lo ----
    #pragma unroll
    for (int i = 0; i < 4; i++) {
        int idx = tid + (i << 8);          // 0..1023
        int r = idx >> 3, c = idx & 7;
        cp16(sb + SM_QH + (uint32_t)(r * AST + c * 16), qh + (size_t)r * HD + c * 8);
        cp16(sb + SM_QL + (uint32_t)(r * AST + c * 16), ql + (size_t)r * HD + c * 8);
    }
    asm volatile("cp.async.commit_group;" ::: "memory");
    asm volatile("cp.async.wait_group 0;" ::: "memory");
    __syncthreads();

    // ---- ldmatrix Q fragments (A-operand): 4 k-steps of 16 d ----
    const uint32_t qoff = (uint32_t)((wid * 16 + (lane & 15)) * AST + (lane >> 4) * 16);
    uint32_t qfh[4][4], qfl[4][4];
    #pragma unroll
    for (int ks = 0; ks < 4; ks++) {
        LDSM4(qfh[ks], sb + SM_QH + qoff + ks * 32);
        LDSM4(qfl[ks], sb + SM_QL + qoff + ks * 32);
    }
    __syncthreads();   // Q smem no longer needed (frags in regs)

    // B-operand lane offset (shared by K and Vt tiles)
    const uint32_t boff = (uint32_t)(((lane & 7) + ((lane >> 4) << 3)) * AST + ((lane >> 3) & 1) * 16);

    float oacc[8][4];
    #pragma unroll
    for (int nt = 0; nt < 8; nt++)
        #pragma unroll
        for (int e = 0; e < 4; e++) oacc[nt][e] = 0.f;
    float m[2] = {-1e30f, -1e30f};
    float l[2] = {0.f, 0.f};

    const int r0 = qb * 128 + wid * 16 + (lane >> 2);   // this thread's first q row
    const int kbmax = 2 * qb + 1;

    for (int kb = 0; kb <= kbmax; kb++) {
        // ---- load K/V tile (64 rows x 64 bf16 x hi/lo x K,Vt) ----
        #pragma unroll
        for (int i = 0; i < 2; i++) {
            int idx = tid + (i << 8);       // 0..511
            int r = idx >> 3, c = idx & 7;
            uint32_t so = (uint32_t)(r * AST + c * 16);
            size_t kg = ((size_t)(kb * 64 + r)) * HD + c * 8;
            size_t vg = ((size_t)r) * NN + kb * 64 + c * 8;   // Vt rows are d
            cp16(sb + SM_KH + so, kh + kg);
            cp16(sb + SM_KL + so, kl + kg);
            cp16(sb + SM_VH + so, vh + vg);
            cp16(sb + SM_VL + so, vl + vg);
        }
        asm volatile("cp.async.commit_group;" ::: "memory");
        asm volatile("cp.async.wait_group 0;" ::: "memory");
        __syncthreads();

        // ---- S = Q K^T (3-term split), 16x64 per warp ----
        float sacc[8][4];
        #pragma unroll
        for (int nt = 0; nt < 8; nt++)
            #pragma unroll
            for (int e = 0; e < 4; e++) sacc[nt][e] = 0.f;

        #pragma unroll
        for (int ks = 0; ks < 4; ks++) {
            #pragma unroll
            for (int kg = 0; kg < 4; kg++) {
                uint32_t bh_[4], bl_[4];
                LDSM4(bh_, sb + SM_KH + boff + (uint32_t)(kg * 16 * AST) + ks * 32);
                LDSM4(bl_, sb + SM_KL + boff + (uint32_t)(kg * 16 * AST) + ks * 32);
                MMA16816(sacc[2*kg],   qfh[ks], bh_[0], bh_[1]);
                MMA16816(sacc[2*kg],   qfh[ks], bl_[0], bl_[1]);
                MMA16816(sacc[2*kg],   qfl[ks], bh_[0], bh_[1]);
                MMA16816(sacc[2*kg+1], qfh[ks], bh_[2], bh_[3]);
                MMA16816(sacc[2*kg+1], qfh[ks], bl_[2], bl_[3]);
                MMA16816(sacc[2*kg+1], qfl[ks], bh_[2], bh_[3]);
            }
        }

        // ---- causal mask (diagonal tiles only) ----
        if (kb * 64 + 63 > r0) {
            #pragma unroll
            for (int nt = 0; nt < 8; nt++) {
                int c = kb * 64 + nt * 8 + (lane & 3) * 2;
                if (c > r0)     sacc[nt][0] = -1e30f;
                if (c + 1 > r0) sacc[nt][1] = -1e30f;
                if (c > r0 + 8)     sacc[nt][2] = -1e30f;
                if (c + 1 > r0 + 8) sacc[nt][3] = -1e30f;
            }
        }

        // ---- online softmax ----
        float rmax[2] = {-1e30f, -1e30f};
        #pragma unroll
        for (int nt = 0; nt < 8; nt++) {
            rmax[0] = fmaxf(rmax[0], fmaxf(sacc[nt][0], sacc[nt][1]));
            rmax[1] = fmaxf(rmax[1], fmaxf(sacc[nt][2], sacc[nt][3]));
        }
        #pragma unroll
        for (int w = 1; w <= 2; w <<= 1) {
            rmax[0] = fmaxf(rmax[0], __shfl_xor_sync(0xffffffffu, rmax[0], w));
            rmax[1] = fmaxf(rmax[1], __shfl_xor_sync(0xffffffffu, rmax[1], w));
        }
        float nm0 = fmaxf(m[0], rmax[0]);
        float nm1 = fmaxf(m[1], rmax[1]);
        float c0 = __expf(m[0] - nm0);
        float c1 = __expf(m[1] - nm1);
        m[0] = nm0; m[1] = nm1;
        #pragma unroll
        for (int nt = 0; nt < 8; nt++) {
            oacc[nt][0] *= c0; oacc[nt][1] *= c0;
            oacc[nt][2] *= c1; oacc[nt][3] *= c1;
        }
        float sum0 = 0.f, sum1 = 0.f;
        uint32_t ph[8][2], pl[8][2];
        #pragma unroll
        for (int nt = 0; nt < 8; nt++) {
            float p0 = __expf(sacc[nt][0] - nm0);
            float p1 = __expf(sacc[nt][1] - nm0);
            float p2 = __expf(sacc[nt][2] - nm1);
            float p3 = __expf(sacc[nt][3] - nm1);
            sum0 += p0 + p1; sum1 += p2 + p3;
            float h0 = __bfloat162float(__float2bfloat16(p0));
            float h1 = __bfloat162float(__float2bfloat16(p1));
            float h2 = __bfloat162float(__float2bfloat16(p2));
            float h3 = __bfloat162float(__float2bfloat16(p3));
            ph[nt][0] = pack_bf16(h0, h1);
            ph[nt][1] = pack_bf16(h2, h3);
            pl[nt][0] = pack_bf16(p0 - h0, p1 - h1);
            pl[nt][1] = pack_bf16(p2 - h2, p3 - h3);
        }
        #pragma unroll
        for (int w = 1; w <= 2; w <<= 1) {
            sum0 += __shfl_xor_sync(0xffffffffu, sum0, w);
            sum1 += __shfl_xor_sync(0xffffffffu, sum1, w);
        }
        l[0] = l[0] * c0 + sum0;
        l[1] = l[1] * c1 + sum1;

        // ---- O += P V (3-term split): A = P frags from regs, B = Vt tiles ----
        #pragma unroll
        for (int ks = 0; ks < 4; ks++) {           // key chunks of 16
            uint32_t aph[4] = {ph[2*ks][0], ph[2*ks][1], ph[2*ks+1][0], ph[2*ks+1][1]};
            uint32_t apl[4] = {pl[2*ks][0], pl[2*ks][1], pl[2*ks+1][0], pl[2*ks+1][1]};
            #pragma unroll
            for (int dg = 0; dg < 4; dg++) {       // d groups of 16
                uint32_t vbh[4], vbl[4];
                LDSM4(vbh, sb + SM_VH + boff + (uint32_t)(dg * 16 * AST) + ks * 32);
                LDSM4(vbl, sb + SM_VL + boff + (uint32_t)(dg * 16 * AST) + ks * 32);
                MMA16816(oacc[2*dg],   aph, vbh[0], vbh[1]);
                MMA16816(oacc[2*dg],   aph, vbl[0], vbl[1]);
                MMA16816(oacc[2*dg],   apl, vbh[0], vbh[1]);
                MMA16816(oacc[2*dg+1], aph, vbh[2], vbh[3]);
                MMA16816(oacc[2*dg+1], aph, vbl[2], vbl[3]);
                MMA16816(oacc[2*dg+1], apl, vbh[2], vbh[3]);
            }
        }
        __syncthreads();
    }

    // ---- write O to g_attn [b*NN+q][DIMX] at head*64 ----
    float inv0 = 1.f / l[0];
    float inv1 = 1.f / l[1];
    size_t row = (size_t)(b * NN) + r0;
    #pragma unroll
    for (int nt = 0; nt < 8; nt++) {
        int col = head * HD + nt * 8 + (lane & 3) * 2;
        *(float2*)(O + row * DIMX + col)             = make_float2(oacc[nt][0] * inv0, oacc[nt][1] * inv0);
        *(float2*)(O + (row + 8) * DIMX + col)       = make_float2(oacc[nt][2] * inv1, oacc[nt][3] * inv1);
    }
}

// ---------------- launch ----------------
extern "C" void kernel_launch(void* const* d_in, const int* in_sizes, int n_in,
                              void* d_out, int out_size)
{
    const float* x   = (const float*)d_in[0];
    const float* Wq  = (const float*)d_in[1];
    const float* Wkv = (const float*)d_in[2];
    const float* Wo  = (const float*)d_in[3];
    const float* rc  = (const float*)d_in[4];
    const float* rs  = (const float*)d_in[5];
    float* out = (float*)d_out;

    float *q, *kv, *attn;
    __nv_bfloat16 *xhi, *xlo, *wqh, *wql, *wkvh, *wkvl, *woh, *wol, *ahi, *alo;
    __nv_bfloat16 *qbh, *qbl, *kbh, *kbl, *vth, *vtl;
    cudaGetSymbolAddress((void**)&q,    g_q);
    cudaGetSymbolAddress((void**)&kv,   g_kv);
    cudaGetSymbolAddress((void**)&attn, g_attn);
    cudaGetSymbolAddress((void**)&xhi,  g_xhi);
    cudaGetSymbolAddress((void**)&xlo,  g_xlo);
    cudaGetSymbolAddress((void**)&wqh,  g_wqh);
    cudaGetSymbolAddress((void**)&wql,  g_wql);
    cudaGetSymbolAddress((void**)&wkvh, g_wkvh);
    cudaGetSymbolAddress((void**)&wkvl, g_wkvl);
    cudaGetSymbolAddress((void**)&woh,  g_woh);
    cudaGetSymbolAddress((void**)&wol,  g_wol);
    cudaGetSymbolAddress((void**)&ahi,  g_ahi);
    cudaGetSymbolAddress((void**)&alo,  g_alo);
    cudaGetSymbolAddress((void**)&qbh,  g_qbh);
    cudaGetSymbolAddress((void**)&qbl,  g_qbl);
    cudaGetSymbolAddress((void**)&kbh,  g_kbh);
    cudaGetSymbolAddress((void**)&kbl,  g_kbl);
    cudaGetSymbolAddress((void**)&vth,  g_vth);
    cudaGetSymbolAddress((void**)&vtl,  g_vtl);

    cudaFuncSetAttribute(mma_gemm, cudaFuncAttributeMaxDynamicSharedMemorySize, GEMM_SMEM);
    cudaFuncSetAttribute(flash_attn_mma, cudaFuncAttributeMaxDynamicSharedMemorySize, FLASH_SMEM);

    // 1. split x
    int n4x = MM * DIMX / 4;
    split_kernel<<<(n4x + 255) / 256, 256>>>((const float4*)x, xhi, xlo, n4x);

    // 2. weights
    transpose_split<<<dim3(DIMX / 32, DIMX / 32), dim3(32, 8)>>>(Wq,  wqh,  wql,  DIMX, DIMX);
    transpose_split<<<dim3(KVW  / 32, DIMX / 32), dim3(32, 8)>>>(Wkv, wkvh, wkvl, DIMX, KVW);
    transpose_split<<<dim3(DIMX / 32, DIMX / 32), dim3(32, 8)>>>(Wo,  woh,  wol,  DIMX, DIMX);

    // 3. projections
    mma_gemm<<<dim3(DIMX / 128, MM / 128), 256, GEMM_SMEM>>>(xhi, xlo, wqh,  wql,  q,  DIMX, DIMX);
    mma_gemm<<<dim3(KVW  / 128, MM / 128), 256, GEMM_SMEM>>>(xhi, xlo, wkvh, wkvl, kv, KVW,  DIMX);

    // 4. RoPE
    int totalQ = MM * NH * (HD / 2);
    rope_kernel<<<(totalQ + 255) / 256, 256>>>(q, rc, rs, NH, DIMX, totalQ);
    int totalK = MM * NKV * (HD / 2);
    rope_kernel<<<(totalK + 255) / 256, 256>>>(kv, rc, rs, NKV, KVW, totalK);

    // 5. attention-layout conversions
    int nq4 = BB * NH * NN * 16;
    qsplit_kernel<<<(nq4 + 255) / 256, 256>>>(q, qbh, qbl);
    int nk4 = BB * NKV * NN * 16;
    ksplit_kernel<<<(nk4 + 255) / 256, 256>>>(kv, kbh, kbl);
    vtsplit_kernel<<<dim3(NN / 32, HD / 32, BB * NKV), dim3(32, 8)>>>(kv, vth, vtl);

    // 6. tensor-core flash attention
    flash_attn_mma<<<dim3(NN / 128, NH, BB), 256, FLASH_SMEM>>>(
        qbh, qbl, kbh, kbl, vth, vtl, attn);

    // 7. output projection
    split_kernel<<<(n4x + 255) / 256, 256>>>((const float4*)attn, ahi, alo, n4x);
    mma_gemm<<<dim3(DIMX / 128, MM / 128), 256, GEMM_SMEM>>>(ahi, alo, woh, wol, out, DIMX, DIMX);
}

// round 7
// speedup vs baseline: 3.2817x; 1.0777x over previous
#include <cuda_runtime.h>
#include <cuda_bf16.h>
#include <cstdint>
#include <cstddef>

#define BB   2
#define NN   2048
#define DIMX 2048
#define NH   32
#define NKV  8
#define HD   64
#define KVW  (2*NKV*HD)   // 1024
#define MM   (BB*NN)      // 4096

// ---------------- scratch (__device__ globals; allocation-free rule) ----------------
__device__ __nv_bfloat16 g_xhi [(size_t)MM*DIMX];
__device__ __nv_bfloat16 g_xlo [(size_t)MM*DIMX];
__device__ __nv_bfloat16 g_wqh [(size_t)DIMX*DIMX];
__device__ __nv_bfloat16 g_wql [(size_t)DIMX*DIMX];
__device__ __nv_bfloat16 g_wkvh[(size_t)KVW*DIMX];
__device__ __nv_bfloat16 g_wkvl[(size_t)KVW*DIMX];
__device__ __nv_bfloat16 g_woh [(size_t)DIMX*DIMX];
__device__ __nv_bfloat16 g_wol [(size_t)DIMX*DIMX];
__device__ __nv_bfloat16 g_ahi [(size_t)MM*DIMX];   // flash out hi (O-proj A)
__device__ __nv_bfloat16 g_alo [(size_t)MM*DIMX];

// attention-layout buffers
__device__ __nv_bfloat16 g_qbh [(size_t)BB*NH*NN*HD];   // [bh][n][d] hi (rope+scale applied)
__device__ __nv_bfloat16 g_qbl [(size_t)BB*NH*NN*HD];
__device__ __nv_bfloat16 g_kbh [(size_t)BB*NKV*NN*HD];  // [bh][n][d] hi (rope applied)
__device__ __nv_bfloat16 g_kbl [(size_t)BB*NKV*NN*HD];
__device__ float         g_v   [(size_t)BB*NKV*NN*HD];  // compact V fp32 [bh][n][d]
__device__ __nv_bfloat16 g_vth [(size_t)BB*NKV*HD*NN];  // [bh][d][n] hi (transposed)
__device__ __nv_bfloat16 g_vtl [(size_t)BB*NKV*HD*NN];

// ---------------- helpers (baseline PTX ISA only) ----------------
__device__ __forceinline__ uint32_t smem_u32(const void* p){
    uint32_t a;
    asm("{ .reg .u64 t; cvta.to.shared.u64 t, %1; cvt.u32.u64 %0, t; }" : "=r"(a) : "l"(p));
    return a;
}
__device__ __forceinline__ void cp16(uint32_t dst, const void* src){
    asm volatile("cp.async.cg.shared.global [%0], [%1], 16;" :: "r"(dst), "l"(src));
}

#define LDSM4(r, addr) \
    asm volatile("ldmatrix.sync.aligned.m8n8.x4.shared.b16 {%0,%1,%2,%3}, [%4];" \
        : "=r"((r)[0]), "=r"((r)[1]), "=r"((r)[2]), "=r"((r)[3]) : "r"(addr))

#define MMA16816(d, a, b0, b1) \
    asm volatile("mma.sync.aligned.m16n8k16.row.col.f32.bf16.bf16.f32 " \
        "{%0,%1,%2,%3}, {%4,%5,%6,%7}, {%8,%9}, {%0,%1,%2,%3};" \
        : "+f"((d)[0]), "+f"((d)[1]), "+f"((d)[2]), "+f"((d)[3]) \
        : "r"((a)[0]), "r"((a)[1]), "r"((a)[2]), "r"((a)[3]), "r"(b0), "r"(b1))

__device__ __forceinline__ uint32_t pack_bf16(float a, float b){
    __nv_bfloat162 p = __floats2bfloat162_rn(a, b);
    return *(uint32_t*)&p;
}

// split-store a pair (a,b) into hi/lo bf16 buffers at idx (idx even, 4B-aligned)
__device__ __forceinline__ void store_split_pair(__nv_bfloat16* hi, __nv_bfloat16* lo,
                                                 size_t idx, float a, float b){
    __nv_bfloat16 ha = __float2bfloat16(a);
    __nv_bfloat16 hb = __float2bfloat16(b);
    *(__nv_bfloat162*)(hi + idx) = __halves2bfloat162(ha, hb);
    *(__nv_bfloat162*)(lo + idx) =
        __floats2bfloat162_rn(a - __bfloat162float(ha), b - __bfloat162float(hb));
}

// ---------------- conversion passes ----------------
__global__ void split_kernel(const float4* __restrict__ src,
                             __nv_bfloat16* __restrict__ hi, __nv_bfloat16* __restrict__ lo, int n4)
{
    int i = blockIdx.x * blockDim.x + threadIdx.x;
    if (i >= n4) return;
    float4 v = src[i];
    float vv[4] = {v.x, v.y, v.z, v.w};
    #pragma unroll
    for (int j = 0; j < 4; j++) {
        __nv_bfloat16 h = __float2bfloat16(vv[j]);
        hi[4*i + j] = h;
        lo[4*i + j] = __float2bfloat16(vv[j] - __bfloat162float(h));
    }
}

__global__ void transpose_split(const float* __restrict__ W,
                                __nv_bfloat16* __restrict__ hi, __nv_bfloat16* __restrict__ lo,
                                int K, int Nc)
{
    __shared__ float t[32][33];
    int x  = blockIdx.x * 32 + threadIdx.x;
    int y0 = blockIdx.y * 32;
    #pragma unroll
    for (int j = 0; j < 32; j += 8)
        t[threadIdx.y + j][threadIdx.x] = W[(size_t)(y0 + threadIdx.y + j) * Nc + x];
    __syncthreads();
    int ox = y0 + threadIdx.x;
    int oy = blockIdx.x * 32;
    #pragma unroll
    for (int j = 0; j < 32; j += 8) {
        float v = t[threadIdx.x][threadIdx.y + j];
        __nv_bfloat16 h = __float2bfloat16(v);
        hi[(size_t)(oy + threadIdx.y + j) * K + ox] = h;
        lo[(size_t)(oy + threadIdx.y + j) * K + ox] = __float2bfloat16(v - __bfloat162float(h));
    }
}

// compact V [bh][n][64] fp32 -> transposed [bh][d][n] bf16 hi/lo
__global__ void vtsplit_kernel(const float* __restrict__ V,
                               __nv_bfloat16* __restrict__ hi, __nv_bfloat16* __restrict__ lo)
{
    __shared__ float t[32][33];
    int bh = blockIdx.z;
    int n0 = blockIdx.x * 32;
    int d0 = blockIdx.y * 32;
    #pragma unroll
    for (int j = 0; j < 32; j += 8)
        t[threadIdx.y + j][threadIdx.x] =
            V[((size_t)bh * NN + n0 + threadIdx.y + j) * HD + d0 + threadIdx.x];
    __syncthreads();
    #pragma unroll
    for (int j = 0; j < 32; j += 8) {
        float v = t[threadIdx.x][threadIdx.y + j];   // = V[n0+tx][d0+ty+j]
        __nv_bfloat16 hh = __float2bfloat16(v);
        size_t o = ((size_t)bh * HD + d0 + threadIdx.y + j) * NN + n0 + threadIdx.x;
        hi[o] = hh;
        lo[o] = __float2bfloat16(v - __bfloat162float(hh));
    }
}

// ---------------- mma.sync bf16-split GEMM, templated epilogue ----------------
// EPI 0: plain fp32 C       (O projection -> d_out)
// EPI 1: rope+scale+split   (Q projection -> g_qbh/g_qbl [bh][n][64])
// EPI 2: K rope+split / V compact (KV projection -> g_kbh/g_kbl, g_v)
#define TILE_B   10240u
#define STAGE_B  (4u*TILE_B)
#define GEMM_SMEM (2*STAGE_B)

template<int EPI>
__global__ __launch_bounds__(256) void mma_gemm_t(
    const __nv_bfloat16* __restrict__ Ahi, const __nv_bfloat16* __restrict__ Alo,
    const __nv_bfloat16* __restrict__ Bhi, const __nv_bfloat16* __restrict__ Blo,
    float* __restrict__ C,
    const float* __restrict__ rc, const float* __restrict__ rs,
    int Nc, int K)
{
    extern __shared__ __align__(128) char smem[];
    const uint32_t dbase = smem_u32(smem);
    const int tid   = threadIdx.x;
    const int lane  = tid & 31;
    const int wid   = tid >> 5;
    const int warpM = wid & 3;
    const int warpN = wid >> 2;

    const int rowBase = blockIdx.y * 128;
    const int colBase = blockIdx.x * 128;
    const int nChunks = K >> 5;

    const __nv_bfloat16* srcs[4] = {Ahi, Alo, Bhi, Blo};

    auto load_chunk = [&](int chunk, int stage) {
        const uint32_t sbase = dbase + (uint32_t)stage * STAGE_B;
        const int k0 = chunk << 5;
        #pragma unroll
        for (int tile = 0; tile < 4; tile++) {
            const __nv_bfloat16* s = srcs[tile];
            const int gBase = (tile < 2) ? rowBase : colBase;
            const uint32_t tb = sbase + (uint32_t)tile * TILE_B;
            #pragma unroll
            for (int i = 0; i < 2; i++) {
                int idx = tid + (i << 8);
                int r = idx >> 2, c = idx & 3;
                cp16(tb + (uint32_t)(r * 80 + c * 16),
                     s + (size_t)(gBase + r) * K + k0 + c * 8);
            }
        }
        asm volatile("cp.async.commit_group;" ::: "memory");
    };

    const uint32_t aoff = (uint32_t)((warpM * 32 + (lane & 15)) * 80 + (lane >> 4) * 16);
    const uint32_t boff = (uint32_t)((warpN * 64 + (lane & 7) + ((lane >> 4) << 3)) * 80
                                     + ((lane >> 3) & 1) * 16);

    float acc[2][8][4];
    #pragma unroll
    for (int mt = 0; mt < 2; mt++)
        #pragma unroll
        for (int nt = 0; nt < 8; nt++)
            #pragma unroll
            for (int e = 0; e < 4; e++) acc[mt][nt][e] = 0.f;

    load_chunk(0, 0);
    int buf = 0;
    for (int chunk = 0; chunk < nChunks; chunk++) {
        if (chunk + 1 < nChunks) {
            load_chunk(chunk + 1, buf ^ 1);
            asm volatile("cp.async.wait_group 1;" ::: "memory");
        } else {
            asm volatile("cp.async.wait_group 0;" ::: "memory");
        }
        __syncthreads();

        const uint32_t sbase = dbase + (uint32_t)buf * STAGE_B;
        const uint32_t sAh = sbase + aoff;
        const uint32_t sAl = sAh + TILE_B;
        const uint32_t sBh = sbase + 2u * TILE_B + boff;
        const uint32_t sBl = sBh + TILE_B;

        #pragma unroll
        for (int ks = 0; ks < 2; ks++) {
            uint32_t ah[2][4], al[2][4];
            LDSM4(ah[0], sAh + ks * 32);
            LDSM4(ah[1], sAh + 16 * 80 + ks * 32);
            LDSM4(al[0], sAl + ks * 32);
            LDSM4(al[1], sAl + 16 * 80 + ks * 32);
            #pragma unroll
            for (int ntp = 0; ntp < 4; ntp++) {
                uint32_t bh[4], bl[4];
                LDSM4(bh, sBh + ntp * 16 * 80 + ks * 32);
                LDSM4(bl, sBl + ntp * 16 * 80 + ks * 32);
                #pragma unroll
                for (int mt = 0; mt < 2; mt++) {
                    MMA16816(acc[mt][2*ntp],   ah[mt], bh[0], bh[1]);
                    MMA16816(acc[mt][2*ntp],   ah[mt], bl[0], bl[1]);
                    MMA16816(acc[mt][2*ntp],   al[mt], bh[0], bh[1]);
                    MMA16816(acc[mt][2*ntp+1], ah[mt], bh[2], bh[3]);
                    MMA16816(acc[mt][2*ntp+1], ah[mt], bl[2], bl[3]);
                    MMA16816(acc[mt][2*ntp+1], al[mt], bh[2], bh[3]);
                }
            }
        }
        buf ^= 1;
        __syncthreads();
    }

    // ---- epilogues ----
    #pragma unroll
    for (int mt = 0; mt < 2; mt++) {
        int row0 = rowBase + warpM * 32 + mt * 16 + (lane >> 2);
        #pragma unroll
        for (int nt = 0; nt < 8; nt++) {
            int col = colBase + warpN * 64 + nt * 8 + (lane & 3) * 2;

            if (EPI == 0) {
                *(float2*)(C + (size_t)row0 * Nc + col)       = make_float2(acc[mt][nt][0], acc[mt][nt][1]);
                *(float2*)(C + (size_t)(row0 + 8) * Nc + col) = make_float2(acc[mt][nt][2], acc[mt][nt][3]);
            }
            else if (EPI == 1) {
                // Q: rope + 0.125 scale + split -> [b*NH+h][n][64]
                int h = col >> 6, dp = col & 63, p = dp >> 1;
                #pragma unroll
                for (int half = 0; half < 2; half++) {
                    int row = row0 + 8 * half;
                    int b = row >> 11, n = row & (NN - 1);
                    float c = rc[n * 32 + p], s = rs[n * 32 + p];
                    float e = acc[mt][nt][2*half]     * 0.125f;
                    float o = acc[mt][nt][2*half + 1] * 0.125f;
                    float yr = e * c - o * s;
                    float yi = e * s + o * c;
                    size_t idx = ((size_t)(b * NH + h) * NN + n) * HD + dp;
                    store_split_pair(g_qbh, g_qbl, idx, yr, yi);
                }
            }
            else {  // EPI == 2: KV projection
                if (col < NKV * HD) {
                    // K: rope + split -> [b*NKV+h][n][64]
                    int h = col >> 6, dp = col & 63, p = dp >> 1;
                    #pragma unroll
                    for (int half = 0; half < 2; half++) {
                        int row = row0 + 8 * half;
                        int b = row >> 11, n = row & (NN - 1);
                        float c = rc[n * 32 + p], s = rs[n * 32 + p];
                        float e = acc[mt][nt][2*half];
                        float o = acc[mt][nt][2*half + 1];
                        float yr = e * c - o * s;
                        float yi = e * s + o * c;
                        size_t idx = ((size_t)(b * NKV + h) * NN + n) * HD + dp;
                        store_split_pair(g_kbh, g_kbl, idx, yr, yi);
                    }
                } else {
                    // V: compact fp32 [b*NKV+h][n][64]
                    int vc = col - NKV * HD;
                    int h = vc >> 6, d = vc & 63;
                    #pragma unroll
                    for (int half = 0; half < 2; half++) {
                        int row = row0 + 8 * half;
                        int b = row >> 11, n = row & (NN - 1);
                        *(float2*)(g_v + ((size_t)(b * NKV + h) * NN + n) * HD + d) =
                            make_float2(acc[mt][nt][2*half], acc[mt][nt][2*half + 1]);
                    }
                }
            }
        }
    }
}

// ---------------- tensor-core flash attention (double-buffered K/V) ----------------
#define AST 144u
#define AQ_B  (128u*AST)          // 18432 per q buffer
#define AK_B  (64u*AST)           // 9216 per k/v tile
#define AKST  (4u*AK_B)           // 36864 per kv stage (Kh,Kl,Vh,Vl)
#define SM_QH 0u
#define SM_QL AQ_B
#define SM_KV (2u*AQ_B)
#define FLASH_SMEM (2u*AQ_B + 2u*AKST)   // 110592 B

__global__ __launch_bounds__(256) void flash_attn_mma(
    const __nv_bfloat16* __restrict__ Qh, const __nv_bfloat16* __restrict__ Ql,
    const __nv_bfloat16* __restrict__ Kh, const __nv_bfloat16* __restrict__ Kl,
    const __nv_bfloat16* __restrict__ Vh, const __nv_bfloat16* __restrict__ Vl)
{
    extern __shared__ __align__(128) char smem[];
    const uint32_t sb = smem_u32(smem);
    const int tid  = threadIdx.x;
    const int lane = tid & 31;
    const int wid  = tid >> 5;
    const int qb   = blockIdx.x;
    const int head = blockIdx.y;
    const int b    = blockIdx.z;
    const int bhq  = b * NH + head;
    const int bhk  = b * NKV + (head & (NKV - 1));

    const __nv_bfloat16* qh = Qh + ((size_t)bhq * NN + qb * 128) * HD;
    const __nv_bfloat16* ql = Ql + ((size_t)bhq * NN + qb * 128) * HD;
    const __nv_bfloat16* kh = Kh + (size_t)bhk * NN * HD;
    const __nv_bfloat16* kl = Kl + (size_t)bhk * NN * HD;
    const __nv_bfloat16* vh = Vh + (size_t)bhk * HD * NN;
    const __nv_bfloat16* vl = Vl + (size_t)bhk * HD * NN;

    auto load_kv = [&](int kb, int st) {
        const uint32_t base = sb + SM_KV + (uint32_t)st * AKST;
        #pragma unroll
        for (int i = 0; i < 2; i++) {
            int idx = tid + (i << 8);
            int r = idx >> 3, c = idx & 7;
            uint32_t so = (uint32_t)(r * AST + c * 16);
            size_t kg = ((size_t)(kb * 64 + r)) * HD + c * 8;
            size_t vg = ((size_t)r) * NN + kb * 64 + c * 8;
            cp16(base + so,            kh + kg);
            cp16(base + AK_B + so,     kl + kg);
            cp16(base + 2u*AK_B + so,  vh + vg);
            cp16(base + 3u*AK_B + so,  vl + vg);
        }
        asm volatile("cp.async.commit_group;" ::: "memory");
    };

    // ---- load Q + first KV tile ----
    #pragma unroll
    for (int i = 0; i < 4; i++) {
        int idx = tid + (i << 8);
        int r = idx >> 3, c = idx & 7;
        cp16(sb + SM_QH + (uint32_t)(r * AST + c * 16), qh + (size_t)r * HD + c * 8);
        cp16(sb + SM_QL + (uint32_t)(r * AST + c * 16), ql + (size_t)r * HD + c * 8);
    }
    asm volatile("cp.async.commit_group;" ::: "memory");
    load_kv(0, 0);
    asm volatile("cp.async.wait_group 0;" ::: "memory");
    __syncthreads();

    // ---- ldmatrix Q fragments ----
    const uint32_t qoff = (uint32_t)((wid * 16 + (lane & 15)) * AST + (lane >> 4) * 16);
    uint32_t qfh[4][4], qfl[4][4];
    #pragma unroll
    for (int ks = 0; ks < 4; ks++) {
        LDSM4(qfh[ks], sb + SM_QH + qoff + ks * 32);
        LDSM4(qfl[ks], sb + SM_QL + qoff + ks * 32);
    }
    __syncthreads();

    const uint32_t boff = (uint32_t)(((lane & 7) + ((lane >> 4) << 3)) * AST + ((lane >> 3) & 1) * 16);

    float oacc[8][4];
    #pragma unroll
    for (int nt = 0; nt < 8; nt++)
        #pragma unroll
        for (int e = 0; e < 4; e++) oacc[nt][e] = 0.f;
    float m[2] = {-1e30f, -1e30f};
    float l[2] = {0.f, 0.f};

    const int r0 = qb * 128 + wid * 16 + (lane >> 2);
    const int kbmax = 2 * qb + 1;

    for (int kb = 0; kb <= kbmax; kb++) {
        const int st = kb & 1;
        if (kb + 1 <= kbmax) {
            load_kv(kb + 1, st ^ 1);
            asm volatile("cp.async.wait_group 1;" ::: "memory");
        } else {
            asm volatile("cp.async.wait_group 0;" ::: "memory");
        }
        __syncthreads();

        const uint32_t skh = sb + SM_KV + (uint32_t)st * AKST + boff;
        const uint32_t skl = skh + AK_B;
        const uint32_t svh = skh + 2u*AK_B;
        const uint32_t svl = skh + 3u*AK_B;

        // ---- S = Q K^T ----
        float sacc[8][4];
        #pragma unroll
        for (int nt = 0; nt < 8; nt++)
            #pragma unroll
            for (int e = 0; e < 4; e++) sacc[nt][e] = 0.f;

        #pragma unroll
        for (int ks = 0; ks < 4; ks++) {
            #pragma unroll
            for (int kg = 0; kg < 4; kg++) {
                uint32_t bh_[4], bl_[4];
                LDSM4(bh_, skh + (uint32_t)(kg * 16 * AST) + ks * 32);
                LDSM4(bl_, skl + (uint32_t)(kg * 16 * AST) + ks * 32);
                MMA16816(sacc[2*kg],   qfh[ks], bh_[0], bh_[1]);
                MMA16816(sacc[2*kg],   qfh[ks], bl_[0], bl_[1]);
                MMA16816(sacc[2*kg],   qfl[ks], bh_[0], bh_[1]);
                MMA16816(sacc[2*kg+1], qfh[ks], bh_[2], bh_[3]);
                MMA16816(sacc[2*kg+1], qfh[ks], bl_[2], bl_[3]);
                MMA16816(sacc[2*kg+1], qfl[ks], bh_[2], bh_[3]);
            }
        }

        // ---- causal mask ----
        if (kb * 64 + 63 > r0) {
            #pragma unroll
            for (int nt = 0; nt < 8; nt++) {
                int c = kb * 64 + nt * 8 + (lane & 3) * 2;
                if (c > r0)         sacc[nt][0] = -1e30f;
                if (c + 1 > r0)     sacc[nt][1] = -1e30f;
                if (c > r0 + 8)     sacc[nt][2] = -1e30f;
                if (c + 1 > r0 + 8) sacc[nt][3] = -1e30f;
            }
        }

        // ---- online softmax ----
        float rmax[2] = {-1e30f, -1e30f};
        #pragma unroll
        for (int nt = 0; nt < 8; nt++) {
            rmax[0] = fmaxf(rmax[0], fmaxf(sacc[nt][0], sacc[nt][1]));
            rmax[1] = fmaxf(rmax[1], fmaxf(sacc[nt][2], sacc[nt][3]));
        }
        #pragma unroll
        for (int w = 1; w <= 2; w <<= 1) {
            rmax[0] = fmaxf(rmax[0], __shfl_xor_sync(0xffffffffu, rmax[0], w));
            rmax[1] = fmaxf(rmax[1], __shfl_xor_sync(0xffffffffu, rmax[1], w));
        }
        float nm0 = fmaxf(m[0], rmax[0]);
        float nm1 = fmaxf(m[1], rmax[1]);
        float c0 = __expf(m[0] - nm0);
        float c1 = __expf(m[1] - nm1);
        m[0] = nm0; m[1] = nm1;
        #pragma unroll
        for (int nt = 0; nt < 8; nt++) {
            oacc[nt][0] *= c0; oacc[nt][1] *= c0;
            oacc[nt][2] *= c1; oacc[nt][3] *= c1;
        }
        float sum0 = 0.f, sum1 = 0.f;
        uint32_t ph[8][2], pl[8][2];
        #pragma unroll
        for (int nt = 0; nt < 8; nt++) {
            float p0 = __expf(sacc[nt][0] - nm0);
            float p1 = __expf(sacc[nt][1] - nm0);
            float p2 = __expf(sacc[nt][2] - nm1);
            float p3 = __expf(sacc[nt][3] - nm1);
            sum0 += p0 + p1; sum1 += p2 + p3;
            float h0 = __bfloat162float(__float2bfloat16(p0));
            float h1 = __bfloat162float(__float2bfloat16(p1));
            float h2 = __bfloat162float(__float2bfloat16(p2));
            float h3 = __bfloat162float(__float2bfloat16(p3));
            ph[nt][0] = pack_bf16(h0, h1);
            ph[nt][1] = pack_bf16(h2, h3);
            pl[nt][0] = pack_bf16(p0 - h0, p1 - h1);
            pl[nt][1] = pack_bf16(p2 - h2, p3 - h3);
        }
        #pragma unroll
        for (int w = 1; w <= 2; w <<= 1) {
            sum0 += __shfl_xor_sync(0xffffffffu, sum0, w);
            sum1 += __shfl_xor_sync(0xffffffffu, sum1, w);
        }
        l[0] = l[0] * c0 + sum0;
        l[1] = l[1] * c1 + sum1;

        // ---- O += P V ----
        #pragma unroll
        for (int ks = 0; ks < 4; ks++) {
            uint32_t aph[4] = {ph[2*ks][0], ph[2*ks][1], ph[2*ks+1][0], ph[2*ks+1][1]};
            uint32_t apl[4] = {pl[2*ks][0], pl[2*ks][1], pl[2*ks+1][0], pl[2*ks+1][1]};
            #pragma unroll
            for (int dg = 0; dg < 4; dg++) {
                uint32_t vbh[4], vbl[4];
                LDSM4(vbh, svh + (uint32_t)(dg * 16 * AST) + ks * 32);
                LDSM4(vbl, svl + (uint32_t)(dg * 16 * AST) + ks * 32);
                MMA16816(oacc[2*dg],   aph, vbh[0], vbh[1]);
                MMA16816(oacc[2*dg],   aph, vbl[0], vbl[1]);
                MMA16816(oacc[2*dg],   apl, vbh[0], vbh[1]);
                MMA16816(oacc[2*dg+1], aph, vbh[2], vbh[3]);
                MMA16816(oacc[2*dg+1], aph, vbl[2], vbl[3]);
                MMA16816(oacc[2*dg+1], apl, vbh[2], vbh[3]);
            }
        }
        __syncthreads();
    }

    // ---- write O as bf16 hi/lo directly (O-proj A operands) ----
    float inv0 = 1.f / l[0];
    float inv1 = 1.f / l[1];
    size_t row = (size_t)(b * NN) + r0;
    #pragma unroll
    for (int nt = 0; nt < 8; nt++) {
        int col = head * HD + nt * 8 + (lane & 3) * 2;
        store_split_pair(g_ahi, g_alo, row * DIMX + col,
                         oacc[nt][0] * inv0, oacc[nt][1] * inv0);
        store_split_pair(g_ahi, g_alo, (row + 8) * DIMX + col,
                         oacc[nt][2] * inv1, oacc[nt][3] * inv1);
    }
}

// ---------------- launch ----------------
extern "C" void kernel_launch(void* const* d_in, const int* in_sizes, int n_in,
                              void* d_out, int out_size)
{
    const float* x   = (const float*)d_in[0];
    const float* Wq  = (const float*)d_in[1];
    const float* Wkv = (const float*)d_in[2];
    const float* Wo  = (const float*)d_in[3];
    const float* rc  = (const float*)d_in[4];
    const float* rs  = (const float*)d_in[5];
    float* out = (float*)d_out;

    __nv_bfloat16 *xhi, *xlo, *wqh, *wql, *wkvh, *wkvl, *woh, *wol, *ahi, *alo;
    __nv_bfloat16 *qbh, *qbl, *kbh, *kbl, *vth, *vtl;
    float* v;
    cudaGetSymbolAddress((void**)&xhi,  g_xhi);
    cudaGetSymbolAddress((void**)&xlo,  g_xlo);
    cudaGetSymbolAddress((void**)&wqh,  g_wqh);
    cudaGetSymbolAddress((void**)&wql,  g_wql);
    cudaGetSymbolAddress((void**)&wkvh, g_wkvh);
    cudaGetSymbolAddress((void**)&wkvl, g_wkvl);
    cudaGetSymbolAddress((void**)&woh,  g_woh);
    cudaGetSymbolAddress((void**)&wol,  g_wol);
    cudaGetSymbolAddress((void**)&ahi,  g_ahi);
    cudaGetSymbolAddress((void**)&alo,  g_alo);
    cudaGetSymbolAddress((void**)&qbh,  g_qbh);
    cudaGetSymbolAddress((void**)&qbl,  g_qbl);
    cudaGetSymbolAddress((void**)&kbh,  g_kbh);
    cudaGetSymbolAddress((void**)&kbl,  g_kbl);
    cudaGetSymbolAddress((void**)&v,    g_v);
    cudaGetSymbolAddress((void**)&vth,  g_vth);
    cudaGetSymbolAddress((void**)&vtl,  g_vtl);

    cudaFuncSetAttribute(mma_gemm_t<0>, cudaFuncAttributeMaxDynamicSharedMemorySize, GEMM_SMEM);
    cudaFuncSetAttribute(mma_gemm_t<1>, cudaFuncAttributeMaxDynamicSharedMemorySize, GEMM_SMEM);
    cudaFuncSetAttribute(mma_gemm_t<2>, cudaFuncAttributeMaxDynamicSharedMemorySize, GEMM_SMEM);
    cudaFuncSetAttribute(flash_attn_mma, cudaFuncAttributeMaxDynamicSharedMemorySize, FLASH_SMEM);

    // 1. split x
    int n4x = MM * DIMX / 4;
    split_kernel<<<(n4x + 255) / 256, 256>>>((const float4*)x, xhi, xlo, n4x);

    // 2. weights
    transpose_split<<<dim3(DIMX / 32, DIMX / 32), dim3(32, 8)>>>(Wq,  wqh,  wql,  DIMX, DIMX);
    transpose_split<<<dim3(KVW  / 32, DIMX / 32), dim3(32, 8)>>>(Wkv, wkvh, wkvl, DIMX, KVW);
    transpose_split<<<dim3(DIMX / 32, DIMX / 32), dim3(32, 8)>>>(Wo,  woh,  wol,  DIMX, DIMX);

    // 3. Q projection (fused rope+scale+split epilogue)
    mma_gemm_t<1><<<dim3(DIMX / 128, MM / 128), 256, GEMM_SMEM>>>(
        xhi, xlo, wqh, wql, nullptr, rc, rs, DIMX, DIMX);
    // 4. KV projection (fused K-rope+split / V-compact epilogue)
    mma_gemm_t<2><<<dim3(KVW / 128, MM / 128), 256, GEMM_SMEM>>>(
        xhi, xlo, wkvh, wkvl, nullptr, rc, rs, KVW, DIMX);

    // 5. V transpose+split
    vtsplit_kernel<<<dim3(NN / 32, HD / 32, BB * NKV), dim3(32, 8)>>>(v, vth, vtl);

    // 6. flash attention (writes bf16 hi/lo directly)
    flash_attn_mma<<<dim3(NN / 128, NH, BB), 256, FLASH_SMEM>>>(
        qbh, qbl, kbh, kbl, vth, vtl);

    // 7. output projection
    mma_gemm_t<0><<<dim3(DIMX / 128, MM / 128), 256, GEMM_SMEM>>>(
        ahi, alo, woh, wol, out, nullptr, nullptr, DIMX, DIMX);
}

// round 8
// speedup vs baseline: 4.3532x; 1.3265x over previous
#include <cuda_runtime.h>
#include <cuda_bf16.h>
#include <cuda_fp16.h>
#include <cstdint>
#include <cstddef>

#define BB   2
#define NN   2048
#define DIMX 2048
#define NH   32
#define NKV  8
#define HD   64
#define KVW  (2*NKV*HD)   // 1024
#define MM   (BB*NN)      // 4096

// ---------------- scratch (__device__ globals; allocation-free rule) ----------------
__device__ __nv_bfloat16 g_xhi [(size_t)MM*DIMX];
__device__ __nv_bfloat16 g_xlo [(size_t)MM*DIMX];
__device__ __nv_bfloat16 g_wqh [(size_t)DIMX*DIMX];
__device__ __nv_bfloat16 g_wql [(size_t)DIMX*DIMX];
__device__ __nv_bfloat16 g_wkvh[(size_t)KVW*DIMX];
__device__ __nv_bfloat16 g_wkvl[(size_t)KVW*DIMX];
__device__ __half        g_woth[(size_t)DIMX*DIMX];   // Wo transposed, single fp16
__device__ __half        g_aht [(size_t)MM*DIMX];     // flash out, single fp16

// attention-layout buffers
__device__ __nv_bfloat16 g_qbh [(size_t)BB*NH*NN*HD];   // [bh][n][d] hi (rope+scale)
__device__ __nv_bfloat16 g_qbl [(size_t)BB*NH*NN*HD];
__device__ __nv_bfloat16 g_kbh [(size_t)BB*NKV*NN*HD];  // [bh][n][d] hi (rope)
__device__ __nv_bfloat16 g_kbl [(size_t)BB*NKV*NN*HD];
__device__ __half        g_v   [(size_t)BB*NKV*NN*HD];  // compact V fp16 [bh][n][d]
__device__ __half        g_vt  [(size_t)BB*NKV*HD*NN];  // [bh][d][n] fp16 (transposed)

// ---------------- helpers (baseline PTX ISA only) ----------------
__device__ __forceinline__ uint32_t smem_u32(const void* p){
    uint32_t a;
    asm("{ .reg .u64 t; cvta.to.shared.u64 t, %1; cvt.u32.u64 %0, t; }" : "=r"(a) : "l"(p));
    return a;
}
__device__ __forceinline__ void cp16(uint32_t dst, const void* src){
    asm volatile("cp.async.cg.shared.global [%0], [%1], 16;" :: "r"(dst), "l"(src));
}

#define LDSM4(r, addr) \
    asm volatile("ldmatrix.sync.aligned.m8n8.x4.shared.b16 {%0,%1,%2,%3}, [%4];" \
        : "=r"((r)[0]), "=r"((r)[1]), "=r"((r)[2]), "=r"((r)[3]) : "r"(addr))

#define MMA16816(d, a, b0, b1) \
    asm volatile("mma.sync.aligned.m16n8k16.row.col.f32.bf16.bf16.f32 " \
        "{%0,%1,%2,%3}, {%4,%5,%6,%7}, {%8,%9}, {%0,%1,%2,%3};" \
        : "+f"((d)[0]), "+f"((d)[1]), "+f"((d)[2]), "+f"((d)[3]) \
        : "r"((a)[0]), "r"((a)[1]), "r"((a)[2]), "r"((a)[3]), "r"(b0), "r"(b1))

#define MMA16816F16(d, a, b0, b1) \
    asm volatile("mma.sync.aligned.m16n8k16.row.col.f32.f16.f16.f32 " \
        "{%0,%1,%2,%3}, {%4,%5,%6,%7}, {%8,%9}, {%0,%1,%2,%3};" \
        : "+f"((d)[0]), "+f"((d)[1]), "+f"((d)[2]), "+f"((d)[3]) \
        : "r"((a)[0]), "r"((a)[1]), "r"((a)[2]), "r"((a)[3]), "r"(b0), "r"(b1))

__device__ __forceinline__ uint32_t pack_half(float a, float b){
    __half2 p = __floats2half2_rn(a, b);
    return *(uint32_t*)&p;
}

// split-store a pair (a,b) into hi/lo bf16 buffers at idx (idx even)
__device__ __forceinline__ void store_split_pair(__nv_bfloat16* hi, __nv_bfloat16* lo,
                                                 size_t idx, float a, float b){
    __nv_bfloat16 ha = __float2bfloat16(a);
    __nv_bfloat16 hb = __float2bfloat16(b);
    *(__nv_bfloat162*)(hi + idx) = __halves2bfloat162(ha, hb);
    *(__nv_bfloat162*)(lo + idx) =
        __floats2bfloat162_rn(a - __bfloat162float(ha), b - __bfloat162float(hb));
}

// ---------------- conversion passes ----------------
__global__ void split_kernel(const float4* __restrict__ src,
                             __nv_bfloat16* __restrict__ hi, __nv_bfloat16* __restrict__ lo, int n4)
{
    int i = blockIdx.x * blockDim.x + threadIdx.x;
    if (i >= n4) return;
    float4 v = src[i];
    float vv[4] = {v.x, v.y, v.z, v.w};
    #pragma unroll
    for (int j = 0; j < 4; j++) {
        __nv_bfloat16 h = __float2bfloat16(vv[j]);
        hi[4*i + j] = h;
        lo[4*i + j] = __float2bfloat16(vv[j] - __bfloat162float(h));
    }
}

__global__ void transpose_split(const float* __restrict__ W,
                                __nv_bfloat16* __restrict__ hi, __nv_bfloat16* __restrict__ lo,
                                int K, int Nc)
{
    __shared__ float t[32][33];
    int x  = blockIdx.x * 32 + threadIdx.x;
    int y0 = blockIdx.y * 32;
    #pragma unroll
    for (int j = 0; j < 32; j += 8)
        t[threadIdx.y + j][threadIdx.x] = W[(size_t)(y0 + threadIdx.y + j) * Nc + x];
    __syncthreads();
    int ox = y0 + threadIdx.x;
    int oy = blockIdx.x * 32;
    #pragma unroll
    for (int j = 0; j < 32; j += 8) {
        float v = t[threadIdx.x][threadIdx.y + j];
        __nv_bfloat16 h = __float2bfloat16(v);
        hi[(size_t)(oy + threadIdx.y + j) * K + ox] = h;
        lo[(size_t)(oy + threadIdx.y + j) * K + ox] = __float2bfloat16(v - __bfloat162float(h));
    }
}

// W [K, Nc] fp32 -> Wt [Nc, K] single fp16
__global__ void transpose_half(const float* __restrict__ W, __half* __restrict__ out,
                               int K, int Nc)
{
    __shared__ float t[32][33];
    int x  = blockIdx.x * 32 + threadIdx.x;
    int y0 = blockIdx.y * 32;
    #pragma unroll
    for (int j = 0; j < 32; j += 8)
        t[threadIdx.y + j][threadIdx.x] = W[(size_t)(y0 + threadIdx.y + j) * Nc + x];
    __syncthreads();
    int ox = y0 + threadIdx.x;
    int oy = blockIdx.x * 32;
    #pragma unroll
    for (int j = 0; j < 32; j += 8)
        out[(size_t)(oy + threadIdx.y + j) * K + ox] = __float2half(t[threadIdx.x][threadIdx.y + j]);
}

// compact V fp16 [bh][n][64] -> transposed [bh][d][n] fp16
__global__ void vtsplit_kernel(const __half* __restrict__ V, __half* __restrict__ out)
{
    __shared__ float t[32][33];
    int bh = blockIdx.z;
    int n0 = blockIdx.x * 32;
    int d0 = blockIdx.y * 32;
    #pragma unroll
    for (int j = 0; j < 32; j += 8)
        t[threadIdx.y + j][threadIdx.x] =
            __half2float(V[((size_t)bh * NN + n0 + threadIdx.y + j) * HD + d0 + threadIdx.x]);
    __syncthreads();
    #pragma unroll
    for (int j = 0; j < 32; j += 8) {
        size_t o = ((size_t)bh * HD + d0 + threadIdx.y + j) * NN + n0 + threadIdx.x;
        out[o] = __float2half(t[threadIdx.x][threadIdx.y + j]);
    }
}

// ---------------- 3-term bf16 GEMM (Q / KV projections, fused epilogues) ----------------
// EPI 1: rope+scale+split   (Q projection -> g_qbh/g_qbl)
// EPI 2: K rope+split / V compact fp16 (KV projection)
#define TILE_B   10240u
#define STAGE_B  (4u*TILE_B)
#define GEMM_SMEM (2*STAGE_B)

template<int EPI>
__global__ __launch_bounds__(256) void mma_gemm_t(
    const __nv_bfloat16* __restrict__ Ahi, const __nv_bfloat16* __restrict__ Alo,
    const __nv_bfloat16* __restrict__ Bhi, const __nv_bfloat16* __restrict__ Blo,
    const float* __restrict__ rc, const float* __restrict__ rs,
    int Nc, int K)
{
    extern __shared__ __align__(128) char smem[];
    const uint32_t dbase = smem_u32(smem);
    const int tid   = threadIdx.x;
    const int lane  = tid & 31;
    const int wid   = tid >> 5;
    const int warpM = wid & 3;
    const int warpN = wid >> 2;

    const int rowBase = blockIdx.y * 128;
    const int colBase = blockIdx.x * 128;
    const int nChunks = K >> 5;

    const __nv_bfloat16* srcs[4] = {Ahi, Alo, Bhi, Blo};

    auto load_chunk = [&](int chunk, int stage) {
        const uint32_t sbase = dbase + (uint32_t)stage * STAGE_B;
        const int k0 = chunk << 5;
        #pragma unroll
        for (int tile = 0; tile < 4; tile++) {
            const __nv_bfloat16* s = srcs[tile];
            const int gBase = (tile < 2) ? rowBase : colBase;
            const uint32_t tb = sbase + (uint32_t)tile * TILE_B;
            #pragma unroll
            for (int i = 0; i < 2; i++) {
                int idx = tid + (i << 8);
                int r = idx >> 2, c = idx & 3;
                cp16(tb + (uint32_t)(r * 80 + c * 16),
                     s + (size_t)(gBase + r) * K + k0 + c * 8);
            }
        }
        asm volatile("cp.async.commit_group;" ::: "memory");
    };

    const uint32_t aoff = (uint32_t)((warpM * 32 + (lane & 15)) * 80 + (lane >> 4) * 16);
    const uint32_t boff = (uint32_t)((warpN * 64 + (lane & 7) + ((lane >> 4) << 3)) * 80
                                     + ((lane >> 3) & 1) * 16);

    float acc[2][8][4];
    #pragma unroll
    for (int mt = 0; mt < 2; mt++)
        #pragma unroll
        for (int nt = 0; nt < 8; nt++)
            #pragma unroll
            for (int e = 0; e < 4; e++) acc[mt][nt][e] = 0.f;

    load_chunk(0, 0);
    int buf = 0;
    for (int chunk = 0; chunk < nChunks; chunk++) {
        if (chunk + 1 < nChunks) {
            load_chunk(chunk + 1, buf ^ 1);
            asm volatile("cp.async.wait_group 1;" ::: "memory");
        } else {
            asm volatile("cp.async.wait_group 0;" ::: "memory");
        }
        __syncthreads();

        const uint32_t sbase = dbase + (uint32_t)buf * STAGE_B;
        const uint32_t sAh = sbase + aoff;
        const uint32_t sAl = sAh + TILE_B;
        const uint32_t sBh = sbase + 2u * TILE_B + boff;
        const uint32_t sBl = sBh + TILE_B;

        #pragma unroll
        for (int ks = 0; ks < 2; ks++) {
            uint32_t ah[2][4], al[2][4];
            LDSM4(ah[0], sAh + ks * 32);
            LDSM4(ah[1], sAh + 16 * 80 + ks * 32);
            LDSM4(al[0], sAl + ks * 32);
            LDSM4(al[1], sAl + 16 * 80 + ks * 32);
            #pragma unroll
            for (int ntp = 0; ntp < 4; ntp++) {
                uint32_t bh[4], bl[4];
                LDSM4(bh, sBh + ntp * 16 * 80 + ks * 32);
                LDSM4(bl, sBl + ntp * 16 * 80 + ks * 32);
                #pragma unroll
                for (int mt = 0; mt < 2; mt++) {
                    MMA16816(acc[mt][2*ntp],   ah[mt], bh[0], bh[1]);
                    MMA16816(acc[mt][2*ntp],   ah[mt], bl[0], bl[1]);
                    MMA16816(acc[mt][2*ntp],   al[mt], bh[0], bh[1]);
                    MMA16816(acc[mt][2*ntp+1], ah[mt], bh[2], bh[3]);
                    MMA16816(acc[mt][2*ntp+1], ah[mt], bl[2], bl[3]);
                    MMA16816(acc[mt][2*ntp+1], al[mt], bh[2], bh[3]);
                }
            }
        }
        buf ^= 1;
        __syncthreads();
    }

    // ---- epilogues ----
    #pragma unroll
    for (int mt = 0; mt < 2; mt++) {
        int row0 = rowBase + warpM * 32 + mt * 16 + (lane >> 2);
        #pragma unroll
        for (int nt = 0; nt < 8; nt++) {
            int col = colBase + warpN * 64 + nt * 8 + (lane & 3) * 2;

            if (EPI == 1) {
                int h = col >> 6, dp = col & 63, p = dp >> 1;
                #pragma unroll
                for (int half = 0; half < 2; half++) {
                    int row = row0 + 8 * half;
                    int b = row >> 11, n = row & (NN - 1);
                    float c = rc[n * 32 + p], s = rs[n * 32 + p];
                    float e = acc[mt][nt][2*half]     * 0.125f;
                    float o = acc[mt][nt][2*half + 1] * 0.125f;
                    float yr = e * c - o * s;
                    float yi = e * s + o * c;
                    size_t idx = ((size_t)(b * NH + h) * NN + n) * HD + dp;
                    store_split_pair(g_qbh, g_qbl, idx, yr, yi);
                }
            }
            else {  // EPI == 2
                if (col < NKV * HD) {
                    int h = col >> 6, dp = col & 63, p = dp >> 1;
                    #pragma unroll
                    for (int half = 0; half < 2; half++) {
                        int row = row0 + 8 * half;
                        int b = row >> 11, n = row & (NN - 1);
                        float c = rc[n * 32 + p], s = rs[n * 32 + p];
                        float e = acc[mt][nt][2*half];
                        float o = acc[mt][nt][2*half + 1];
                        float yr = e * c - o * s;
                        float yi = e * s + o * c;
                        size_t idx = ((size_t)(b * NKV + h) * NN + n) * HD + dp;
                        store_split_pair(g_kbh, g_kbl, idx, yr, yi);
                    }
                } else {
                    int vc = col - NKV * HD;
                    int h = vc >> 6, d = vc & 63;
                    #pragma unroll
                    for (int half = 0; half < 2; half++) {
                        int row = row0 + 8 * half;
                        int b = row >> 11, n = row & (NN - 1);
                        *(__half2*)(g_v + ((size_t)(b * NKV + h) * NN + n) * HD + d) =
                            __floats2half2_rn(acc[mt][nt][2*half], acc[mt][nt][2*half + 1]);
                    }
                }
            }
        }
    }
}

// ---------------- 1-term fp16 GEMM (O projection -> d_out fp32) ----------------
#define H1_STAGE (2u*TILE_B)
#define H1_SMEM  (2u*H1_STAGE)   // 40960

__global__ __launch_bounds__(256) void mma_gemm_h1(
    const __half* __restrict__ A, const __half* __restrict__ B,
    float* __restrict__ C, int Nc, int K)
{
    extern __shared__ __align__(128) char smem[];
    const uint32_t dbase = smem_u32(smem);
    const int tid   = threadIdx.x;
    const int lane  = tid & 31;
    const int wid   = tid >> 5;
    const int warpM = wid & 3;
    const int warpN = wid >> 2;

    const int rowBase = blockIdx.y * 128;
    const int colBase = blockIdx.x * 128;
    const int nChunks = K >> 5;

    auto load_chunk = [&](int chunk, int stage) {
        const uint32_t sbase = dbase + (uint32_t)stage * H1_STAGE;
        const int k0 = chunk << 5;
        #pragma unroll
        for (int tile = 0; tile < 2; tile++) {
            const __half* s = tile ? B : A;
            const int gBase = tile ? colBase : rowBase;
            const uint32_t tb = sbase + (uint32_t)tile * TILE_B;
            #pragma unroll
            for (int i = 0; i < 2; i++) {
                int idx = tid + (i << 8);
                int r = idx >> 2, c = idx & 3;
                cp16(tb + (uint32_t)(r * 80 + c * 16),
                     s + (size_t)(gBase + r) * K + k0 + c * 8);
            }
        }
        asm volatile("cp.async.commit_group;" ::: "memory");
    };

    const uint32_t aoff = (uint32_t)((warpM * 32 + (lane & 15)) * 80 + (lane >> 4) * 16);
    const uint32_t boff = (uint32_t)((warpN * 64 + (lane & 7) + ((lane >> 4) << 3)) * 80
                                     + ((lane >> 3) & 1) * 16);

    float acc[2][8][4];
    #pragma unroll
    for (int mt = 0; mt < 2; mt++)
        #pragma unroll
        for (int nt = 0; nt < 8; nt++)
            #pragma unroll
            for (int e = 0; e < 4; e++) acc[mt][nt][e] = 0.f;

    load_chunk(0, 0);
    int buf = 0;
    for (int chunk = 0; chunk < nChunks; chunk++) {
        if (chunk + 1 < nChunks) {
            load_chunk(chunk + 1, buf ^ 1);
            asm volatile("cp.async.wait_group 1;" ::: "memory");
        } else {
            asm volatile("cp.async.wait_group 0;" ::: "memory");
        }
        __syncthreads();

        const uint32_t sbase = dbase + (uint32_t)buf * H1_STAGE;
        const uint32_t sA = sbase + aoff;
        const uint32_t sB = sbase + TILE_B + boff;

        #pragma unroll
        for (int ks = 0; ks < 2; ks++) {
            uint32_t ah[2][4];
            LDSM4(ah[0], sA + ks * 32);
            LDSM4(ah[1], sA + 16 * 80 + ks * 32);
            #pragma unroll
            for (int ntp = 0; ntp < 4; ntp++) {
                uint32_t bh[4];
                LDSM4(bh, sB + ntp * 16 * 80 + ks * 32);
                #pragma unroll
                for (int mt = 0; mt < 2; mt++) {
                    MMA16816F16(acc[mt][2*ntp],   ah[mt], bh[0], bh[1]);
                    MMA16816F16(acc[mt][2*ntp+1], ah[mt], bh[2], bh[3]);
                }
            }
        }
        buf ^= 1;
        __syncthreads();
    }

    #pragma unroll
    for (int mt = 0; mt < 2; mt++) {
        int row0 = rowBase + warpM * 32 + mt * 16 + (lane >> 2);
        #pragma unroll
        for (int nt = 0; nt < 8; nt++) {
            int col = colBase + warpN * 64 + nt * 8 + (lane & 3) * 2;
            *(float2*)(C + (size_t)row0 * Nc + col)       = make_float2(acc[mt][nt][0], acc[mt][nt][1]);
            *(float2*)(C + (size_t)(row0 + 8) * Nc + col) = make_float2(acc[mt][nt][2], acc[mt][nt][3]);
        }
    }
}

// ---------------- tensor-core flash attention ----------------
// Q/K: bf16 3-term (score path). P/V: single fp16. Out: single fp16 to g_aht.
#define AST 144u
#define AQ_B  (128u*AST)          // 18432 per q buffer
#define AK_B  (64u*AST)           // 9216 per tile
#define AKST  (3u*AK_B)           // 27648 per kv stage (Kh,Kl,V)
#define SM_QH 0u
#define SM_QL AQ_B
#define SM_KV (2u*AQ_B)
#define FLASH_SMEM (2u*AQ_B + 2u*AKST)   // 92160 B

__global__ __launch_bounds__(256) void flash_attn_mma(
    const __nv_bfloat16* __restrict__ Qh, const __nv_bfloat16* __restrict__ Ql,
    const __nv_bfloat16* __restrict__ Kh, const __nv_bfloat16* __restrict__ Kl,
    const __half* __restrict__ Vt)
{
    extern __shared__ __align__(128) char smem[];
    const uint32_t sb = smem_u32(smem);
    const int tid  = threadIdx.x;
    const int lane = tid & 31;
    const int wid  = tid >> 5;
    const int qb   = blockIdx.x;
    const int head = blockIdx.y;
    const int b    = blockIdx.z;
    const int bhq  = b * NH + head;
    const int bhk  = b * NKV + (head & (NKV - 1));

    const __nv_bfloat16* qh = Qh + ((size_t)bhq * NN + qb * 128) * HD;
    const __nv_bfloat16* ql = Ql + ((size_t)bhq * NN + qb * 128) * HD;
    const __nv_bfloat16* kh = Kh + (size_t)bhk * NN * HD;
    const __nv_bfloat16* kl = Kl + (size_t)bhk * NN * HD;
    const __half*        vt = Vt + (size_t)bhk * HD * NN;

    auto load_kv = [&](int kb, int st) {
        const uint32_t base = sb + SM_KV + (uint32_t)st * AKST;
        #pragma unroll
        for (int i = 0; i < 2; i++) {
            int idx = tid + (i << 8);
            int r = idx >> 3, c = idx & 7;
            uint32_t so = (uint32_t)(r * AST + c * 16);
            size_t kg = ((size_t)(kb * 64 + r)) * HD + c * 8;
            size_t vg = ((size_t)r) * NN + kb * 64 + c * 8;
            cp16(base + so,           kh + kg);
            cp16(base + AK_B + so,    kl + kg);
            cp16(base + 2u*AK_B + so, vt + vg);
        }
        asm volatile("cp.async.commit_group;" ::: "memory");
    };

    // ---- load Q + first KV tile ----
    #pragma unroll
    for (int i = 0; i < 4; i++) {
        int idx = tid + (i << 8);
        int r = idx >> 3, c = idx & 7;
        cp16(sb + SM_QH + (uint32_t)(r * AST + c * 16), qh + (size_t)r * HD + c * 8);
        cp16(sb + SM_QL + (uint32_t)(r * AST + c * 16), ql + (size_t)r * HD + c * 8);
    }
    asm volatile("cp.async.commit_group;" ::: "memory");
    load_kv(0, 0);
    asm volatile("cp.async.wait_group 0;" ::: "memory");
    __syncthreads();

    const uint32_t qoff = (uint32_t)((wid * 16 + (lane & 15)) * AST + (lane >> 4) * 16);
    uint32_t qfh[4][4], qfl[4][4];
    #pragma unroll
    for (int ks = 0; ks < 4; ks++) {
        LDSM4(qfh[ks], sb + SM_QH + qoff + ks * 32);
        LDSM4(qfl[ks], sb + SM_QL + qoff + ks * 32);
    }
    __syncthreads();

    const uint32_t boff = (uint32_t)(((lane & 7) + ((lane >> 4) << 3)) * AST + ((lane >> 3) & 1) * 16);

    float oacc[8][4];
    #pragma unroll
    for (int nt = 0; nt < 8; nt++)
        #pragma unroll
        for (int e = 0; e < 4; e++) oacc[nt][e] = 0.f;
    float m[2] = {-1e30f, -1e30f};
    float l[2] = {0.f, 0.f};

    const int r0 = qb * 128 + wid * 16 + (lane >> 2);
    const int kbmax = 2 * qb + 1;

    for (int kb = 0; kb <= kbmax; kb++) {
        const int st = kb & 1;
        if (kb + 1 <= kbmax) {
            load_kv(kb + 1, st ^ 1);
            asm volatile("cp.async.wait_group 1;" ::: "memory");
        } else {
            asm volatile("cp.async.wait_group 0;" ::: "memory");
        }
        __syncthreads();

        const uint32_t skh = sb + SM_KV + (uint32_t)st * AKST + boff;
        const uint32_t skl = skh + AK_B;
        const uint32_t sv  = skh + 2u*AK_B;

        // ---- S = Q K^T (3-term bf16) ----
        float sacc[8][4];
        #pragma unroll
        for (int nt = 0; nt < 8; nt++)
            #pragma unroll
            for (int e = 0; e < 4; e++) sacc[nt][e] = 0.f;

        #pragma unroll
        for (int ks = 0; ks < 4; ks++) {
            #pragma unroll
            for (int kg = 0; kg < 4; kg++) {
                uint32_t bh_[4], bl_[4];
                LDSM4(bh_, skh + (uint32_t)(kg * 16 * AST) + ks * 32);
                LDSM4(bl_, skl + (uint32_t)(kg * 16 * AST) + ks * 32);
                MMA16816(sacc[2*kg],   qfh[ks], bh_[0], bh_[1]);
                MMA16816(sacc[2*kg],   qfh[ks], bl_[0], bl_[1]);
                MMA16816(sacc[2*kg],   qfl[ks], bh_[0], bh_[1]);
                MMA16816(sacc[2*kg+1], qfh[ks], bh_[2], bh_[3]);
                MMA16816(sacc[2*kg+1], qfh[ks], bl_[2], bl_[3]);
                MMA16816(sacc[2*kg+1], qfl[ks], bh_[2], bh_[3]);
            }
        }

        // ---- causal mask ----
        if (kb * 64 + 63 > r0) {
            #pragma unroll
            for (int nt = 0; nt < 8; nt++) {
                int c = kb * 64 + nt * 8 + (lane & 3) * 2;
                if (c > r0)         sacc[nt][0] = -1e30f;
                if (c + 1 > r0)     sacc[nt][1] = -1e30f;
                if (c > r0 + 8)     sacc[nt][2] = -1e30f;
                if (c + 1 > r0 + 8) sacc[nt][3] = -1e30f;
            }
        }

        // ---- online softmax ----
        float rmax[2] = {-1e30f, -1e30f};
        #pragma unroll
        for (int nt = 0; nt < 8; nt++) {
            rmax[0] = fmaxf(rmax[0], fmaxf(sacc[nt][0], sacc[nt][1]));
            rmax[1] = fmaxf(rmax[1], fmaxf(sacc[nt][2], sacc[nt][3]));
        }
        #pragma unroll
        for (int w = 1; w <= 2; w <<= 1) {
            rmax[0] = fmaxf(rmax[0], __shfl_xor_sync(0xffffffffu, rmax[0], w));
            rmax[1] = fmaxf(rmax[1], __shfl_xor_sync(0xffffffffu, rmax[1], w));
        }
        float nm0 = fmaxf(m[0], rmax[0]);
        float nm1 = fmaxf(m[1], rmax[1]);
        float c0 = __expf(m[0] - nm0);
        float c1 = __expf(m[1] - nm1);
        m[0] = nm0; m[1] = nm1;
        #pragma unroll
        for (int nt = 0; nt < 8; nt++) {
            oacc[nt][0] *= c0; oacc[nt][1] *= c0;
            oacc[nt][2] *= c1; oacc[nt][3] *= c1;
        }
        float sum0 = 0.f, sum1 = 0.f;
        uint32_t ph[8][2];
        #pragma unroll
        for (int nt = 0; nt < 8; nt++) {
            float p0 = __expf(sacc[nt][0] - nm0);
            float p1 = __expf(sacc[nt][1] - nm0);
            float p2 = __expf(sacc[nt][2] - nm1);
            float p3 = __expf(sacc[nt][3] - nm1);
            sum0 += p0 + p1; sum1 += p2 + p3;
            ph[nt][0] = pack_half(p0, p1);
            ph[nt][1] = pack_half(p2, p3);
        }
        #pragma unroll
        for (int w = 1; w <= 2; w <<= 1) {
            sum0 += __shfl_xor_sync(0xffffffffu, sum0, w);
            sum1 += __shfl_xor_sync(0xffffffffu, sum1, w);
        }
        l[0] = l[0] * c0 + sum0;
        l[1] = l[1] * c1 + sum1;

        // ---- O += P V (single fp16) ----
        #pragma unroll
        for (int ks = 0; ks < 4; ks++) {
            uint32_t aph[4] = {ph[2*ks][0], ph[2*ks][1], ph[2*ks+1][0], ph[2*ks+1][1]};
            #pragma unroll
            for (int dg = 0; dg < 4; dg++) {
                uint32_t vb[4];
                LDSM4(vb, sv + (uint32_t)(dg * 16 * AST) + ks * 32);
                MMA16816F16(oacc[2*dg],   aph, vb[0], vb[1]);
                MMA16816F16(oacc[2*dg+1], aph, vb[2], vb[3]);
            }
        }
        __syncthreads();
    }

    // ---- write O as single fp16 (O-proj A operand) ----
    float inv0 = 1.f / l[0];
    float inv1 = 1.f / l[1];
    size_t row = (size_t)(b * NN) + r0;
    #pragma unroll
    for (int nt = 0; nt < 8; nt++) {
        int col = head * HD + nt * 8 + (lane & 3) * 2;
        *(__half2*)(g_aht + row * DIMX + col) =
            __floats2half2_rn(oacc[nt][0] * inv0, oacc[nt][1] * inv0);
        *(__half2*)(g_aht + (row + 8) * DIMX + col) =
            __floats2half2_rn(oacc[nt][2] * inv1, oacc[nt][3] * inv1);
    }
}

// ---------------- launch ----------------
extern "C" void kernel_launch(void* const* d_in, const int* in_sizes, int n_in,
                              void* d_out, int out_size)
{
    const float* x   = (const float*)d_in[0];
    const float* Wq  = (const float*)d_in[1];
    const float* Wkv = (const float*)d_in[2];
    const float* Wo  = (const float*)d_in[3];
    const float* rc  = (const float*)d_in[4];
    const float* rs  = (const float*)d_in[5];
    float* out = (float*)d_out;

    __nv_bfloat16 *xhi, *xlo, *wqh, *wql, *wkvh, *wkvl;
    __nv_bfloat16 *qbh, *qbl, *kbh, *kbl;
    __half *woth, *aht, *v, *vt;
    cudaGetSymbolAddress((void**)&xhi,  g_xhi);
    cudaGetSymbolAddress((void**)&xlo,  g_xlo);
    cudaGetSymbolAddress((void**)&wqh,  g_wqh);
    cudaGetSymbolAddress((void**)&wql,  g_wql);
    cudaGetSymbolAddress((void**)&wkvh, g_wkvh);
    cudaGetSymbolAddress((void**)&wkvl, g_wkvl);
    cudaGetSymbolAddress((void**)&woth, g_woth);
    cudaGetSymbolAddress((void**)&aht,  g_aht);
    cudaGetSymbolAddress((void**)&qbh,  g_qbh);
    cudaGetSymbolAddress((void**)&qbl,  g_qbl);
    cudaGetSymbolAddress((void**)&kbh,  g_kbh);
    cudaGetSymbolAddress((void**)&kbl,  g_kbl);
    cudaGetSymbolAddress((void**)&v,    g_v);
    cudaGetSymbolAddress((void**)&vt,   g_vt);

    cudaFuncSetAttribute(mma_gemm_t<1>, cudaFuncAttributeMaxDynamicSharedMemorySize, GEMM_SMEM);
    cudaFuncSetAttribute(mma_gemm_t<2>, cudaFuncAttributeMaxDynamicSharedMemorySize, GEMM_SMEM);
    cudaFuncSetAttribute(mma_gemm_h1,   cudaFuncAttributeMaxDynamicSharedMemorySize, H1_SMEM);
    cudaFuncSetAttribute(flash_attn_mma, cudaFuncAttributeMaxDynamicSharedMemorySize, FLASH_SMEM);

    // 1. split x
    int n4x = MM * DIMX / 4;
    split_kernel<<<(n4x + 255) / 256, 256>>>((const float4*)x, xhi, xlo, n4x);

    // 2. weights
    transpose_split<<<dim3(DIMX / 32, DIMX / 32), dim3(32, 8)>>>(Wq,  wqh,  wql,  DIMX, DIMX);
    transpose_split<<<dim3(KVW  / 32, DIMX / 32), dim3(32, 8)>>>(Wkv, wkvh, wkvl, DIMX, KVW);
    transpose_half <<<dim3(DIMX / 32, DIMX / 32), dim3(32, 8)>>>(Wo,  woth, DIMX, DIMX);

    // 3. Q projection (fused rope+scale+split)
    mma_gemm_t<1><<<dim3(DIMX / 128, MM / 128), 256, GEMM_SMEM>>>(
        xhi, xlo, wqh, wql, rc, rs, DIMX, DIMX);
    // 4. KV projection (fused K-rope+split / V fp16)
    mma_gemm_t<2><<<dim3(KVW / 128, MM / 128), 256, GEMM_SMEM>>>(
        xhi, xlo, wkvh, wkvl, rc, rs, KVW, DIMX);

    // 5. V transpose
    vtsplit_kernel<<<dim3(NN / 32, HD / 32, BB * NKV), dim3(32, 8)>>>(v, vt);

    // 6. flash attention
    flash_attn_mma<<<dim3(NN / 128, NH, BB), 256, FLASH_SMEM>>>(
        qbh, qbl, kbh, kbl, vt);

    // 7. output projection (1-term fp16)
    mma_gemm_h1<<<dim3(DIMX / 128, MM / 128), 256, H1_SMEM>>>(aht, woth, out, DIMX, DIMX);
}

// round 9
// speedup vs baseline: 5.5247x; 1.2691x over previous
#include <cuda_runtime.h>
#include <cuda_bf16.h>
#include <cuda_fp16.h>
#include <cstdint>
#include <cstddef>

#define BB   2
#define NN   2048
#define DIMX 2048
#define NH   32
#define NKV  8
#define HD   64
#define KVW  (2*NKV*HD)   // 1024
#define QKVW (DIMX + KVW) // 3072
#define MM   (BB*NN)      // 4096

// ---------------- scratch (__device__ globals; allocation-free rule) ----------------
__device__ __half g_xh  [(size_t)MM*DIMX];        // x hi fp16
__device__ __half g_xl  [(size_t)MM*DIMX];        // x lo fp16
__device__ __half g_wqkvt[(size_t)QKVW*DIMX];     // [Wq|Wkv] transposed, single fp16
__device__ __half g_woth[(size_t)DIMX*DIMX];      // Wo transposed, single fp16
__device__ __half g_aht [(size_t)MM*DIMX];        // flash out, single fp16

// attention-layout buffers
__device__ __half g_qbh [(size_t)BB*NH*NN*HD];    // [bh][n][d] Q hi fp16 (rope+scale)
__device__ __half g_qbl [(size_t)BB*NH*NN*HD];    // Q lo fp16
__device__ __half g_kb  [(size_t)BB*NKV*NN*HD];   // [bh][n][d] K single fp16 (rope)
__device__ __half g_v   [(size_t)BB*NKV*NN*HD];   // compact V fp16 [bh][n][d]
__device__ __half g_vt  [(size_t)BB*NKV*HD*NN];   // [bh][d][n] fp16 (transposed)

// ---------------- helpers (baseline PTX ISA only) ----------------
__device__ __forceinline__ uint32_t smem_u32(const void* p){
    uint32_t a;
    asm("{ .reg .u64 t; cvta.to.shared.u64 t, %1; cvt.u32.u64 %0, t; }" : "=r"(a) : "l"(p));
    return a;
}
__device__ __forceinline__ void cp16(uint32_t dst, const void* src){
    asm volatile("cp.async.cg.shared.global [%0], [%1], 16;" :: "r"(dst), "l"(src));
}

#define LDSM4(r, addr) \
    asm volatile("ldmatrix.sync.aligned.m8n8.x4.shared.b16 {%0,%1,%2,%3}, [%4];" \
        : "=r"((r)[0]), "=r"((r)[1]), "=r"((r)[2]), "=r"((r)[3]) : "r"(addr))

#define MMA16816F16(d, a, b0, b1) \
    asm volatile("mma.sync.aligned.m16n8k16.row.col.f32.f16.f16.f32 " \
        "{%0,%1,%2,%3}, {%4,%5,%6,%7}, {%8,%9}, {%0,%1,%2,%3};" \
        : "+f"((d)[0]), "+f"((d)[1]), "+f"((d)[2]), "+f"((d)[3]) \
        : "r"((a)[0]), "r"((a)[1]), "r"((a)[2]), "r"((a)[3]), "r"(b0), "r"(b1))

__device__ __forceinline__ uint32_t pack_half(float a, float b){
    __half2 p = __floats2half2_rn(a, b);
    return *(uint32_t*)&p;
}

// split-store a pair (a,b) into hi/lo fp16 buffers at idx (idx even)
__device__ __forceinline__ void store_split_pair_h(__half* hi, __half* lo,
                                                   size_t idx, float a, float b){
    __half ha = __float2half(a);
    __half hb = __float2half(b);
    *(__half2*)(hi + idx) = __halves2half2(ha, hb);
    *(__half2*)(lo + idx) =
        __floats2half2_rn(a - __half2float(ha), b - __half2float(hb));
}

// ---------------- conversion passes ----------------
__global__ void split_half_kernel(const float4* __restrict__ src,
                                  __half* __restrict__ hi, __half* __restrict__ lo, int n4)
{
    int i = blockIdx.x * blockDim.x + threadIdx.x;
    if (i >= n4) return;
    float4 v = src[i];
    float vv[4] = {v.x, v.y, v.z, v.w};
    #pragma unroll
    for (int j = 0; j < 4; j++) {
        __half h = __float2half(vv[j]);
        hi[4*i + j] = h;
        lo[4*i + j] = __float2half(vv[j] - __half2float(h));
    }
}

// W [K, Nc] fp32 -> out [Nc, K] single fp16
__global__ void transpose_half(const float* __restrict__ W, __half* __restrict__ out,
                               int K, int Nc)
{
    __shared__ float t[32][33];
    int x  = blockIdx.x * 32 + threadIdx.x;
    int y0 = blockIdx.y * 32;
    #pragma unroll
    for (int j = 0; j < 32; j += 8)
        t[threadIdx.y + j][threadIdx.x] = W[(size_t)(y0 + threadIdx.y + j) * Nc + x];
    __syncthreads();
    int ox = y0 + threadIdx.x;
    int oy = blockIdx.x * 32;
    #pragma unroll
    for (int j = 0; j < 32; j += 8)
        out[(size_t)(oy + threadIdx.y + j) * K + ox] = __float2half(t[threadIdx.x][threadIdx.y + j]);
}

// compact V fp16 [bh][n][64] -> transposed [bh][d][n] fp16
__global__ void vtsplit_kernel(const __half* __restrict__ V, __half* __restrict__ out)
{
    __shared__ float t[32][33];
    int bh = blockIdx.z;
    int n0 = blockIdx.x * 32;
    int d0 = blockIdx.y * 32;
    #pragma unroll
    for (int j = 0; j < 32; j += 8)
        t[threadIdx.y + j][threadIdx.x] =
            __half2float(V[((size_t)bh * NN + n0 + threadIdx.y + j) * HD + d0 + threadIdx.x]);
    __syncthreads();
    #pragma unroll
    for (int j = 0; j < 32; j += 8) {
        size_t o = ((size_t)bh * HD + d0 + threadIdx.y + j) * NN + n0 + threadIdx.x;
        out[o] = __float2half(t[threadIdx.x][threadIdx.y + j]);
    }
}

// ---------------- 2-term fp16 GEMM: fused QKV projection ----------------
// C = (Ah + Al)[M,K] @ B^T, B = [Wq|Wkv]^T stored [3072, K] K-major, single fp16.
// Epilogue: col<2048 -> Q rope+scale+fp16-split; col<2560 -> K rope single fp16; else V fp16.
#define TILE_B   10240u              // 128 rows * 80B
#define H2_STAGE (3u*TILE_B)         // Ah, Al, B
#define H2_SMEM  (2u*H2_STAGE)       // 61440

__global__ __launch_bounds__(256) void mma_gemm_qkv(
    const __half* __restrict__ Ah, const __half* __restrict__ Al,
    const __half* __restrict__ B,
    const float* __restrict__ rc, const float* __restrict__ rs, int K)
{
    extern __shared__ __align__(128) char smem[];
    const uint32_t dbase = smem_u32(smem);
    const int tid   = threadIdx.x;
    const int lane  = tid & 31;
    const int wid   = tid >> 5;
    const int warpM = wid & 3;
    const int warpN = wid >> 2;

    const int rowBase = blockIdx.y * 128;
    const int colBase = blockIdx.x * 128;
    const int nChunks = K >> 5;

    const __half* srcs[3] = {Ah, Al, B};

    auto load_chunk = [&](int chunk, int stage) {
        const uint32_t sbase = dbase + (uint32_t)stage * H2_STAGE;
        const int k0 = chunk << 5;
        #pragma unroll
        for (int tile = 0; tile < 3; tile++) {
            const __half* s = srcs[tile];
            const int gBase = (tile < 2) ? rowBase : colBase;
            const uint32_t tb = sbase + (uint32_t)tile * TILE_B;
            #pragma unroll
            for (int i = 0; i < 2; i++) {
                int idx = tid + (i << 8);
                int r = idx >> 2, c = idx & 3;
                cp16(tb + (uint32_t)(r * 80 + c * 16),
                     s + (size_t)(gBase + r) * K + k0 + c * 8);
            }
        }
        asm volatile("cp.async.commit_group;" ::: "memory");
    };

    const uint32_t aoff = (uint32_t)((warpM * 32 + (lane & 15)) * 80 + (lane >> 4) * 16);
    const uint32_t boff = (uint32_t)((warpN * 64 + (lane & 7) + ((lane >> 4) << 3)) * 80
                                     + ((lane >> 3) & 1) * 16);

    float acc[2][8][4];
    #pragma unroll
    for (int mt = 0; mt < 2; mt++)
        #pragma unroll
        for (int nt = 0; nt < 8; nt++)
            #pragma unroll
            for (int e = 0; e < 4; e++) acc[mt][nt][e] = 0.f;

    load_chunk(0, 0);
    int buf = 0;
    for (int chunk = 0; chunk < nChunks; chunk++) {
        if (chunk + 1 < nChunks) {
            load_chunk(chunk + 1, buf ^ 1);
            asm volatile("cp.async.wait_group 1;" ::: "memory");
        } else {
            asm volatile("cp.async.wait_group 0;" ::: "memory");
        }
        __syncthreads();

        const uint32_t sbase = dbase + (uint32_t)buf * H2_STAGE;
        const uint32_t sAh = sbase + aoff;
        const uint32_t sAl = sAh + TILE_B;
        const uint32_t sB  = sbase + 2u * TILE_B + boff;

        #pragma unroll
        for (int ks = 0; ks < 2; ks++) {
            uint32_t ah[2][4], al[2][4];
            LDSM4(ah[0], sAh + ks * 32);
            LDSM4(ah[1], sAh + 16 * 80 + ks * 32);
            LDSM4(al[0], sAl + ks * 32);
            LDSM4(al[1], sAl + 16 * 80 + ks * 32);
            #pragma unroll
            for (int ntp = 0; ntp < 4; ntp++) {
                uint32_t bb[4];
                LDSM4(bb, sB + ntp * 16 * 80 + ks * 32);
                #pragma unroll
                for (int mt = 0; mt < 2; mt++) {
                    MMA16816F16(acc[mt][2*ntp],   ah[mt], bb[0], bb[1]);
                    MMA16816F16(acc[mt][2*ntp],   al[mt], bb[0], bb[1]);
                    MMA16816F16(acc[mt][2*ntp+1], ah[mt], bb[2], bb[3]);
                    MMA16816F16(acc[mt][2*ntp+1], al[mt], bb[2], bb[3]);
                }
            }
        }
        buf ^= 1;
        __syncthreads();
    }

    // ---- fused epilogue ----
    #pragma unroll
    for (int mt = 0; mt < 2; mt++) {
        int row0 = rowBase + warpM * 32 + mt * 16 + (lane >> 2);
        #pragma unroll
        for (int nt = 0; nt < 8; nt++) {
            int col = colBase + warpN * 64 + nt * 8 + (lane & 3) * 2;

            if (col < DIMX) {
                // Q: rope + 0.125 scale + fp16 hi/lo split
                int h = col >> 6, dp = col & 63, p = dp >> 1;
                #pragma unroll
                for (int half = 0; half < 2; half++) {
                    int row = row0 + 8 * half;
                    int b = row >> 11, n = row & (NN - 1);
                    float c = rc[n * 32 + p], s = rs[n * 32 + p];
                    float e = acc[mt][nt][2*half]     * 0.125f;
                    float o = acc[mt][nt][2*half + 1] * 0.125f;
                    float yr = e * c - o * s;
                    float yi = e * s + o * c;
                    size_t idx = ((size_t)(b * NH + h) * NN + n) * HD + dp;
                    store_split_pair_h(g_qbh, g_qbl, idx, yr, yi);
                }
            } else if (col < DIMX + NKV * HD) {
                // K: rope + single fp16
                int kc = col - DIMX;
                int h = kc >> 6, dp = kc & 63, p = dp >> 1;
                #pragma unroll
                for (int half = 0; half < 2; half++) {
                    int row = row0 + 8 * half;
                    int b = row >> 11, n = row & (NN - 1);
                    float c = rc[n * 32 + p], s = rs[n * 32 + p];
                    float e = acc[mt][nt][2*half];
                    float o = acc[mt][nt][2*half + 1];
                    float yr = e * c - o * s;
                    float yi = e * s + o * c;
                    *(__half2*)(g_kb + ((size_t)(b * NKV + h) * NN + n) * HD + dp) =
                        __floats2half2_rn(yr, yi);
                }
            } else {
                // V: compact fp16
                int vc = col - DIMX - NKV * HD;
                int h = vc >> 6, d = vc & 63;
                #pragma unroll
                for (int half = 0; half < 2; half++) {
                    int row = row0 + 8 * half;
                    int b = row >> 11, n = row & (NN - 1);
                    *(__half2*)(g_v + ((size_t)(b * NKV + h) * NN + n) * HD + d) =
                        __floats2half2_rn(acc[mt][nt][2*half], acc[mt][nt][2*half + 1]);
                }
            }
        }
    }
}

// ---------------- 1-term fp16 GEMM (O projection -> d_out fp32) ----------------
#define H1_STAGE (2u*TILE_B)
#define H1_SMEM  (2u*H1_STAGE)   // 40960

__global__ __launch_bounds__(256) void mma_gemm_h1(
    const __half* __restrict__ A, const __half* __restrict__ B,
    float* __restrict__ C, int Nc, int K)
{
    extern __shared__ __align__(128) char smem[];
    const uint32_t dbase = smem_u32(smem);
    const int tid   = threadIdx.x;
    const int lane  = tid & 31;
    const int wid   = tid >> 5;
    const int warpM = wid & 3;
    const int warpN = wid >> 2;

    const int rowBase = blockIdx.y * 128;
    const int colBase = blockIdx.x * 128;
    const int nChunks = K >> 5;

    auto load_chunk = [&](int chunk, int stage) {
        const uint32_t sbase = dbase + (uint32_t)stage * H1_STAGE;
        const int k0 = chunk << 5;
        #pragma unroll
        for (int tile = 0; tile < 2; tile++) {
            const __half* s = tile ? B : A;
            const int gBase = tile ? colBase : rowBase;
            const uint32_t tb = sbase + (uint32_t)tile * TILE_B;
            #pragma unroll
            for (int i = 0; i < 2; i++) {
                int idx = tid + (i << 8);
                int r = idx >> 2, c = idx & 3;
                cp16(tb + (uint32_t)(r * 80 + c * 16),
                     s + (size_t)(gBase + r) * K + k0 + c * 8);
            }
        }
        asm volatile("cp.async.commit_group;" ::: "memory");
    };

    const uint32_t aoff = (uint32_t)((warpM * 32 + (lane & 15)) * 80 + (lane >> 4) * 16);
    const uint32_t boff = (uint32_t)((warpN * 64 + (lane & 7) + ((lane >> 4) << 3)) * 80
                                     + ((lane >> 3) & 1) * 16);

    float acc[2][8][4];
    #pragma unroll
    for (int mt = 0; mt < 2; mt++)
        #pragma unroll
        for (int nt = 0; nt < 8; nt++)
            #pragma unroll
            for (int e = 0; e < 4; e++) acc[mt][nt][e] = 0.f;

    load_chunk(0, 0);
    int buf = 0;
    for (int chunk = 0; chunk < nChunks; chunk++) {
        if (chunk + 1 < nChunks) {
            load_chunk(chunk + 1, buf ^ 1);
            asm volatile("cp.async.wait_group 1;" ::: "memory");
        } else {
            asm volatile("cp.async.wait_group 0;" ::: "memory");
        }
        __syncthreads();

        const uint32_t sbase = dbase + (uint32_t)buf * H1_STAGE;
        const uint32_t sA = sbase + aoff;
        const uint32_t sB = sbase + TILE_B + boff;

        #pragma unroll
        for (int ks = 0; ks < 2; ks++) {
            uint32_t ah[2][4];
            LDSM4(ah[0], sA + ks * 32);
            LDSM4(ah[1], sA + 16 * 80 + ks * 32);
            #pragma unroll
            for (int ntp = 0; ntp < 4; ntp++) {
                uint32_t bb[4];
                LDSM4(bb, sB + ntp * 16 * 80 + ks * 32);
                #pragma unroll
                for (int mt = 0; mt < 2; mt++) {
                    MMA16816F16(acc[mt][2*ntp],   ah[mt], bb[0], bb[1]);
                    MMA16816F16(acc[mt][2*ntp+1], ah[mt], bb[2], bb[3]);
                }
            }
        }
        buf ^= 1;
        __syncthreads();
    }

    #pragma unroll
    for (int mt = 0; mt < 2; mt++) {
        int row0 = rowBase + warpM * 32 + mt * 16 + (lane >> 2);
        #pragma unroll
        for (int nt = 0; nt < 8; nt++) {
            int col = colBase + warpN * 64 + nt * 8 + (lane & 3) * 2;
            *(float2*)(C + (size_t)row0 * Nc + col)       = make_float2(acc[mt][nt][0], acc[mt][nt][1]);
            *(float2*)(C + (size_t)(row0 + 8) * Nc + col) = make_float2(acc[mt][nt][2], acc[mt][nt][3]);
        }
    }
}

// ---------------- tensor-core flash attention ----------------
// S = (Qh+Ql)·K^T (2-term fp16, K single). P/V single fp16. Out single fp16.
#define AST 144u
#define AQ_B  (128u*AST)          // 18432 per q buffer
#define AK_B  (64u*AST)           // 9216 per tile
#define AKST  (2u*AK_B)           // 18432 per kv stage (K, V)
#define SM_QH 0u
#define SM_QL AQ_B
#define SM_KV (2u*AQ_B)
#define FLASH_SMEM (2u*AQ_B + 2u*AKST)   // 73728 B

__global__ __launch_bounds__(256) void flash_attn_mma(
    const __half* __restrict__ Qh, const __half* __restrict__ Ql,
    const __half* __restrict__ Kk, const __half* __restrict__ Vt)
{
    extern __shared__ __align__(128) char smem[];
    const uint32_t sb = smem_u32(smem);
    const int tid  = threadIdx.x;
    const int lane = tid & 31;
    const int wid  = tid >> 5;
    const int qb   = blockIdx.x;
    const int head = blockIdx.y;
    const int b    = blockIdx.z;
    const int bhq  = b * NH + head;
    const int bhk  = b * NKV + (head & (NKV - 1));

    const __half* qh = Qh + ((size_t)bhq * NN + qb * 128) * HD;
    const __half* ql = Ql + ((size_t)bhq * NN + qb * 128) * HD;
    const __half* kk = Kk + (size_t)bhk * NN * HD;
    const __half* vt = Vt + (size_t)bhk * HD * NN;

    auto load_kv = [&](int kb, int st) {
        const uint32_t base = sb + SM_KV + (uint32_t)st * AKST;
        #pragma unroll
        for (int i = 0; i < 2; i++) {
            int idx = tid + (i << 8);
            int r = idx >> 3, c = idx & 7;
            uint32_t so = (uint32_t)(r * AST + c * 16);
            size_t kg = ((size_t)(kb * 64 + r)) * HD + c * 8;
            size_t vg = ((size_t)r) * NN + kb * 64 + c * 8;
            cp16(base + so,        kk + kg);
            cp16(base + AK_B + so, vt + vg);
        }
        asm volatile("cp.async.commit_group;" ::: "memory");
    };

    // ---- load Q + first KV tile ----
    #pragma unroll
    for (int i = 0; i < 4; i++) {
        int idx = tid + (i << 8);
        int r = idx >> 3, c = idx & 7;
        cp16(sb + SM_QH + (uint32_t)(r * AST + c * 16), qh + (size_t)r * HD + c * 8);
        cp16(sb + SM_QL + (uint32_t)(r * AST + c * 16), ql + (size_t)r * HD + c * 8);
    }
    asm volatile("cp.async.commit_group;" ::: "memory");
    load_kv(0, 0);
    asm volatile("cp.async.wait_group 0;" ::: "memory");
    __syncthreads();

    const uint32_t qoff = (uint32_t)((wid * 16 + (lane & 15)) * AST + (lane >> 4) * 16);
    uint32_t qfh[4][4], qfl[4][4];
    #pragma unroll
    for (int ks = 0; ks < 4; ks++) {
        LDSM4(qfh[ks], sb + SM_QH + qoff + ks * 32);
        LDSM4(qfl[ks], sb + SM_QL + qoff + ks * 32);
    }
    __syncthreads();

    const uint32_t boff = (uint32_t)(((lane & 7) + ((lane >> 4) << 3)) * AST + ((lane >> 3) & 1) * 16);

    float oacc[8][4];
    #pragma unroll
    for (int nt = 0; nt < 8; nt++)
        #pragma unroll
        for (int e = 0; e < 4; e++) oacc[nt][e] = 0.f;
    float m[2] = {-1e30f, -1e30f};
    float l[2] = {0.f, 0.f};

    const int r0 = qb * 128 + wid * 16 + (lane >> 2);
    const int kbmax = 2 * qb + 1;

    for (int kb = 0; kb <= kbmax; kb++) {
        const int st = kb & 1;
        if (kb + 1 <= kbmax) {
            load_kv(kb + 1, st ^ 1);
            asm volatile("cp.async.wait_group 1;" ::: "memory");
        } else {
            asm volatile("cp.async.wait_group 0;" ::: "memory");
        }
        __syncthreads();

        const uint32_t sk = sb + SM_KV + (uint32_t)st * AKST + boff;
        const uint32_t sv = sk + AK_B;

        // ---- S = Q K^T (2-term fp16) ----
        float sacc[8][4];
        #pragma unroll
        for (int nt = 0; nt < 8; nt++)
            #pragma unroll
            for (int e = 0; e < 4; e++) sacc[nt][e] = 0.f;

        #pragma unroll
        for (int ks = 0; ks < 4; ks++) {
            #pragma unroll
            for (int kg = 0; kg < 4; kg++) {
                uint32_t kb_[4];
                LDSM4(kb_, sk + (uint32_t)(kg * 16 * AST) + ks * 32);
                MMA16816F16(sacc[2*kg],   qfh[ks], kb_[0], kb_[1]);
                MMA16816F16(sacc[2*kg],   qfl[ks], kb_[0], kb_[1]);
                MMA16816F16(sacc[2*kg+1], qfh[ks], kb_[2], kb_[3]);
                MMA16816F16(sacc[2*kg+1], qfl[ks], kb_[2], kb_[3]);
            }
        }

        // ---- causal mask ----
        if (kb * 64 + 63 > r0) {
            #pragma unroll
            for (int nt = 0; nt < 8; nt++) {
                int c = kb * 64 + nt * 8 + (lane & 3) * 2;
                if (c > r0)         sacc[nt][0] = -1e30f;
                if (c + 1 > r0)     sacc[nt][1] = -1e30f;
                if (c > r0 + 8)     sacc[nt][2] = -1e30f;
                if (c + 1 > r0 + 8) sacc[nt][3] = -1e30f;
            }
        }

        // ---- online softmax ----
        float rmax[2] = {-1e30f, -1e30f};
        #pragma unroll
        for (int nt = 0; nt < 8; nt++) {
            rmax[0] = fmaxf(rmax[0], fmaxf(sacc[nt][0], sacc[nt][1]));
            rmax[1] = fmaxf(rmax[1], fmaxf(sacc[nt][2], sacc[nt][3]));
        }
        #pragma unroll
        for (int w = 1; w <= 2; w <<= 1) {
            rmax[0] = fmaxf(rmax[0], __shfl_xor_sync(0xffffffffu, rmax[0], w));
            rmax[1] = fmaxf(rmax[1], __shfl_xor_sync(0xffffffffu, rmax[1], w));
        }
        float nm0 = fmaxf(m[0], rmax[0]);
        float nm1 = fmaxf(m[1], rmax[1]);
        float c0 = __expf(m[0] - nm0);
        float c1 = __expf(m[1] - nm1);
        m[0] = nm0; m[1] = nm1;
        #pragma unroll
        for (int nt = 0; nt < 8; nt++) {
            oacc[nt][0] *= c0; oacc[nt][1] *= c0;
            oacc[nt][2] *= c1; oacc[nt][3] *= c1;
        }
        float sum0 = 0.f, sum1 = 0.f;
        uint32_t ph[8][2];
        #pragma unroll
        for (int nt = 0; nt < 8; nt++) {
            float p0 = __expf(sacc[nt][0] - nm0);
            float p1 = __expf(sacc[nt][1] - nm0);
            float p2 = __expf(sacc[nt][2] - nm1);
            float p3 = __expf(sacc[nt][3] - nm1);
            sum0 += p0 + p1; sum1 += p2 + p3;
            ph[nt][0] = pack_half(p0, p1);
            ph[nt][1] = pack_half(p2, p3);
        }
        #pragma unroll
        for (int w = 1; w <= 2; w <<= 1) {
            sum0 += __shfl_xor_sync(0xffffffffu, sum0, w);
            sum1 += __shfl_xor_sync(0xffffffffu, sum1, w);
        }
        l[0] = l[0] * c0 + sum0;
        l[1] = l[1] * c1 + sum1;

        // ---- O += P V (single fp16) ----
        #pragma unroll
        for (int ks = 0; ks < 4; ks++) {
            uint32_t aph[4] = {ph[2*ks][0], ph[2*ks][1], ph[2*ks+1][0], ph[2*ks+1][1]};
            #pragma unroll
            for (int dg = 0; dg < 4; dg++) {
                uint32_t vb[4];
                LDSM4(vb, sv + (uint32_t)(dg * 16 * AST) + ks * 32);
                MMA16816F16(oacc[2*dg],   aph, vb[0], vb[1]);
                MMA16816F16(oacc[2*dg+1], aph, vb[2], vb[3]);
            }
        }
        __syncthreads();
    }

    // ---- write O as single fp16 (O-proj A operand) ----
    float inv0 = 1.f / l[0];
    float inv1 = 1.f / l[1];
    size_t row = (size_t)(b * NN) + r0;
    #pragma unroll
    for (int nt = 0; nt < 8; nt++) {
        int col = head * HD + nt * 8 + (lane & 3) * 2;
        *(__half2*)(g_aht + row * DIMX + col) =
            __floats2half2_rn(oacc[nt][0] * inv0, oacc[nt][1] * inv0);
        *(__half2*)(g_aht + (row + 8) * DIMX + col) =
            __floats2half2_rn(oacc[nt][2] * inv1, oacc[nt][3] * inv1);
    }
}

// ---------------- launch ----------------
extern "C" void kernel_launch(void* const* d_in, const int* in_sizes, int n_in,
                              void* d_out, int out_size)
{
    const float* x   = (const float*)d_in[0];
    const float* Wq  = (const float*)d_in[1];
    const float* Wkv = (const float*)d_in[2];
    const float* Wo  = (const float*)d_in[3];
    const float* rc  = (const float*)d_in[4];
    const float* rs  = (const float*)d_in[5];
    float* out = (float*)d_out;

    __half *xh, *xl, *wqkvt, *woth, *aht, *qbh, *qbl, *kb, *v, *vt;
    cudaGetSymbolAddress((void**)&xh,    g_xh);
    cudaGetSymbolAddress((void**)&xl,    g_xl);
    cudaGetSymbolAddress((void**)&wqkvt, g_wqkvt);
    cudaGetSymbolAddress((void**)&woth,  g_woth);
    cudaGetSymbolAddress((void**)&aht,   g_aht);
    cudaGetSymbolAddress((void**)&qbh,   g_qbh);
    cudaGetSymbolAddress((void**)&qbl,   g_qbl);
    cudaGetSymbolAddress((void**)&kb,    g_kb);
    cudaGetSymbolAddress((void**)&v,     g_v);
    cudaGetSymbolAddress((void**)&vt,    g_vt);

    cudaFuncSetAttribute(mma_gemm_qkv, cudaFuncAttributeMaxDynamicSharedMemorySize, H2_SMEM);
    cudaFuncSetAttribute(mma_gemm_h1,  cudaFuncAttributeMaxDynamicSharedMemorySize, H1_SMEM);
    cudaFuncSetAttribute(flash_attn_mma, cudaFuncAttributeMaxDynamicSharedMemorySize, FLASH_SMEM);

    // 1. split x into fp16 hi/lo
    int n4x = MM * DIMX / 4;
    split_half_kernel<<<(n4x + 255) / 256, 256>>>((const float4*)x, xh, xl, n4x);

    // 2. weights: [Wq|Wkv] -> g_wqkvt rows [0,2048)+[2048,3072); Wo -> g_woth
    transpose_half<<<dim3(DIMX / 32, DIMX / 32), dim3(32, 8)>>>(Wq,  wqkvt, DIMX, DIMX);
    transpose_half<<<dim3(KVW  / 32, DIMX / 32), dim3(32, 8)>>>(Wkv, wqkvt + (size_t)DIMX * DIMX, DIMX, KVW);
    transpose_half<<<dim3(DIMX / 32, DIMX / 32), dim3(32, 8)>>>(Wo,  woth, DIMX, DIMX);

    // 3. fused QKV projection (2-term fp16, fused rope/scale/split epilogues)
    mma_gemm_qkv<<<dim3(QKVW / 128, MM / 128), 256, H2_SMEM>>>(
        xh, xl, wqkvt, rc, rs, DIMX);

    // 4. V transpose
    vtsplit_kernel<<<dim3(NN / 32, HD / 32, BB * NKV), dim3(32, 8)>>>(v, vt);

    // 5. flash attention
    flash_attn_mma<<<dim3(NN / 128, NH, BB), 256, FLASH_SMEM>>>(qbh, qbl, kb, vt);

    // 6. output projection (1-term fp16)
    mma_gemm_h1<<<dim3(DIMX / 128, MM / 128), 256, H1_SMEM>>>(aht, woth, out, DIMX, DIMX);
}

// round 10
// speedup vs baseline: 7.3300x; 1.3268x over previous
#include <cuda_runtime.h>
#include <cuda_fp16.h>
#include <cstdint>
#include <cstddef>

#define BB   2
#define NN   2048
#define DIMX 2048
#define NH   32
#define NKV  8
#define HD   64
#define KVW  (2*NKV*HD)   // 1024
#define QKVW (DIMX + KVW) // 3072
#define MM   (BB*NN)      // 4096

// ---------------- scratch (__device__ globals; allocation-free rule) ----------------
__device__ __half g_xh  [(size_t)MM*DIMX];        // x single fp16
__device__ __half g_wqkvt[(size_t)QKVW*DIMX];     // [Wq|Wkv] transposed, single fp16
__device__ __half g_woth[(size_t)DIMX*DIMX];      // Wo transposed, single fp16
__device__ __half g_aht [(size_t)MM*DIMX];        // flash out, single fp16

// attention-layout buffers
__device__ __half g_qb  [(size_t)BB*NH*NN*HD];    // [bh][n][d] Q fp16 (rope+scale)
__device__ __half g_kb  [(size_t)BB*NKV*NN*HD];   // [bh][n][d] K fp16 (rope)
__device__ __half g_v   [(size_t)BB*NKV*NN*HD];   // compact V fp16 [bh][n][d]
__device__ __half g_vt  [(size_t)BB*NKV*HD*NN];   // [bh][d][n] fp16 (transposed)

// ---------------- helpers (baseline PTX ISA only) ----------------
__device__ __forceinline__ uint32_t smem_u32(const void* p){
    uint32_t a;
    asm("{ .reg .u64 t; cvta.to.shared.u64 t, %1; cvt.u32.u64 %0, t; }" : "=r"(a) : "l"(p));
    return a;
}
__device__ __forceinline__ void cp16(uint32_t dst, const void* src){
    asm volatile("cp.async.cg.shared.global [%0], [%1], 16;" :: "r"(dst), "l"(src));
}

#define LDSM4(r, addr) \
    asm volatile("ldmatrix.sync.aligned.m8n8.x4.shared.b16 {%0,%1,%2,%3}, [%4];" \
        : "=r"((r)[0]), "=r"((r)[1]), "=r"((r)[2]), "=r"((r)[3]) : "r"(addr))

#define MMA16816F16(d, a, b0, b1) \
    asm volatile("mma.sync.aligned.m16n8k16.row.col.f32.f16.f16.f32 " \
        "{%0,%1,%2,%3}, {%4,%5,%6,%7}, {%8,%9}, {%0,%1,%2,%3};" \
        : "+f"((d)[0]), "+f"((d)[1]), "+f"((d)[2]), "+f"((d)[3]) \
        : "r"((a)[0]), "r"((a)[1]), "r"((a)[2]), "r"((a)[3]), "r"(b0), "r"(b1))

__device__ __forceinline__ uint32_t pack_half(float a, float b){
    __half2 p = __floats2half2_rn(a, b);
    return *(uint32_t*)&p;
}

// ---------------- conversion passes ----------------
__global__ void cvt_half_kernel(const float4* __restrict__ src, __half* __restrict__ out, int n4)
{
    int i = blockIdx.x * blockDim.x + threadIdx.x;
    if (i >= n4) return;
    float4 v = src[i];
    __half2 a = __floats2half2_rn(v.x, v.y);
    __half2 b = __floats2half2_rn(v.z, v.w);
    *(__half2*)(out + 4*i)     = a;
    *(__half2*)(out + 4*i + 2) = b;
}

// W [K, Nc] fp32 -> out [Nc, K] single fp16
__global__ void transpose_half(const float* __restrict__ W, __half* __restrict__ out,
                               int K, int Nc)
{
    __shared__ float t[32][33];
    int x  = blockIdx.x * 32 + threadIdx.x;
    int y0 = blockIdx.y * 32;
    #pragma unroll
    for (int j = 0; j < 32; j += 8)
        t[threadIdx.y + j][threadIdx.x] = W[(size_t)(y0 + threadIdx.y + j) * Nc + x];
    __syncthreads();
    int ox = y0 + threadIdx.x;
    int oy = blockIdx.x * 32;
    #pragma unroll
    for (int j = 0; j < 32; j += 8)
        out[(size_t)(oy + threadIdx.y + j) * K + ox] = __float2half(t[threadIdx.x][threadIdx.y + j]);
}

// compact V fp16 [bh][n][64] -> transposed [bh][d][n] fp16
__global__ void vtsplit_kernel(const __half* __restrict__ V, __half* __restrict__ out)
{
    __shared__ float t[32][33];
    int bh = blockIdx.z;
    int n0 = blockIdx.x * 32;
    int d0 = blockIdx.y * 32;
    #pragma unroll
    for (int j = 0; j < 32; j += 8)
        t[threadIdx.y + j][threadIdx.x] =
            __half2float(V[((size_t)bh * NN + n0 + threadIdx.y + j) * HD + d0 + threadIdx.x]);
    __syncthreads();
    #pragma unroll
    for (int j = 0; j < 32; j += 8) {
        size_t o = ((size_t)bh * HD + d0 + threadIdx.y + j) * NN + n0 + threadIdx.x;
        out[o] = __float2half(t[threadIdx.x][threadIdx.y + j]);
    }
}

// ---------------- 1-term fp16 GEMM: fused QKV projection ----------------
// C = A[M,K] @ B^T, B = [Wq|Wkv]^T stored [3072, K] K-major, single fp16.
// Epilogue: col<2048 -> Q rope+scale fp16; col<2560 -> K rope fp16; else V fp16.
#define TILE_B   10240u              // 128 rows * 80B
#define H1_STAGE (2u*TILE_B)         // A, B
#define H1_SMEM  (2u*H1_STAGE)       // 40960

__global__ __launch_bounds__(256) void mma_gemm_qkv(
    const __half* __restrict__ A, const __half* __restrict__ B,
    const float* __restrict__ rc, const float* __restrict__ rs, int K)
{
    extern __shared__ __align__(128) char smem[];
    const uint32_t dbase = smem_u32(smem);
    const int tid   = threadIdx.x;
    const int lane  = tid & 31;
    const int wid   = tid >> 5;
    const int warpM = wid & 3;
    const int warpN = wid >> 2;

    const int rowBase = blockIdx.y * 128;
    const int colBase = blockIdx.x * 128;
    const int nChunks = K >> 5;

    auto load_chunk = [&](int chunk, int stage) {
        const uint32_t sbase = dbase + (uint32_t)stage * H1_STAGE;
        const int k0 = chunk << 5;
        #pragma unroll
        for (int tile = 0; tile < 2; tile++) {
            const __half* s = tile ? B : A;
            const int gBase = tile ? colBase : rowBase;
            const uint32_t tb = sbase + (uint32_t)tile * TILE_B;
            #pragma unroll
            for (int i = 0; i < 2; i++) {
                int idx = tid + (i << 8);
                int r = idx >> 2, c = idx & 3;
                cp16(tb + (uint32_t)(r * 80 + c * 16),
                     s + (size_t)(gBase + r) * K + k0 + c * 8);
            }
        }
        asm volatile("cp.async.commit_group;" ::: "memory");
    };

    const uint32_t aoff = (uint32_t)((warpM * 32 + (lane & 15)) * 80 + (lane >> 4) * 16);
    const uint32_t boff = (uint32_t)((warpN * 64 + (lane & 7) + ((lane >> 4) << 3)) * 80
                                     + ((lane >> 3) & 1) * 16);

    float acc[2][8][4];
    #pragma unroll
    for (int mt = 0; mt < 2; mt++)
        #pragma unroll
        for (int nt = 0; nt < 8; nt++)
            #pragma unroll
            for (int e = 0; e < 4; e++) acc[mt][nt][e] = 0.f;

    load_chunk(0, 0);
    int buf = 0;
    for (int chunk = 0; chunk < nChunks; chunk++) {
        if (chunk + 1 < nChunks) {
            load_chunk(chunk + 1, buf ^ 1);
            asm volatile("cp.async.wait_group 1;" ::: "memory");
        } else {
            asm volatile("cp.async.wait_group 0;" ::: "memory");
        }
        __syncthreads();

        const uint32_t sbase = dbase + (uint32_t)buf * H1_STAGE;
        const uint32_t sA = sbase + aoff;
        const uint32_t sB = sbase + TILE_B + boff;

        #pragma unroll
        for (int ks = 0; ks < 2; ks++) {
            uint32_t ah[2][4];
            LDSM4(ah[0], sA + ks * 32);
            LDSM4(ah[1], sA + 16 * 80 + ks * 32);
            #pragma unroll
            for (int ntp = 0; ntp < 4; ntp++) {
                uint32_t bb[4];
                LDSM4(bb, sB + ntp * 16 * 80 + ks * 32);
                #pragma unroll
                for (int mt = 0; mt < 2; mt++) {
                    MMA16816F16(acc[mt][2*ntp],   ah[mt], bb[0], bb[1]);
                    MMA16816F16(acc[mt][2*ntp+1], ah[mt], bb[2], bb[3]);
                }
            }
        }
        buf ^= 1;
        __syncthreads();
    }

    // ---- fused epilogue ----
    #pragma unroll
    for (int mt = 0; mt < 2; mt++) {
        int row0 = rowBase + warpM * 32 + mt * 16 + (lane >> 2);
        #pragma unroll
        for (int nt = 0; nt < 8; nt++) {
            int col = colBase + warpN * 64 + nt * 8 + (lane & 3) * 2;

            if (col < DIMX) {
                // Q: rope + 0.125 scale -> single fp16
                int h = col >> 6, dp = col & 63, p = dp >> 1;
                #pragma unroll
                for (int half = 0; half < 2; half++) {
                    int row = row0 + 8 * half;
                    int b = row >> 11, n = row & (NN - 1);
                    float c = rc[n * 32 + p], s = rs[n * 32 + p];
                    float e = acc[mt][nt][2*half]     * 0.125f;
                    float o = acc[mt][nt][2*half + 1] * 0.125f;
                    *(__half2*)(g_qb + ((size_t)(b * NH + h) * NN + n) * HD + dp) =
                        __floats2half2_rn(e * c - o * s, e * s + o * c);
                }
            } else if (col < DIMX + NKV * HD) {
                // K: rope -> single fp16
                int kc = col - DIMX;
                int h = kc >> 6, dp = kc & 63, p = dp >> 1;
                #pragma unroll
                for (int half = 0; half < 2; half++) {
                    int row = row0 + 8 * half;
                    int b = row >> 11, n = row & (NN - 1);
                    float c = rc[n * 32 + p], s = rs[n * 32 + p];
                    float e = acc[mt][nt][2*half];
                    float o = acc[mt][nt][2*half + 1];
                    *(__half2*)(g_kb + ((size_t)(b * NKV + h) * NN + n) * HD + dp) =
                        __floats2half2_rn(e * c - o * s, e * s + o * c);
                }
            } else {
                // V: compact fp16
                int vc = col - DIMX - NKV * HD;
                int h = vc >> 6, d = vc & 63;
                #pragma unroll
                for (int half = 0; half < 2; half++) {
                    int row = row0 + 8 * half;
                    int b = row >> 11, n = row & (NN - 1);
                    *(__half2*)(g_v + ((size_t)(b * NKV + h) * NN + n) * HD + d) =
                        __floats2half2_rn(acc[mt][nt][2*half], acc[mt][nt][2*half + 1]);
                }
            }
        }
    }
}

// ---------------- 1-term fp16 GEMM (O projection -> d_out fp32) ----------------
__global__ __launch_bounds__(256) void mma_gemm_h1(
    const __half* __restrict__ A, const __half* __restrict__ B,
    float* __restrict__ C, int Nc, int K)
{
    extern __shared__ __align__(128) char smem[];
    const uint32_t dbase = smem_u32(smem);
    const int tid   = threadIdx.x;
    const int lane  = tid & 31;
    const int wid   = tid >> 5;
    const int warpM = wid & 3;
    const int warpN = wid >> 2;

    const int rowBase = blockIdx.y * 128;
    const int colBase = blockIdx.x * 128;
    const int nChunks = K >> 5;

    auto load_chunk = [&](int chunk, int stage) {
        const uint32_t sbase = dbase + (uint32_t)stage * H1_STAGE;
        const int k0 = chunk << 5;
        #pragma unroll
        for (int tile = 0; tile < 2; tile++) {
            const __half* s = tile ? B : A;
            const int gBase = tile ? colBase : rowBase;
            const uint32_t tb = sbase + (uint32_t)tile * TILE_B;
            #pragma unroll
            for (int i = 0; i < 2; i++) {
                int idx = tid + (i << 8);
                int r = idx >> 2, c = idx & 3;
                cp16(tb + (uint32_t)(r * 80 + c * 16),
                     s + (size_t)(gBase + r) * K + k0 + c * 8);
            }
        }
        asm volatile("cp.async.commit_group;" ::: "memory");
    };

    const uint32_t aoff = (uint32_t)((warpM * 32 + (lane & 15)) * 80 + (lane >> 4) * 16);
    const uint32_t boff = (uint32_t)((warpN * 64 + (lane & 7) + ((lane >> 4) << 3)) * 80
                                     + ((lane >> 3) & 1) * 16);

    float acc[2][8][4];
    #pragma unroll
    for (int mt = 0; mt < 2; mt++)
        #pragma unroll
        for (int nt = 0; nt < 8; nt++)
            #pragma unroll
            for (int e = 0; e < 4; e++) acc[mt][nt][e] = 0.f;

    load_chunk(0, 0);
    int buf = 0;
    for (int chunk = 0; chunk < nChunks; chunk++) {
        if (chunk + 1 < nChunks) {
            load_chunk(chunk + 1, buf ^ 1);
            asm volatile("cp.async.wait_group 1;" ::: "memory");
        } else {
            asm volatile("cp.async.wait_group 0;" ::: "memory");
        }
        __syncthreads();

        const uint32_t sbase = dbase + (uint32_t)buf * H1_STAGE;
        const uint32_t sA = sbase + aoff;
        const uint32_t sB = sbase + TILE_B + boff;

        #pragma unroll
        for (int ks = 0; ks < 2; ks++) {
            uint32_t ah[2][4];
            LDSM4(ah[0], sA + ks * 32);
            LDSM4(ah[1], sA + 16 * 80 + ks * 32);
            #pragma unroll
            for (int ntp = 0; ntp < 4; ntp++) {
                uint32_t bb[4];
                LDSM4(bb, sB + ntp * 16 * 80 + ks * 32);
                #pragma unroll
                for (int mt = 0; mt < 2; mt++) {
                    MMA16816F16(acc[mt][2*ntp],   ah[mt], bb[0], bb[1]);
                    MMA16816F16(acc[mt][2*ntp+1], ah[mt], bb[2], bb[3]);
                }
            }
        }
        buf ^= 1;
        __syncthreads();
    }

    #pragma unroll
    for (int mt = 0; mt < 2; mt++) {
        int row0 = rowBase + warpM * 32 + mt * 16 + (lane >> 2);
        #pragma unroll
        for (int nt = 0; nt < 8; nt++) {
            int col = colBase + warpN * 64 + nt * 8 + (lane & 3) * 2;
            *(float2*)(C + (size_t)row0 * Nc + col)       = make_float2(acc[mt][nt][0], acc[mt][nt][1]);
            *(float2*)(C + (size_t)(row0 + 8) * Nc + col) = make_float2(acc[mt][nt][2], acc[mt][nt][3]);
        }
    }
}

// ---------------- tensor-core flash attention (all 1-term fp16) ----------------
#define AST 144u
#define AQ_B  (128u*AST)          // 18432 q buffer
#define AK_B  (64u*AST)           // 9216 per tile
#define AKST  (2u*AK_B)           // 18432 per kv stage (K, V)
#define SM_Q  0u
#define SM_KV AQ_B
#define FLASH_SMEM (AQ_B + 2u*AKST)   // 55296 B

__global__ __launch_bounds__(256) void flash_attn_mma(
    const __half* __restrict__ Q,
    const __half* __restrict__ Kk, const __half* __restrict__ Vt)
{
    extern __shared__ __align__(128) char smem[];
    const uint32_t sb = smem_u32(smem);
    const int tid  = threadIdx.x;
    const int lane = tid & 31;
    const int wid  = tid >> 5;
    const int qb   = blockIdx.x;
    const int head = blockIdx.y;
    const int b    = blockIdx.z;
    const int bhq  = b * NH + head;
    const int bhk  = b * NKV + (head & (NKV - 1));

    const __half* q  = Q  + ((size_t)bhq * NN + qb * 128) * HD;
    const __half* kk = Kk + (size_t)bhk * NN * HD;
    const __half* vt = Vt + (size_t)bhk * HD * NN;

    auto load_kv = [&](int kb, int st) {
        const uint32_t base = sb + SM_KV + (uint32_t)st * AKST;
        #pragma unroll
        for (int i = 0; i < 2; i++) {
            int idx = tid + (i << 8);
            int r = idx >> 3, c = idx & 7;
            uint32_t so = (uint32_t)(r * AST + c * 16);
            size_t kg = ((size_t)(kb * 64 + r)) * HD + c * 8;
            size_t vg = ((size_t)r) * NN + kb * 64 + c * 8;
            cp16(base + so,        kk + kg);
            cp16(base + AK_B + so, vt + vg);
        }
        asm volatile("cp.async.commit_group;" ::: "memory");
    };

    // ---- load Q + first KV tile ----
    #pragma unroll
    for (int i = 0; i < 4; i++) {
        int idx = tid + (i << 8);
        int r = idx >> 3, c = idx & 7;
        cp16(sb + SM_Q + (uint32_t)(r * AST + c * 16), q + (size_t)r * HD + c * 8);
    }
    asm volatile("cp.async.commit_group;" ::: "memory");
    load_kv(0, 0);
    asm volatile("cp.async.wait_group 0;" ::: "memory");
    __syncthreads();

    const uint32_t qoff = (uint32_t)((wid * 16 + (lane & 15)) * AST + (lane >> 4) * 16);
    uint32_t qf[4][4];
    #pragma unroll
    for (int ks = 0; ks < 4; ks++)
        LDSM4(qf[ks], sb + SM_Q + qoff + ks * 32);
    __syncthreads();

    const uint32_t boff = (uint32_t)(((lane & 7) + ((lane >> 4) << 3)) * AST + ((lane >> 3) & 1) * 16);

    float oacc[8][4];
    #pragma unroll
    for (int nt = 0; nt < 8; nt++)
        #pragma unroll
        for (int e = 0; e < 4; e++) oacc[nt][e] = 0.f;
    float m[2] = {-1e30f, -1e30f};
    float l[2] = {0.f, 0.f};

    const int r0 = qb * 128 + wid * 16 + (lane >> 2);
    const int kbmax = 2 * qb + 1;

    for (int kb = 0; kb <= kbmax; kb++) {
        const int st = kb & 1;
        if (kb + 1 <= kbmax) {
            load_kv(kb + 1, st ^ 1);
            asm volatile("cp.async.wait_group 1;" ::: "memory");
        } else {
            asm volatile("cp.async.wait_group 0;" ::: "memory");
        }
        __syncthreads();

        const uint32_t sk = sb + SM_KV + (uint32_t)st * AKST + boff;
        const uint32_t sv = sk + AK_B;

        // ---- S = Q K^T (1-term fp16) ----
        float sacc[8][4];
        #pragma unroll
        for (int nt = 0; nt < 8; nt++)
            #pragma unroll
            for (int e = 0; e < 4; e++) sacc[nt][e] = 0.f;

        #pragma unroll
        for (int ks = 0; ks < 4; ks++) {
            #pragma unroll
            for (int kg = 0; kg < 4; kg++) {
                uint32_t kb_[4];
                LDSM4(kb_, sk + (uint32_t)(kg * 16 * AST) + ks * 32);
                MMA16816F16(sacc[2*kg],   qf[ks], kb_[0], kb_[1]);
                MMA16816F16(sacc[2*kg+1], qf[ks], kb_[2], kb_[3]);
            }
        }

        // ---- causal mask ----
        if (kb * 64 + 63 > r0) {
            #pragma unroll
            for (int nt = 0; nt < 8; nt++) {
                int c = kb * 64 + nt * 8 + (lane & 3) * 2;
                if (c > r0)         sacc[nt][0] = -1e30f;
                if (c + 1 > r0)     sacc[nt][1] = -1e30f;
                if (c > r0 + 8)     sacc[nt][2] = -1e30f;
                if (c + 1 > r0 + 8) sacc[nt][3] = -1e30f;
            }
        }

        // ---- online softmax ----
        float rmax[2] = {-1e30f, -1e30f};
        #pragma unroll
        for (int nt = 0; nt < 8; nt++) {
            rmax[0] = fmaxf(rmax[0], fmaxf(sacc[nt][0], sacc[nt][1]));
            rmax[1] = fmaxf(rmax[1], fmaxf(sacc[nt][2], sacc[nt][3]));
        }
        #pragma unroll
        for (int w = 1; w <= 2; w <<= 1) {
            rmax[0] = fmaxf(rmax[0], __shfl_xor_sync(0xffffffffu, rmax[0], w));
            rmax[1] = fmaxf(rmax[1], __shfl_xor_sync(0xffffffffu, rmax[1], w));
        }
        float nm0 = fmaxf(m[0], rmax[0]);
        float nm1 = fmaxf(m[1], rmax[1]);
        float c0 = __expf(m[0] - nm0);
        float c1 = __expf(m[1] - nm1);
        m[0] = nm0; m[1] = nm1;
        #pragma unroll
        for (int nt = 0; nt < 8; nt++) {
            oacc[nt][0] *= c0; oacc[nt][1] *= c0;
            oacc[nt][2] *= c1; oacc[nt][3] *= c1;
        }
        float sum0 = 0.f, sum1 = 0.f;
        uint32_t ph[8][2];
        #pragma unroll
        for (int nt = 0; nt < 8; nt++) {
            float p0 = __expf(sacc[nt][0] - nm0);
            float p1 = __expf(sacc[nt][1] - nm0);
            float p2 = __expf(sacc[nt][2] - nm1);
            float p3 = __expf(sacc[nt][3] - nm1);
            sum0 += p0 + p1; sum1 += p2 + p3;
            ph[nt][0] = pack_half(p0, p1);
            ph[nt][1] = pack_half(p2, p3);
        }
        #pragma unroll
        for (int w = 1; w <= 2; w <<= 1) {
            sum0 += __shfl_xor_sync(0xffffffffu, sum0, w);
            sum1 += __shfl_xor_sync(0xffffffffu, sum1, w);
        }
        l[0] = l[0] * c0 + sum0;
        l[1] = l[1] * c1 + sum1;

        // ---- O += P V (single fp16) ----
        #pragma unroll
        for (int ks = 0; ks < 4; ks++) {
            uint32_t aph[4] = {ph[2*ks][0], ph[2*ks][1], ph[2*ks+1][0], ph[2*ks+1][1]};
            #pragma unroll
            for (int dg = 0; dg < 4; dg++) {
                uint32_t vb[4];
                LDSM4(vb, sv + (uint32_t)(dg * 16 * AST) + ks * 32);
                MMA16816F16(oacc[2*dg],   aph, vb[0], vb[1]);
                MMA16816F16(oacc[2*dg+1], aph, vb[2], vb[3]);
            }
        }
        __syncthreads();
    }

    // ---- write O as single fp16 (O-proj A operand) ----
    float inv0 = 1.f / l[0];
    float inv1 = 1.f / l[1];
    size_t row = (size_t)(b * NN) + r0;
    #pragma unroll
    for (int nt = 0; nt < 8; nt++) {
        int col = head * HD + nt * 8 + (lane & 3) * 2;
        *(__half2*)(g_aht + row * DIMX + col) =
            __floats2half2_rn(oacc[nt][0] * inv0, oacc[nt][1] * inv0);
        *(__half2*)(g_aht + (row + 8) * DIMX + col) =
            __floats2half2_rn(oacc[nt][2] * inv1, oacc[nt][3] * inv1);
    }
}

// ---------------- launch ----------------
extern "C" void kernel_launch(void* const* d_in, const int* in_sizes, int n_in,
                              void* d_out, int out_size)
{
    const float* x   = (const float*)d_in[0];
    const float* Wq  = (const float*)d_in[1];
    const float* Wkv = (const float*)d_in[2];
    const float* Wo  = (const float*)d_in[3];
    const float* rc  = (const float*)d_in[4];
    const float* rs  = (const float*)d_in[5];
    float* out = (float*)d_out;

    __half *xh, *wqkvt, *woth, *aht, *qb, *kb, *v, *vt;
    cudaGetSymbolAddress((void**)&xh,    g_xh);
    cudaGetSymbolAddress((void**)&wqkvt, g_wqkvt);
    cudaGetSymbolAddress((void**)&woth,  g_woth);
    cudaGetSymbolAddress((void**)&aht,   g_aht);
    cudaGetSymbolAddress((void**)&qb,    g_qb);
    cudaGetSymbolAddress((void**)&kb,    g_kb);
    cudaGetSymbolAddress((void**)&v,     g_v);
    cudaGetSymbolAddress((void**)&vt,    g_vt);

    cudaFuncSetAttribute(mma_gemm_qkv, cudaFuncAttributeMaxDynamicSharedMemorySize, H1_SMEM);
    cudaFuncSetAttribute(mma_gemm_h1,  cudaFuncAttributeMaxDynamicSharedMemorySize, H1_SMEM);
    cudaFuncSetAttribute(flash_attn_mma, cudaFuncAttributeMaxDynamicSharedMemorySize, FLASH_SMEM);

    // 1. x -> single fp16
    int n4x = MM * DIMX / 4;
    cvt_half_kernel<<<(n4x + 255) / 256, 256>>>((const float4*)x, xh, n4x);

    // 2. weights: [Wq|Wkv] -> g_wqkvt; Wo -> g_woth
    transpose_half<<<dim3(DIMX / 32, DIMX / 32), dim3(32, 8)>>>(Wq,  wqkvt, DIMX, DIMX);
    transpose_half<<<dim3(KVW  / 32, DIMX / 32), dim3(32, 8)>>>(Wkv, wqkvt + (size_t)DIMX * DIMX, DIMX, KVW);
    transpose_half<<<dim3(DIMX / 32, DIMX / 32), dim3(32, 8)>>>(Wo,  woth, DIMX, DIMX);

    // 3. fused QKV projection (1-term fp16, fused rope/scale epilogues)
    mma_gemm_qkv<<<dim3(QKVW / 128, MM / 128), 256, H1_SMEM>>>(xh, wqkvt, rc, rs, DIMX);

    // 4. V transpose
    vtsplit_kernel<<<dim3(NN / 32, HD / 32, BB * NKV), dim3(32, 8)>>>(v, vt);

    // 5. flash attention (all 1-term fp16)
    flash_attn_mma<<<dim3(NN / 128, NH, BB), 256, FLASH_SMEM>>>(qb, kb, vt);

    // 6. output projection (1-term fp16)
    mma_gemm_h1<<<dim3(DIMX / 128, MM / 128), 256, H1_SMEM>>>(aht, woth, out, DIMX, DIMX);
}

// round 11
// speedup vs baseline: 8.2994x; 1.1323x over previous
#include <cuda_runtime.h>
#include <cuda_fp16.h>
#include <cstdint>
#include <cstddef>

#define BB   2
#define NN   2048
#define DIMX 2048
#define NH   32
#define NKV  8
#define HD   64
#define KVW  (2*NKV*HD)   // 1024
#define QKVW (DIMX + KVW) // 3072
#define MM   (BB*NN)      // 4096

// ---------------- scratch (__device__ globals; allocation-free rule) ----------------
__device__ __half g_xh  [(size_t)MM*DIMX];        // x single fp16
__device__ __half g_wqkvt[(size_t)QKVW*DIMX];     // [Wq|Wkv] transposed, single fp16
__device__ __half g_woth[(size_t)DIMX*DIMX];      // Wo transposed, single fp16
__device__ __half g_aht [(size_t)MM*DIMX];        // flash out, single fp16

// attention-layout buffers
__device__ __half g_qb  [(size_t)BB*NH*NN*HD];    // [bh][n][d] Q fp16 (rope+scale)
__device__ __half g_kb  [(size_t)BB*NKV*NN*HD];   // [bh][n][d] K fp16 (rope)
__device__ __half g_v   [(size_t)BB*NKV*NN*HD];   // compact V fp16 [bh][n][d]
__device__ __half g_vt  [(size_t)BB*NKV*HD*NN];   // [bh][d][n] fp16 (transposed)

// ---------------- helpers (baseline PTX ISA only) ----------------
__device__ __forceinline__ uint32_t smem_u32(const void* p){
    uint32_t a;
    asm("{ .reg .u64 t; cvta.to.shared.u64 t, %1; cvt.u32.u64 %0, t; }" : "=r"(a) : "l"(p));
    return a;
}
__device__ __forceinline__ void cp16(uint32_t dst, const void* src){
    asm volatile("cp.async.cg.shared.global [%0], [%1], 16;" :: "r"(dst), "l"(src));
}

#define LDSM4(r, addr) \
    asm volatile("ldmatrix.sync.aligned.m8n8.x4.shared.b16 {%0,%1,%2,%3}, [%4];" \
        : "=r"((r)[0]), "=r"((r)[1]), "=r"((r)[2]), "=r"((r)[3]) : "r"(addr))

#define MMA16816F16(d, a, b0, b1) \
    asm volatile("mma.sync.aligned.m16n8k16.row.col.f32.f16.f16.f32 " \
        "{%0,%1,%2,%3}, {%4,%5,%6,%7}, {%8,%9}, {%0,%1,%2,%3};" \
        : "+f"((d)[0]), "+f"((d)[1]), "+f"((d)[2]), "+f"((d)[3]) \
        : "r"((a)[0]), "r"((a)[1]), "r"((a)[2]), "r"((a)[3]), "r"(b0), "r"(b1))

__device__ __forceinline__ uint32_t pack_half(float a, float b){
    __half2 p = __floats2half2_rn(a, b);
    return *(uint32_t*)&p;
}

// ---------------- conversion passes ----------------
__global__ void cvt_half_kernel(const float4* __restrict__ src, __half* __restrict__ out, int n4)
{
    int i = blockIdx.x * blockDim.x + threadIdx.x;
    if (i >= n4) return;
    float4 v = src[i];
    *(__half2*)(out + 4*i)     = __floats2half2_rn(v.x, v.y);
    *(__half2*)(out + 4*i + 2) = __floats2half2_rn(v.z, v.w);
}

// W [K, Nc] fp32 -> out [Nc, K] single fp16
__global__ void transpose_half(const float* __restrict__ W, __half* __restrict__ out,
                               int K, int Nc)
{
    __shared__ float t[32][33];
    int x  = blockIdx.x * 32 + threadIdx.x;
    int y0 = blockIdx.y * 32;
    #pragma unroll
    for (int j = 0; j < 32; j += 8)
        t[threadIdx.y + j][threadIdx.x] = W[(size_t)(y0 + threadIdx.y + j) * Nc + x];
    __syncthreads();
    int ox = y0 + threadIdx.x;
    int oy = blockIdx.x * 32;
    #pragma unroll
    for (int j = 0; j < 32; j += 8)
        out[(size_t)(oy + threadIdx.y + j) * K + ox] = __float2half(t[threadIdx.x][threadIdx.y + j]);
}

// compact V fp16 [bh][n][64] -> transposed [bh][d][n] fp16
__global__ void vtsplit_kernel(const __half* __restrict__ V, __half* __restrict__ out)
{
    __shared__ float t[32][33];
    int bh = blockIdx.z;
    int n0 = blockIdx.x * 32;
    int d0 = blockIdx.y * 32;
    #pragma unroll
    for (int j = 0; j < 32; j += 8)
        t[threadIdx.y + j][threadIdx.x] =
            __half2float(V[((size_t)bh * NN + n0 + threadIdx.y + j) * HD + d0 + threadIdx.x]);
    __syncthreads();
    #pragma unroll
    for (int j = 0; j < 32; j += 8) {
        size_t o = ((size_t)bh * HD + d0 + threadIdx.y + j) * NN + n0 + threadIdx.x;
        out[o] = __float2half(t[threadIdx.x][threadIdx.y + j]);
    }
}

// ---------------- 1-term fp16 GEMM, BK=64, templated epilogue ----------------
// EPI 0: plain fp32 C (O projection). EPI 1: QKV fused rope/scale epilogue.
// Tile 128x128, BK=64 (128B rows, 144B stride: phase (9r+c)%8 conflict-free).
#define TB64  18432u              // 128 rows * 144B
#define ST64  (2u*TB64)           // A + B per stage = 36864
#define SM64  (2u*ST64)           // double-buffered  = 73728

template<int EPI>
__global__ __launch_bounds__(256) void mma_gemm64(
    const __half* __restrict__ A, const __half* __restrict__ B,
    float* __restrict__ C,
    const float* __restrict__ rc, const float* __restrict__ rs,
    int Nc, int K)
{
    extern __shared__ __align__(128) char smem[];
    const uint32_t dbase = smem_u32(smem);
    const int tid   = threadIdx.x;
    const int lane  = tid & 31;
    const int wid   = tid >> 5;
    const int warpM = wid & 3;
    const int warpN = wid >> 2;

    const int rowBase = blockIdx.y * 128;
    const int colBase = blockIdx.x * 128;
    const int nChunks = K >> 6;    // BK = 64

    auto load_chunk = [&](int chunk, int stage) {
        const uint32_t sbase = dbase + (uint32_t)stage * ST64;
        const int k0 = chunk << 6;
        #pragma unroll
        for (int tile = 0; tile < 2; tile++) {
            const __half* s = tile ? B : A;
            const int gBase = tile ? colBase : rowBase;
            const uint32_t tb = sbase + (uint32_t)tile * TB64;
            #pragma unroll
            for (int i = 0; i < 4; i++) {
                int idx = tid + (i << 8);          // 0..1023
                int r = idx >> 3, c = idx & 7;     // row, 16B chunk (8 per 128B row)
                cp16(tb + (uint32_t)(r * 144 + c * 16),
                     s + (size_t)(gBase + r) * K + k0 + c * 8);
            }
        }
        asm volatile("cp.async.commit_group;" ::: "memory");
    };

    const uint32_t aoff = (uint32_t)((warpM * 32 + (lane & 15)) * 144 + (lane >> 4) * 16);
    const uint32_t boff = (uint32_t)((warpN * 64 + (lane & 7) + ((lane >> 4) << 3)) * 144
                                     + ((lane >> 3) & 1) * 16);

    float acc[2][8][4];
    #pragma unroll
    for (int mt = 0; mt < 2; mt++)
        #pragma unroll
        for (int nt = 0; nt < 8; nt++)
            #pragma unroll
            for (int e = 0; e < 4; e++) acc[mt][nt][e] = 0.f;

    load_chunk(0, 0);
    int buf = 0;
    for (int chunk = 0; chunk < nChunks; chunk++) {
        if (chunk + 1 < nChunks) {
            load_chunk(chunk + 1, buf ^ 1);
            asm volatile("cp.async.wait_group 1;" ::: "memory");
        } else {
            asm volatile("cp.async.wait_group 0;" ::: "memory");
        }
        __syncthreads();

        const uint32_t sbase = dbase + (uint32_t)buf * ST64;
        const uint32_t sA = sbase + aoff;
        const uint32_t sB = sbase + TB64 + boff;

        #pragma unroll
        for (int ks = 0; ks < 4; ks++) {           // 4 x 16-K steps = 64 K
            uint32_t ah[2][4];
            LDSM4(ah[0], sA + ks * 32);
            LDSM4(ah[1], sA + 16 * 144 + ks * 32);
            #pragma unroll
            for (int ntp = 0; ntp < 4; ntp++) {
                uint32_t bb[4];
                LDSM4(bb, sB + ntp * 16 * 144 + ks * 32);
                #pragma unroll
                for (int mt = 0; mt < 2; mt++) {
                    MMA16816F16(acc[mt][2*ntp],   ah[mt], bb[0], bb[1]);
                    MMA16816F16(acc[mt][2*ntp+1], ah[mt], bb[2], bb[3]);
                }
            }
        }
        buf ^= 1;
        __syncthreads();
    }

    // ---- epilogues ----
    #pragma unroll
    for (int mt = 0; mt < 2; mt++) {
        int row0 = rowBase + warpM * 32 + mt * 16 + (lane >> 2);
        #pragma unroll
        for (int nt = 0; nt < 8; nt++) {
            int col = colBase + warpN * 64 + nt * 8 + (lane & 3) * 2;

            if (EPI == 0) {
                *(float2*)(C + (size_t)row0 * Nc + col)       = make_float2(acc[mt][nt][0], acc[mt][nt][1]);
                *(float2*)(C + (size_t)(row0 + 8) * Nc + col) = make_float2(acc[mt][nt][2], acc[mt][nt][3]);
            } else {
                if (col < DIMX) {
                    // Q: rope + 0.125 scale -> single fp16
                    int h = col >> 6, dp = col & 63, p = dp >> 1;
                    #pragma unroll
                    for (int half = 0; half < 2; half++) {
                        int row = row0 + 8 * half;
                        int b = row >> 11, n = row & (NN - 1);
                        float c = rc[n * 32 + p], s = rs[n * 32 + p];
                        float e = acc[mt][nt][2*half]     * 0.125f;
                        float o = acc[mt][nt][2*half + 1] * 0.125f;
                        *(__half2*)(g_qb + ((size_t)(b * NH + h) * NN + n) * HD + dp) =
                            __floats2half2_rn(e * c - o * s, e * s + o * c);
                    }
                } else if (col < DIMX + NKV * HD) {
                    // K: rope -> single fp16
                    int kc = col - DIMX;
                    int h = kc >> 6, dp = kc & 63, p = dp >> 1;
                    #pragma unroll
                    for (int half = 0; half < 2; half++) {
                        int row = row0 + 8 * half;
                        int b = row >> 11, n = row & (NN - 1);
                        float c = rc[n * 32 + p], s = rs[n * 32 + p];
                        float e = acc[mt][nt][2*half];
                        float o = acc[mt][nt][2*half + 1];
                        *(__half2*)(g_kb + ((size_t)(b * NKV + h) * NN + n) * HD + dp) =
                            __floats2half2_rn(e * c - o * s, e * s + o * c);
                    }
                } else {
                    // V: compact fp16
                    int vc = col - DIMX - NKV * HD;
                    int h = vc >> 6, d = vc & 63;
                    #pragma unroll
                    for (int half = 0; half < 2; half++) {
                        int row = row0 + 8 * half;
                        int b = row >> 11, n = row & (NN - 1);
                        *(__half2*)(g_v + ((size_t)(b * NKV + h) * NN + n) * HD + d) =
                            __floats2half2_rn(acc[mt][nt][2*half], acc[mt][nt][2*half + 1]);
                    }
                }
            }
        }
    }
}

// ---------------- tensor-core flash attention (all 1-term fp16) ----------------
#define AST 144u
#define AQ_B  (128u*AST)          // 18432 q buffer
#define AK_B  (64u*AST)           // 9216 per tile
#define AKST  (2u*AK_B)           // 18432 per kv stage (K, V)
#define SM_Q  0u
#define SM_KV AQ_B
#define FLASH_SMEM (AQ_B + 2u*AKST)   // 55296 B

__global__ __launch_bounds__(256) void flash_attn_mma(
    const __half* __restrict__ Q,
    const __half* __restrict__ Kk, const __half* __restrict__ Vt)
{
    extern __shared__ __align__(128) char smem[];
    const uint32_t sb = smem_u32(smem);
    const int tid  = threadIdx.x;
    const int lane = tid & 31;
    const int wid  = tid >> 5;
    const int qb   = (int)gridDim.x - 1 - (int)blockIdx.x;   // heaviest tiles first
    const int head = blockIdx.y;
    const int b    = blockIdx.z;
    const int bhq  = b * NH + head;
    const int bhk  = b * NKV + (head & (NKV - 1));

    const __half* q  = Q  + ((size_t)bhq * NN + qb * 128) * HD;
    const __half* kk = Kk + (size_t)bhk * NN * HD;
    const __half* vt = Vt + (size_t)bhk * HD * NN;

    auto load_kv = [&](int kb, int st) {
        const uint32_t base = sb + SM_KV + (uint32_t)st * AKST;
        #pragma unroll
        for (int i = 0; i < 2; i++) {
            int idx = tid + (i << 8);
            int r = idx >> 3, c = idx & 7;
            uint32_t so = (uint32_t)(r * AST + c * 16);
            size_t kg = ((size_t)(kb * 64 + r)) * HD + c * 8;
            size_t vg = ((size_t)r) * NN + kb * 64 + c * 8;
            cp16(base + so,        kk + kg);
            cp16(base + AK_B + so, vt + vg);
        }
        asm volatile("cp.async.commit_group;" ::: "memory");
    };

    // ---- load Q + first KV tile ----
    #pragma unroll
    for (int i = 0; i < 4; i++) {
        int idx = tid + (i << 8);
        int r = idx >> 3, c = idx & 7;
        cp16(sb + SM_Q + (uint32_t)(r * AST + c * 16), q + (size_t)r * HD + c * 8);
    }
    asm volatile("cp.async.commit_group;" ::: "memory");
    load_kv(0, 0);
    asm volatile("cp.async.wait_group 0;" ::: "memory");
    __syncthreads();

    const uint32_t qoff = (uint32_t)((wid * 16 + (lane & 15)) * AST + (lane >> 4) * 16);
    uint32_t qf[4][4];
    #pragma unroll
    for (int ks = 0; ks < 4; ks++)
        LDSM4(qf[ks], sb + SM_Q + qoff + ks * 32);
    __syncthreads();

    const uint32_t boff = (uint32_t)(((lane & 7) + ((lane >> 4) << 3)) * AST + ((lane >> 3) & 1) * 16);

    float oacc[8][4];
    #pragma unroll
    for (int nt = 0; nt < 8; nt++)
        #pragma unroll
        for (int e = 0; e < 4; e++) oacc[nt][e] = 0.f;
    float m[2] = {-1e30f, -1e30f};
    float l[2] = {0.f, 0.f};

    const int r0 = qb * 128 + wid * 16 + (lane >> 2);
    const int kbmax = 2 * qb + 1;

    for (int kb = 0; kb <= kbmax; kb++) {
        const int st = kb & 1;
        if (kb + 1 <= kbmax) {
            load_kv(kb + 1, st ^ 1);
            asm volatile("cp.async.wait_group 1;" ::: "memory");
        } else {
            asm volatile("cp.async.wait_group 0;" ::: "memory");
        }
        __syncthreads();

        const uint32_t sk = sb + SM_KV + (uint32_t)st * AKST + boff;
        const uint32_t sv = sk + AK_B;

        // ---- S = Q K^T (1-term fp16) ----
        float sacc[8][4];
        #pragma unroll
        for (int nt = 0; nt < 8; nt++)
            #pragma unroll
            for (int e = 0; e < 4; e++) sacc[nt][e] = 0.f;

        #pragma unroll
        for (int ks = 0; ks < 4; ks++) {
            #pragma unroll
            for (int kg = 0; kg < 4; kg++) {
                uint32_t kb_[4];
                LDSM4(kb_, sk + (uint32_t)(kg * 16 * AST) + ks * 32);
                MMA16816F16(sacc[2*kg],   qf[ks], kb_[0], kb_[1]);
                MMA16816F16(sacc[2*kg+1], qf[ks], kb_[2], kb_[3]);
            }
        }

        // ---- causal mask ----
        if (kb * 64 + 63 > r0) {
            #pragma unroll
            for (int nt = 0; nt < 8; nt++) {
                int c = kb * 64 + nt * 8 + (lane & 3) * 2;
                if (c > r0)         sacc[nt][0] = -1e30f;
                if (c + 1 > r0)     sacc[nt][1] = -1e30f;
                if (c > r0 + 8)     sacc[nt][2] = -1e30f;
                if (c + 1 > r0 + 8) sacc[nt][3] = -1e30f;
            }
        }

        // ---- online softmax ----
        float rmax[2] = {-1e30f, -1e30f};
        #pragma unroll
        for (int nt = 0; nt < 8; nt++) {
            rmax[0] = fmaxf(rmax[0], fmaxf(sacc[nt][0], sacc[nt][1]));
            rmax[1] = fmaxf(rmax[1], fmaxf(sacc[nt][2], sacc[nt][3]));
        }
        #pragma unroll
        for (int w = 1; w <= 2; w <<= 1) {
            rmax[0] = fmaxf(rmax[0], __shfl_xor_sync(0xffffffffu, rmax[0], w));
            rmax[1] = fmaxf(rmax[1], __shfl_xor_sync(0xffffffffu, rmax[1], w));
        }
        float nm0 = fmaxf(m[0], rmax[0]);
        float nm1 = fmaxf(m[1], rmax[1]);
        float c0 = __expf(m[0] - nm0);
        float c1 = __expf(m[1] - nm1);
        m[0] = nm0; m[1] = nm1;
        #pragma unroll
        for (int nt = 0; nt < 8; nt++) {
            oacc[nt][0] *= c0; oacc[nt][1] *= c0;
            oacc[nt][2] *= c1; oacc[nt][3] *= c1;
        }
        float sum0 = 0.f, sum1 = 0.f;
        uint32_t ph[8][2];
        #pragma unroll
        for (int nt = 0; nt < 8; nt++) {
            float p0 = __expf(sacc[nt][0] - nm0);
            float p1 = __expf(sacc[nt][1] - nm0);
            float p2 = __expf(sacc[nt][2] - nm1);
            float p3 = __expf(sacc[nt][3] - nm1);
            sum0 += p0 + p1; sum1 += p2 + p3;
            ph[nt][0] = pack_half(p0, p1);
            ph[nt][1] = pack_half(p2, p3);
        }
        #pragma unroll
        for (int w = 1; w <= 2; w <<= 1) {
            sum0 += __shfl_xor_sync(0xffffffffu, sum0, w);
            sum1 += __shfl_xor_sync(0xffffffffu, sum1, w);
        }
        l[0] = l[0] * c0 + sum0;
        l[1] = l[1] * c1 + sum1;

        // ---- O += P V (single fp16) ----
        #pragma unroll
        for (int ks = 0; ks < 4; ks++) {
            uint32_t aph[4] = {ph[2*ks][0], ph[2*ks][1], ph[2*ks+1][0], ph[2*ks+1][1]};
            #pragma unroll
            for (int dg = 0; dg < 4; dg++) {
                uint32_t vb[4];
                LDSM4(vb, sv + (uint32_t)(dg * 16 * AST) + ks * 32);
                MMA16816F16(oacc[2*dg],   aph, vb[0], vb[1]);
                MMA16816F16(oacc[2*dg+1], aph, vb[2], vb[3]);
            }
        }
        __syncthreads();
    }

    // ---- write O as single fp16 (O-proj A operand) ----
    float inv0 = 1.f / l[0];
    float inv1 = 1.f / l[1];
    size_t row = (size_t)(b * NN) + r0;
    #pragma unroll
    for (int nt = 0; nt < 8; nt++) {
        int col = head * HD + nt * 8 + (lane & 3) * 2;
        *(__half2*)(g_aht + row * DIMX + col) =
            __floats2half2_rn(oacc[nt][0] * inv0, oacc[nt][1] * inv0);
        *(__half2*)(g_aht + (row + 8) * DIMX + col) =
            __floats2half2_rn(oacc[nt][2] * inv1, oacc[nt][3] * inv1);
    }
}

// ---------------- launch ----------------
extern "C" void kernel_launch(void* const* d_in, const int* in_sizes, int n_in,
                              void* d_out, int out_size)
{
    const float* x   = (const float*)d_in[0];
    const float* Wq  = (const float*)d_in[1];
    const float* Wkv = (const float*)d_in[2];
    const float* Wo  = (const float*)d_in[3];
    const float* rc  = (const float*)d_in[4];
    const float* rs  = (const float*)d_in[5];
    float* out = (float*)d_out;

    __half *xh, *wqkvt, *woth, *aht, *qb, *kb, *v, *vt;
    cudaGetSymbolAddress((void**)&xh,    g_xh);
    cudaGetSymbolAddress((void**)&wqkvt, g_wqkvt);
    cudaGetSymbolAddress((void**)&woth,  g_woth);
    cudaGetSymbolAddress((void**)&aht,   g_aht);
    cudaGetSymbolAddress((void**)&qb,    g_qb);
    cudaGetSymbolAddress((void**)&kb,    g_kb);
    cudaGetSymbolAddress((void**)&v,     g_v);
    cudaGetSymbolAddress((void**)&vt,    g_vt);

    cudaFuncSetAttribute(mma_gemm64<0>, cudaFuncAttributeMaxDynamicSharedMemorySize, SM64);
    cudaFuncSetAttribute(mma_gemm64<1>, cudaFuncAttributeMaxDynamicSharedMemorySize, SM64);
    cudaFuncSetAttribute(flash_attn_mma, cudaFuncAttributeMaxDynamicSharedMemorySize, FLASH_SMEM);

    // 1. x -> single fp16
    int n4x = MM * DIMX / 4;
    cvt_half_kernel<<<(n4x + 255) / 256, 256>>>((const float4*)x, xh, n4x);

    // 2. weights: [Wq|Wkv] -> g_wqkvt; Wo -> g_woth
    transpose_half<<<dim3(DIMX / 32, DIMX / 32), dim3(32, 8)>>>(Wq,  wqkvt, DIMX, DIMX);
    transpose_half<<<dim3(KVW  / 32, DIMX / 32), dim3(32, 8)>>>(Wkv, wqkvt + (size_t)DIMX * DIMX, DIMX, KVW);
    transpose_half<<<dim3(DIMX / 32, DIMX / 32), dim3(32, 8)>>>(Wo,  woth, DIMX, DIMX);

    // 3. fused QKV projection (1-term fp16, BK=64, fused rope/scale epilogues)
    mma_gemm64<1><<<dim3(QKVW / 128, MM / 128), 256, SM64>>>(
        xh, wqkvt, nullptr, rc, rs, QKVW, DIMX);

    // 4. V transpose
    vtsplit_kernel<<<dim3(NN / 32, HD / 32, BB * NKV), dim3(32, 8)>>>(v, vt);

    // 5. flash attention
    flash_attn_mma<<<dim3(NN / 128, NH, BB), 256, FLASH_SMEM>>>(qb, kb, vt);

    // 6. output projection (1-term fp16, BK=64)
    mma_gemm64<0><<<dim3(DIMX / 128, MM / 128), 256, SM64>>>(
        aht, woth, out, nullptr, nullptr, DIMX, DIMX);
}

// round 12
// speedup vs baseline: 8.4334x; 1.0161x over previous
#include <cuda_runtime.h>
#include <cuda_fp16.h>
#include <cstdint>
#include <cstddef>

#define BB   2
#define NN   2048
#define DIMX 2048
#define NH   32
#define NKV  8
#define HD   64
#define KVW  (2*NKV*HD)   // 1024
#define QKVW (DIMX + KVW) // 3072
#define MM   (BB*NN)      // 4096

// ---------------- scratch (__device__ globals; allocation-free rule) ----------------
__device__ __half g_xh  [(size_t)MM*DIMX];        // x single fp16
__device__ __half g_wqkvt[(size_t)QKVW*DIMX];     // [Wq|Wkv] transposed, single fp16
__device__ __half g_woth[(size_t)DIMX*DIMX];      // Wo transposed, single fp16
__device__ __half g_aht [(size_t)MM*DIMX];        // flash out, single fp16

// attention-layout buffers
__device__ __half g_qb  [(size_t)BB*NH*NN*HD];    // [bh][n][d] Q fp16 (rope+scale)
__device__ __half g_kb  [(size_t)BB*NKV*NN*HD];   // [bh][n][d] K fp16 (rope)
__device__ __half g_v   [(size_t)BB*NKV*NN*HD];   // compact V fp16 [bh][n][d]
__device__ __half g_vt  [(size_t)BB*NKV*HD*NN];   // [bh][d][n] fp16 (transposed)

// ---------------- helpers (baseline PTX ISA only) ----------------
__device__ __forceinline__ uint32_t smem_u32(const void* p){
    uint32_t a;
    asm("{ .reg .u64 t; cvta.to.shared.u64 t, %1; cvt.u32.u64 %0, t; }" : "=r"(a) : "l"(p));
    return a;
}
__device__ __forceinline__ void cp16(uint32_t dst, const void* src){
    asm volatile("cp.async.cg.shared.global [%0], [%1], 16;" :: "r"(dst), "l"(src));
}

#define LDSM4(r, addr) \
    asm volatile("ldmatrix.sync.aligned.m8n8.x4.shared.b16 {%0,%1,%2,%3}, [%4];" \
        : "=r"((r)[0]), "=r"((r)[1]), "=r"((r)[2]), "=r"((r)[3]) : "r"(addr))

#define MMA16816F16(d, a, b0, b1) \
    asm volatile("mma.sync.aligned.m16n8k16.row.col.f32.f16.f16.f32 " \
        "{%0,%1,%2,%3}, {%4,%5,%6,%7}, {%8,%9}, {%0,%1,%2,%3};" \
        : "+f"((d)[0]), "+f"((d)[1]), "+f"((d)[2]), "+f"((d)[3]) \
        : "r"((a)[0]), "r"((a)[1]), "r"((a)[2]), "r"((a)[3]), "r"(b0), "r"(b1))

__device__ __forceinline__ uint32_t pack_half(float a, float b){
    __half2 p = __floats2half2_rn(a, b);
    return *(uint32_t*)&p;
}

// ---------------- conversion passes ----------------
__global__ void cvt_half_kernel(const float4* __restrict__ src, __half* __restrict__ out, int n4)
{
    int i = blockIdx.x * blockDim.x + threadIdx.x;
    if (i >= n4) return;
    float4 v = src[i];
    *(__half2*)(out + 4*i)     = __floats2half2_rn(v.x, v.y);
    *(__half2*)(out + 4*i + 2) = __floats2half2_rn(v.z, v.w);
}

// W [K, Nc] fp32 -> out [Nc, K] single fp16
__global__ void transpose_half(const float* __restrict__ W, __half* __restrict__ out,
                               int K, int Nc)
{
    __shared__ float t[32][33];
    int x  = blockIdx.x * 32 + threadIdx.x;
    int y0 = blockIdx.y * 32;
    #pragma unroll
    for (int j = 0; j < 32; j += 8)
        t[threadIdx.y + j][threadIdx.x] = W[(size_t)(y0 + threadIdx.y + j) * Nc + x];
    __syncthreads();
    int ox = y0 + threadIdx.x;
    int oy = blockIdx.x * 32;
    #pragma unroll
    for (int j = 0; j < 32; j += 8)
        out[(size_t)(oy + threadIdx.y + j) * K + ox] = __float2half(t[threadIdx.x][threadIdx.y + j]);
}

// compact V fp16 [bh][n][64] -> transposed [bh][d][n] fp16
__global__ void vtsplit_kernel(const __half* __restrict__ V, __half* __restrict__ out)
{
    __shared__ float t[32][33];
    int bh = blockIdx.z;
    int n0 = blockIdx.x * 32;
    int d0 = blockIdx.y * 32;
    #pragma unroll
    for (int j = 0; j < 32; j += 8)
        t[threadIdx.y + j][threadIdx.x] =
            __half2float(V[((size_t)bh * NN + n0 + threadIdx.y + j) * HD + d0 + threadIdx.x]);
    __syncthreads();
    #pragma unroll
    for (int j = 0; j < 32; j += 8) {
        size_t o = ((size_t)bh * HD + d0 + threadIdx.y + j) * NN + n0 + threadIdx.x;
        out[o] = __float2half(t[threadIdx.x][threadIdx.y + j]);
    }
}

// ---------------- 1-term fp16 GEMM, BK=64, one-sync mainloop ----------------
// EPI 0: plain fp32 C (O projection). EPI 1: QKV fused rope/scale epilogue.
// Tile 128x128, BK=64 (128B rows, 144B stride: phase (9r+c)%8 conflict-free).
#define TB64  18432u              // 128 rows * 144B
#define ST64  (2u*TB64)           // A + B per stage = 36864
#define SM64  (2u*ST64)           // double-buffered  = 73728

template<int EPI>
__global__ __launch_bounds__(256) void mma_gemm64(
    const __half* __restrict__ A, const __half* __restrict__ B,
    float* __restrict__ C,
    const float* __restrict__ rc, const float* __restrict__ rs,
    int Nc, int K)
{
    extern __shared__ __align__(128) char smem[];
    const uint32_t dbase = smem_u32(smem);
    const int tid   = threadIdx.x;
    const int lane  = tid & 31;
    const int wid   = tid >> 5;
    const int warpM = wid & 3;
    const int warpN = wid >> 2;

    const int rowBase = blockIdx.y * 128;
    const int colBase = blockIdx.x * 128;
    const int nChunks = K >> 6;    // BK = 64

    auto load_chunk = [&](int chunk, int stage) {
        const uint32_t sbase = dbase + (uint32_t)stage * ST64;
        const int k0 = chunk << 6;
        #pragma unroll
        for (int tile = 0; tile < 2; tile++) {
            const __half* s = tile ? B : A;
            const int gBase = tile ? colBase : rowBase;
            const uint32_t tb = sbase + (uint32_t)tile * TB64;
            #pragma unroll
            for (int i = 0; i < 4; i++) {
                int idx = tid + (i << 8);          // 0..1023
                int r = idx >> 3, c = idx & 7;     // row, 16B chunk (8 per 128B row)
                cp16(tb + (uint32_t)(r * 144 + c * 16),
                     s + (size_t)(gBase + r) * K + k0 + c * 8);
            }
        }
        asm volatile("cp.async.commit_group;" ::: "memory");
    };

    const uint32_t aoff = (uint32_t)((warpM * 32 + (lane & 15)) * 144 + (lane >> 4) * 16);
    const uint32_t boff = (uint32_t)((warpN * 64 + (lane & 7) + ((lane >> 4) << 3)) * 144
                                     + ((lane >> 3) & 1) * 16);

    float acc[2][8][4];
    #pragma unroll
    for (int mt = 0; mt < 2; mt++)
        #pragma unroll
        for (int nt = 0; nt < 8; nt++)
            #pragma unroll
            for (int e = 0; e < 4; e++) acc[mt][nt][e] = 0.f;

    load_chunk(0, 0);
    int buf = 0;
    for (int chunk = 0; chunk < nChunks; chunk++) {
        // ONE barrier per iteration: publishes stage `buf` (just waited) and
        // proves all warps finished compute on stage buf^1 (last iteration),
        // licensing the load below to overwrite it.
        asm volatile("cp.async.wait_group 0;" ::: "memory");
        __syncthreads();
        if (chunk + 1 < nChunks)
            load_chunk(chunk + 1, buf ^ 1);   // overlaps compute below

        const uint32_t sbase = dbase + (uint32_t)buf * ST64;
        const uint32_t sA = sbase + aoff;
        const uint32_t sB = sbase + TB64 + boff;

        #pragma unroll
        for (int ks = 0; ks < 4; ks++) {           // 4 x 16-K steps = 64 K
            uint32_t ah[2][4];
            LDSM4(ah[0], sA + ks * 32);
            LDSM4(ah[1], sA + 16 * 144 + ks * 32);
            #pragma unroll
            for (int ntp = 0; ntp < 4; ntp++) {
                uint32_t bb[4];
                LDSM4(bb, sB + ntp * 16 * 144 + ks * 32);
                #pragma unroll
                for (int mt = 0; mt < 2; mt++) {
                    MMA16816F16(acc[mt][2*ntp],   ah[mt], bb[0], bb[1]);
                    MMA16816F16(acc[mt][2*ntp+1], ah[mt], bb[2], bb[3]);
                }
            }
        }
        buf ^= 1;
    }

    // ---- epilogues ----
    #pragma unroll
    for (int mt = 0; mt < 2; mt++) {
        int row0 = rowBase + warpM * 32 + mt * 16 + (lane >> 2);
        #pragma unroll
        for (int nt = 0; nt < 8; nt++) {
            int col = colBase + warpN * 64 + nt * 8 + (lane & 3) * 2;

            if (EPI == 0) {
                *(float2*)(C + (size_t)row0 * Nc + col)       = make_float2(acc[mt][nt][0], acc[mt][nt][1]);
                *(float2*)(C + (size_t)(row0 + 8) * Nc + col) = make_float2(acc[mt][nt][2], acc[mt][nt][3]);
            } else {
                if (col < DIMX) {
                    // Q: rope + 0.125 scale -> single fp16
                    int h = col >> 6, dp = col & 63, p = dp >> 1;
                    #pragma unroll
                    for (int half = 0; half < 2; half++) {
                        int row = row0 + 8 * half;
                        int b = row >> 11, n = row & (NN - 1);
                        float c = rc[n * 32 + p], s = rs[n * 32 + p];
                        float e = acc[mt][nt][2*half]     * 0.125f;
                        float o = acc[mt][nt][2*half + 1] * 0.125f;
                        *(__half2*)(g_qb + ((size_t)(b * NH + h) * NN + n) * HD + dp) =
                            __floats2half2_rn(e * c - o * s, e * s + o * c);
                    }
                } else if (col < DIMX + NKV * HD) {
                    // K: rope -> single fp16
                    int kc = col - DIMX;
                    int h = kc >> 6, dp = kc & 63, p = dp >> 1;
                    #pragma unroll
                    for (int half = 0; half < 2; half++) {
                        int row = row0 + 8 * half;
                        int b = row >> 11, n = row & (NN - 1);
                        float c = rc[n * 32 + p], s = rs[n * 32 + p];
                        float e = acc[mt][nt][2*half];
                        float o = acc[mt][nt][2*half + 1];
                        *(__half2*)(g_kb + ((size_t)(b * NKV + h) * NN + n) * HD + dp) =
                            __floats2half2_rn(e * c - o * s, e * s + o * c);
                    }
                } else {
                    // V: compact fp16
                    int vc = col - DIMX - NKV * HD;
                    int h = vc >> 6, d = vc & 63;
                    #pragma unroll
                    for (int half = 0; half < 2; half++) {
                        int row = row0 + 8 * half;
                        int b = row >> 11, n = row & (NN - 1);
                        *(__half2*)(g_v + ((size_t)(b * NKV + h) * NN + n) * HD + d) =
                            __floats2half2_rn(acc[mt][nt][2*half], acc[mt][nt][2*half + 1]);
                    }
                }
            }
        }
    }
}

// ---------------- tensor-core flash attention (one-sync mainloop) ----------------
#define AST 144u
#define AQ_B  (128u*AST)          // 18432 q buffer
#define AK_B  (64u*AST)           // 9216 per tile
#define AKST  (2u*AK_B)           // 18432 per kv stage (K, V)
#define SM_Q  0u
#define SM_KV AQ_B
#define FLASH_SMEM (AQ_B + 2u*AKST)   // 55296 B

__global__ __launch_bounds__(256) void flash_attn_mma(
    const __half* __restrict__ Q,
    const __half* __restrict__ Kk, const __half* __restrict__ Vt)
{
    extern __shared__ __align__(128) char smem[];
    const uint32_t sb = smem_u32(smem);
    const int tid  = threadIdx.x;
    const int lane = tid & 31;
    const int wid  = tid >> 5;
    const int qb   = (int)gridDim.x - 1 - (int)blockIdx.x;   // heaviest tiles first
    const int head = blockIdx.y;
    const int b    = blockIdx.z;
    const int bhq  = b * NH + head;
    const int bhk  = b * NKV + (head & (NKV - 1));

    const __half* q  = Q  + ((size_t)bhq * NN + qb * 128) * HD;
    const __half* kk = Kk + (size_t)bhk * NN * HD;
    const __half* vt = Vt + (size_t)bhk * HD * NN;

    auto load_kv = [&](int kb, int st) {
        const uint32_t base = sb + SM_KV + (uint32_t)st * AKST;
        #pragma unroll
        for (int i = 0; i < 2; i++) {
            int idx = tid + (i << 8);
            int r = idx >> 3, c = idx & 7;
            uint32_t so = (uint32_t)(r * AST + c * 16);
            size_t kg = ((size_t)(kb * 64 + r)) * HD + c * 8;
            size_t vg = ((size_t)r) * NN + kb * 64 + c * 8;
            cp16(base + so,        kk + kg);
            cp16(base + AK_B + so, vt + vg);
        }
        asm volatile("cp.async.commit_group;" ::: "memory");
    };

    // ---- load Q + first KV tile ----
    #pragma unroll
    for (int i = 0; i < 4; i++) {
        int idx = tid + (i << 8);
        int r = idx >> 3, c = idx & 7;
        cp16(sb + SM_Q + (uint32_t)(r * AST + c * 16), q + (size_t)r * HD + c * 8);
    }
    asm volatile("cp.async.commit_group;" ::: "memory");
    load_kv(0, 0);
    asm volatile("cp.async.wait_group 0;" ::: "memory");
    __syncthreads();

    const uint32_t qoff = (uint32_t)((wid * 16 + (lane & 15)) * AST + (lane >> 4) * 16);
    uint32_t qf[4][4];
    #pragma unroll
    for (int ks = 0; ks < 4; ks++)
        LDSM4(qf[ks], sb + SM_Q + qoff + ks * 32);
    // no sync needed: Q smem region is never overwritten

    const uint32_t boff = (uint32_t)(((lane & 7) + ((lane >> 4) << 3)) * AST + ((lane >> 3) & 1) * 16);

    float oacc[8][4];
    #pragma unroll
    for (int nt = 0; nt < 8; nt++)
        #pragma unroll
        for (int e = 0; e < 4; e++) oacc[nt][e] = 0.f;
    float m[2] = {-1e30f, -1e30f};
    float l[2] = {0.f, 0.f};

    const int r0 = qb * 128 + wid * 16 + (lane >> 2);
    const int kbmax = 2 * qb + 1;

    for (int kb = 0; kb <= kbmax; kb++) {
        const int st = kb & 1;
        if (kb > 0) {
            // publish kv(kb) + prove compute(kb-1) drained (licenses overwrite below)
            asm volatile("cp.async.wait_group 0;" ::: "memory");
            __syncthreads();
        }
        if (kb + 1 <= kbmax)
            load_kv(kb + 1, st ^ 1);    // overlaps compute below

        const uint32_t sk = sb + SM_KV + (uint32_t)st * AKST + boff;
        const uint32_t sv = sk + AK_B;

        // ---- S = Q K^T (1-term fp16) ----
        float sacc[8][4];
        #pragma unroll
        for (int nt = 0; nt < 8; nt++)
            #pragma unroll
            for (int e = 0; e < 4; e++) sacc[nt][e] = 0.f;

        #pragma unroll
        for (int ks = 0; ks < 4; ks++) {
            #pragma unroll
            for (int kg = 0; kg < 4; kg++) {
                uint32_t kb_[4];
                LDSM4(kb_, sk + (uint32_t)(kg * 16 * AST) + ks * 32);
                MMA16816F16(sacc[2*kg],   qf[ks], kb_[0], kb_[1]);
                MMA16816F16(sacc[2*kg+1], qf[ks], kb_[2], kb_[3]);
            }
        }

        // ---- causal mask ----
        if (kb * 64 + 63 > r0) {
            #pragma unroll
            for (int nt = 0; nt < 8; nt++) {
                int c = kb * 64 + nt * 8 + (lane & 3) * 2;
                if (c > r0)         sacc[nt][0] = -1e30f;
                if (c + 1 > r0)     sacc[nt][1] = -1e30f;
                if (c > r0 + 8)     sacc[nt][2] = -1e30f;
                if (c + 1 > r0 + 8) sacc[nt][3] = -1e30f;
            }
        }

        // ---- online softmax ----
        float rmax[2] = {-1e30f, -1e30f};
        #pragma unroll
        for (int nt = 0; nt < 8; nt++) {
            rmax[0] = fmaxf(rmax[0], fmaxf(sacc[nt][0], sacc[nt][1]));
            rmax[1] = fmaxf(rmax[1], fmaxf(sacc[nt][2], sacc[nt][3]));
        }
        #pragma unroll
        for (int w = 1; w <= 2; w <<= 1) {
            rmax[0] = fmaxf(rmax[0], __shfl_xor_sync(0xffffffffu, rmax[0], w));
            rmax[1] = fmaxf(rmax[1], __shfl_xor_sync(0xffffffffu, rmax[1], w));
        }
        float nm0 = fmaxf(m[0], rmax[0]);
        float nm1 = fmaxf(m[1], rmax[1]);
        float c0 = __expf(m[0] - nm0);
        float c1 = __expf(m[1] - nm1);
        m[0] = nm0; m[1] = nm1;
        #pragma unroll
        for (int nt = 0; nt < 8; nt++) {
            oacc[nt][0] *= c0; oacc[nt][1] *= c0;
            oacc[nt][2] *= c1; oacc[nt][3] *= c1;
        }
        float sum0 = 0.f, sum1 = 0.f;
        uint32_t ph[8][2];
        #pragma unroll
        for (int nt = 0; nt < 8; nt++) {
            float p0 = __expf(sacc[nt][0] - nm0);
            float p1 = __expf(sacc[nt][1] - nm0);
            float p2 = __expf(sacc[nt][2] - nm1);
            float p3 = __expf(sacc[nt][3] - nm1);
            sum0 += p0 + p1; sum1 += p2 + p3;
            ph[nt][0] = pack_half(p0, p1);
            ph[nt][1] = pack_half(p2, p3);
        }
        #pragma unroll
        for (int w = 1; w <= 2; w <<= 1) {
            sum0 += __shfl_xor_sync(0xffffffffu, sum0, w);
            sum1 += __shfl_xor_sync(0xffffffffu, sum1, w);
        }
        l[0] = l[0] * c0 + sum0;
        l[1] = l[1] * c1 + sum1;

        // ---- O += P V (single fp16) ----
        #pragma unroll
        for (int ks = 0; ks < 4; ks++) {
            uint32_t aph[4] = {ph[2*ks][0], ph[2*ks][1], ph[2*ks+1][0], ph[2*ks+1][1]};
            #pragma unroll
            for (int dg = 0; dg < 4; dg++) {
                uint32_t vb[4];
                LDSM4(vb, sv + (uint32_t)(dg * 16 * AST) + ks * 32);
                MMA16816F16(oacc[2*dg],   aph, vb[0], vb[1]);
                MMA16816F16(oacc[2*dg+1], aph, vb[2], vb[3]);
            }
        }
    }

    // ---- write O as single fp16 (O-proj A operand) ----
    float inv0 = 1.f / l[0];
    float inv1 = 1.f / l[1];
    size_t row = (size_t)(b * NN) + r0;
    #pragma unroll
    for (int nt = 0; nt < 8; nt++) {
        int col = head * HD + nt * 8 + (lane & 3) * 2;
        *(__half2*)(g_aht + row * DIMX + col) =
            __floats2half2_rn(oacc[nt][0] * inv0, oacc[nt][1] * inv0);
        *(__half2*)(g_aht + (row + 8) * DIMX + col) =
            __floats2half2_rn(oacc[nt][2] * inv1, oacc[nt][3] * inv1);
    }
}

// ---------------- launch ----------------
extern "C" void kernel_launch(void* const* d_in, const int* in_sizes, int n_in,
                              void* d_out, int out_size)
{
    const float* x   = (const float*)d_in[0];
    const float* Wq  = (const float*)d_in[1];
    const float* Wkv = (const float*)d_in[2];
    const float* Wo  = (const float*)d_in[3];
    const float* rc  = (const float*)d_in[4];
    const float* rs  = (const float*)d_in[5];
    float* out = (float*)d_out;

    __half *xh, *wqkvt, *woth, *aht, *qb, *kb, *v, *vt;
    cudaGetSymbolAddress((void**)&xh,    g_xh);
    cudaGetSymbolAddress((void**)&wqkvt, g_wqkvt);
    cudaGetSymbolAddress((void**)&woth,  g_woth);
    cudaGetSymbolAddress((void**)&aht,   g_aht);
    cudaGetSymbolAddress((void**)&qb,    g_qb);
    cudaGetSymbolAddress((void**)&kb,    g_kb);
    cudaGetSymbolAddress((void**)&v,     g_v);
    cudaGetSymbolAddress((void**)&vt,    g_vt);

    cudaFuncSetAttribute(mma_gemm64<0>, cudaFuncAttributeMaxDynamicSharedMemorySize, SM64);
    cudaFuncSetAttribute(mma_gemm64<1>, cudaFuncAttributeMaxDynamicSharedMemorySize, SM64);
    cudaFuncSetAttribute(flash_attn_mma, cudaFuncAttributeMaxDynamicSharedMemorySize, FLASH_SMEM);

    // 1. x -> single fp16
    int n4x = MM * DIMX / 4;
    cvt_half_kernel<<<(n4x + 255) / 256, 256>>>((const float4*)x, xh, n4x);

    // 2. weights: [Wq|Wkv] -> g_wqkvt; Wo -> g_woth
    transpose_half<<<dim3(DIMX / 32, DIMX / 32), dim3(32, 8)>>>(Wq,  wqkvt, DIMX, DIMX);
    transpose_half<<<dim3(KVW  / 32, DIMX / 32), dim3(32, 8)>>>(Wkv, wqkvt + (size_t)DIMX * DIMX, DIMX, KVW);
    transpose_half<<<dim3(DIMX / 32, DIMX / 32), dim3(32, 8)>>>(Wo,  woth, DIMX, DIMX);

    // 3. fused QKV projection (1-term fp16, BK=64, fused rope/scale epilogues)
    mma_gemm64<1><<<dim3(QKVW / 128, MM / 128), 256, SM64>>>(
        xh, wqkvt, nullptr, rc, rs, QKVW, DIMX);

    // 4. V transpose
    vtsplit_kernel<<<dim3(NN / 32, HD / 32, BB * NKV), dim3(32, 8)>>>(v, vt);

    // 5. flash attention
    flash_attn_mma<<<dim3(NN / 128, NH, BB), 256, FLASH_SMEM>>>(qb, kb, vt);

    // 6. output projection (1-term fp16, BK=64)
    mma_gemm64<0><<<dim3(DIMX / 128, MM / 128), 256, SM64>>>(
        aht, woth, out, nullptr, nullptr, DIMX, DIMX);
}

// round 15
// speedup vs baseline: 8.5380x; 1.0124x over previous
#include <cuda_runtime.h>
#include <cuda_fp16.h>
#include <cstdint>
#include <cstddef>

#define BB   2
#define NN   2048
#define DIMX 2048
#define NH   32
#define NKV  8
#define HD   64
#define KVW  (2*NKV*HD)   // 1024
#define QKVW (DIMX + KVW) // 3072
#define MM   (BB*NN)      // 4096

// ---------------- scratch (__device__ globals; allocation-free rule) ----------------
__device__ __half g_xh  [(size_t)MM*DIMX];        // x single fp16
__device__ __half g_wqkvt[(size_t)QKVW*DIMX];     // [Wq|Wkv] transposed, single fp16
__device__ __half g_woth[(size_t)DIMX*DIMX];      // Wo transposed, single fp16
__device__ __half g_aht [(size_t)MM*DIMX];        // flash out, single fp16

// attention-layout buffers
__device__ __half g_qb  [(size_t)BB*NH*NN*HD];    // [bh][n][d] Q fp16 (rope+scale)
__device__ __half g_kb  [(size_t)BB*NKV*NN*HD];   // [bh][n][d] K fp16 (rope)
__device__ __half g_v   [(size_t)BB*NKV*NN*HD];   // compact V fp16 [bh][n][d]

// ---------------- helpers (baseline PTX ISA only) ----------------
__device__ __forceinline__ uint32_t smem_u32(const void* p){
    uint32_t a;
    asm("{ .reg .u64 t; cvta.to.shared.u64 t, %1; cvt.u32.u64 %0, t; }" : "=r"(a) : "l"(p));
    return a;
}
__device__ __forceinline__ void cp16(uint32_t dst, const void* src){
    asm volatile("cp.async.cg.shared.global [%0], [%1], 16;" :: "r"(dst), "l"(src));
}

#define LDSM4(r, addr) \
    asm volatile("ldmatrix.sync.aligned.m8n8.x4.shared.b16 {%0,%1,%2,%3}, [%4];" \
        : "=r"((r)[0]), "=r"((r)[1]), "=r"((r)[2]), "=r"((r)[3]) : "r"(addr))

#define LDSM4T(r, addr) \
    asm volatile("ldmatrix.sync.aligned.m8n8.x4.trans.shared.b16 {%0,%1,%2,%3}, [%4];" \
        : "=r"((r)[0]), "=r"((r)[1]), "=r"((r)[2]), "=r"((r)[3]) : "r"(addr))

#define MMA16816F16(d, a, b0, b1) \
    asm volatile("mma.sync.aligned.m16n8k16.row.col.f32.f16.f16.f32 " \
        "{%0,%1,%2,%3}, {%4,%5,%6,%7}, {%8,%9}, {%0,%1,%2,%3};" \
        : "+f"((d)[0]), "+f"((d)[1]), "+f"((d)[2]), "+f"((d)[3]) \
        : "r"((a)[0]), "r"((a)[1]), "r"((a)[2]), "r"((a)[3]), "r"(b0), "r"(b1))

__device__ __forceinline__ uint32_t pack_half(float a, float b){
    __half2 p = __floats2half2_rn(a, b);
    return *(uint32_t*)&p;
}

// ---------------- conversion passes ----------------
__global__ void cvt_half_kernel(const float4* __restrict__ src, __half* __restrict__ out, int n4)
{
    int i = blockIdx.x * blockDim.x + threadIdx.x;
    if (i >= n4) return;
    float4 v = src[i];
    *(__half2*)(out + 4*i)     = __floats2half2_rn(v.x, v.y);
    *(__half2*)(out + 4*i + 2) = __floats2half2_rn(v.z, v.w);
}

// W [K, Nc] fp32 -> out [Nc, K] single fp16
__global__ void transpose_half(const float* __restrict__ W, __half* __restrict__ out,
                               int K, int Nc)
{
    __shared__ float t[32][33];
    int x  = blockIdx.x * 32 + threadIdx.x;
    int y0 = blockIdx.y * 32;
    #pragma unroll
    for (int j = 0; j < 32; j += 8)
        t[threadIdx.y + j][threadIdx.x] = W[(size_t)(y0 + threadIdx.y + j) * Nc + x];
    __syncthreads();
    int ox = y0 + threadIdx.x;
    int oy = blockIdx.x * 32;
    #pragma unroll
    for (int j = 0; j < 32; j += 8)
        out[(size_t)(oy + threadIdx.y + j) * K + ox] = __float2half(t[threadIdx.x][threadIdx.y + j]);
}

// ---------------- 1-term fp16 GEMM, BK=64, 3-stage pipeline, one-sync ----------------
// EPI 0: plain fp32 C (O projection). EPI 1: QKV fused rope/scale epilogue.
// Tile 128x128, BK=64 (128B rows, 144B stride: phase (9r+c)%8 conflict-free).
#define TB64  18432u              // 128 rows * 144B
#define ST64  (2u*TB64)           // A + B per stage = 36864
#define SM64  (3u*ST64)           // 3-stage = 110592

template<int EPI>
__global__ __launch_bounds__(256) void mma_gemm64(
    const __half* __restrict__ A, const __half* __restrict__ B,
    float* __restrict__ C,
    const float* __restrict__ rc, const float* __restrict__ rs,
    int Nc, int K)
{
    extern __shared__ __align__(128) char smem[];
    const uint32_t dbase = smem_u32(smem);
    const int tid   = threadIdx.x;
    const int lane  = tid & 31;
    const int wid   = tid >> 5;
    const int warpM = wid & 3;
    const int warpN = wid >> 2;

    const int rowBase = blockIdx.y * 128;
    const int colBase = blockIdx.x * 128;
    const int nChunks = K >> 6;    // BK = 64

    auto load_chunk = [&](int chunk, int stage) {
        const uint32_t sbase = dbase + (uint32_t)stage * ST64;
        const int k0 = chunk << 6;
        #pragma unroll
        for (int tile = 0; tile < 2; tile++) {
            const __half* s = tile ? B : A;
            const int gBase = tile ? colBase : rowBase;
            const uint32_t tb = sbase + (uint32_t)tile * TB64;
            #pragma unroll
            for (int i = 0; i < 4; i++) {
                int idx = tid + (i << 8);          // 0..1023
                int r = idx >> 3, c = idx & 7;     // row, 16B chunk (8 per 128B row)
                cp16(tb + (uint32_t)(r * 144 + c * 16),
                     s + (size_t)(gBase + r) * K + k0 + c * 8);
            }
        }
        asm volatile("cp.async.commit_group;" ::: "memory");
    };

    const uint32_t aoff = (uint32_t)((warpM * 32 + (lane & 15)) * 144 + (lane >> 4) * 16);
    const uint32_t boff = (uint32_t)((warpN * 64 + (lane & 7) + ((lane >> 4) << 3)) * 144
                                     + ((lane >> 3) & 1) * 16);

    float acc[2][8][4];
    #pragma unroll
    for (int mt = 0; mt < 2; mt++)
        #pragma unroll
        for (int nt = 0; nt < 8; nt++)
            #pragma unroll
            for (int e = 0; e < 4; e++) acc[mt][nt][e] = 0.f;

    // prologue: 2 stages in flight
    load_chunk(0, 0);
    load_chunk(1, 1);
    int st = 0;                   // stage of current chunk
    for (int chunk = 0; chunk < nChunks; chunk++) {
        // wait for this chunk's load; leave the next one in flight.
        if (chunk + 1 < nChunks) {
            asm volatile("cp.async.wait_group 1;" ::: "memory");
        } else {
            asm volatile("cp.async.wait_group 0;" ::: "memory");
        }
        // barrier publishes stage `st` AND proves compute on the stage about to
        // be overwritten (used 2 iterations ago) has drained in all warps.
        __syncthreads();
        if (chunk + 2 < nChunks) {
            int st2 = st + 2; if (st2 >= 3) st2 -= 3;
            load_chunk(chunk + 2, st2);   // overlaps compute below
        }

        const uint32_t sbase = dbase + (uint32_t)st * ST64;
        const uint32_t sA = sbase + aoff;
        const uint32_t sB = sbase + TB64 + boff;

        #pragma unroll
        for (int ks = 0; ks < 4; ks++) {           // 4 x 16-K steps = 64 K
            uint32_t ah[2][4];
            LDSM4(ah[0], sA + ks * 32);
            LDSM4(ah[1], sA + 16 * 144 + ks * 32);
            #pragma unroll
            for (int ntp = 0; ntp < 4; ntp++) {
                uint32_t bb[4];
                LDSM4(bb, sB + ntp * 16 * 144 + ks * 32);
                #pragma unroll
                for (int mt = 0; mt < 2; mt++) {
                    MMA16816F16(acc[mt][2*ntp],   ah[mt], bb[0], bb[1]);
                    MMA16816F16(acc[mt][2*ntp+1], ah[mt], bb[2], bb[3]);
                }
            }
        }
        if (++st == 3) st = 0;
    }

    // ---- epilogues ----
    #pragma unroll
    for (int mt = 0; mt < 2; mt++) {
        int row0 = rowBase + warpM * 32 + mt * 16 + (lane >> 2);
        #pragma unroll
        for (int nt = 0; nt < 8; nt++) {
            int col = colBase + warpN * 64 + nt * 8 + (lane & 3) * 2;

            if (EPI == 0) {
                *(float2*)(C + (size_t)row0 * Nc + col)       = make_float2(acc[mt][nt][0], acc[mt][nt][1]);
                *(float2*)(C + (size_t)(row0 + 8) * Nc + col) = make_float2(acc[mt][nt][2], acc[mt][nt][3]);
            } else {
                if (col < DIMX) {
                    // Q: rope + 0.125 scale -> single fp16
                    int h = col >> 6, dp = col & 63, p = dp >> 1;
                    #pragma unroll
                    for (int half = 0; half < 2; half++) {
                        int row = row0 + 8 * half;
                        int b = row >> 11, n = row & (NN - 1);
                        float c = rc[n * 32 + p], s = rs[n * 32 + p];
                        float e = acc[mt][nt][2*half]     * 0.125f;
                        float o = acc[mt][nt][2*half + 1] * 0.125f;
                        *(__half2*)(g_qb + ((size_t)(b * NH + h) * NN + n) * HD + dp) =
                            __floats2half2_rn(e * c - o * s, e * s + o * c);
                    }
                } else if (col < DIMX + NKV * HD) {
                    // K: rope -> single fp16
                    int kc = col - DIMX;
                    int h = kc >> 6, dp = kc & 63, p = dp >> 1;
                    #pragma unroll
                    for (int half = 0; half < 2; half++) {
                        int row = row0 + 8 * half;
                        int b = row >> 11, n = row & (NN - 1);
                        float c = rc[n * 32 + p], s = rs[n * 32 + p];
                        float e = acc[mt][nt][2*half];
                        float o = acc[mt][nt][2*half + 1];
                        *(__half2*)(g_kb + ((size_t)(b * NKV + h) * NN + n) * HD + dp) =
                            __floats2half2_rn(e * c - o * s, e * s + o * c);
                    }
                } else {
                    // V: compact fp16 [bh][n][64]
                    int vc = col - DIMX - NKV * HD;
                    int h = vc >> 6, d = vc & 63;
                    #pragma unroll
                    for (int half = 0; half < 2; half++) {
                        int row = row0 + 8 * half;
                        int b = row >> 11, n = row & (NN - 1);
                        *(__half2*)(g_v + ((size_t)(b * NKV + h) * NN + n) * HD + d) =
                            __floats2half2_rn(acc[mt][nt][2*half], acc[mt][nt][2*half + 1]);
                    }
                }
            }
        }
    }
}

// ---------------- tensor-core flash attention ----------------
// V consumed directly from [bh][key][d] via ldmatrix.trans (no transposed copy).
#define AST 144u
#define AQ_B  (128u*AST)          // 18432 q buffer
#define AK_B  (64u*AST)           // 9216 per tile
#define AKST  (2u*AK_B)           // 18432 per kv stage (K, V)
#define SM_Q  0u
#define SM_KV AQ_B
#define FLASH_SMEM (AQ_B + 2u*AKST)   // 55296 B

__global__ __launch_bounds__(256) void flash_attn_mma(
    const __half* __restrict__ Q,
    const __half* __restrict__ Kk, const __half* __restrict__ Vv)
{
    extern __shared__ __align__(128) char smem[];
    const uint32_t sb = smem_u32(smem);
    const int tid  = threadIdx.x;
    const int lane = tid & 31;
    const int wid  = tid >> 5;
    const int qb   = (int)gridDim.x - 1 - (int)blockIdx.x;   // heaviest tiles first
    const int head = blockIdx.y;
    const int b    = blockIdx.z;
    const int bhq  = b * NH + head;
    const int bhk  = b * NKV + (head & (NKV - 1));

    const __half* q  = Q  + ((size_t)bhq * NN + qb * 128) * HD;
    const __half* kk = Kk + (size_t)bhk * NN * HD;
    const __half* vv = Vv + (size_t)bhk * NN * HD;

    auto load_kv = [&](int kb, int st) {
        const uint32_t base = sb + SM_KV + (uint32_t)st * AKST;
        #pragma unroll
        for (int i = 0; i < 2; i++) {
            int idx = tid + (i << 8);
            int r = idx >> 3, c = idx & 7;
            uint32_t so = (uint32_t)(r * AST + c * 16);
            size_t g = ((size_t)(kb * 64 + r)) * HD + c * 8;   // same for K and V
            cp16(base + so,        kk + g);
            cp16(base + AK_B + so, vv + g);
        }
        asm volatile("cp.async.commit_group;" ::: "memory");
    };

    // ---- load Q + first KV tile ----
    #pragma unroll
    for (int i = 0; i < 4; i++) {
        int idx = tid + (i << 8);
        int r = idx >> 3, c = idx & 7;
        cp16(sb + SM_Q + (uint32_t)(r * AST + c * 16), q + (size_t)r * HD + c * 8);
    }
    asm volatile("cp.async.commit_group;" ::: "memory");
    load_kv(0, 0);
    asm volatile("cp.async.wait_group 0;" ::: "memory");
    __syncthreads();

    const uint32_t qoff = (uint32_t)((wid * 16 + (lane & 15)) * AST + (lane >> 4) * 16);
    uint32_t qf[4][4];
    #pragma unroll
    for (int ks = 0; ks < 4; ks++)
        LDSM4(qf[ks], sb + SM_Q + qoff + ks * 32);
    // no sync needed: Q smem region is never overwritten

    const uint32_t boff = (uint32_t)(((lane & 7) + ((lane >> 4) << 3)) * AST + ((lane >> 3) & 1) * 16);
    // trans-ldmatrix lane offset for V [key][d] tiles: row = lane&15 (key), col16B = lane>>4
    const uint32_t voff = (uint32_t)((lane & 15) * AST + (lane >> 4) * 16);

    float oacc[8][4];
    #pragma unroll
    for (int nt = 0; nt < 8; nt++)
        #pragma unroll
        for (int e = 0; e < 4; e++) oacc[nt][e] = 0.f;
    float m[2] = {-1e30f, -1e30f};
    float l[2] = {0.f, 0.f};

    const int r0 = qb * 128 + wid * 16 + (lane >> 2);
    const int kbmax = 2 * qb + 1;

    for (int kb = 0; kb <= kbmax; kb++) {
        const int st = kb & 1;
        if (kb > 0) {
            asm volatile("cp.async.wait_group 0;" ::: "memory");
            __syncthreads();
        }
        if (kb + 1 <= kbmax)
            load_kv(kb + 1, st ^ 1);    // overlaps compute below

        const uint32_t sk = sb + SM_KV + (uint32_t)st * AKST + boff;
        const uint32_t svb = sb + SM_KV + (uint32_t)st * AKST + AK_B;   // V tile base

        // ---- S = Q K^T (1-term fp16) ----
        float sacc[8][4];
        #pragma unroll
        for (int nt = 0; nt < 8; nt++)
            #pragma unroll
            for (int e = 0; e < 4; e++) sacc[nt][e] = 0.f;

        #pragma unroll
        for (int ks = 0; ks < 4; ks++) {
            #pragma unroll
            for (int kg = 0; kg < 4; kg++) {
                uint32_t kb_[4];
                LDSM4(kb_, sk + (uint32_t)(kg * 16 * AST) + ks * 32);
                MMA16816F16(sacc[2*kg],   qf[ks], kb_[0], kb_[1]);
                MMA16816F16(sacc[2*kg+1], qf[ks], kb_[2], kb_[3]);
            }
        }

        // ---- causal mask ----
        if (kb * 64 + 63 > r0) {
            #pragma unroll
            for (int nt = 0; nt < 8; nt++) {
                int c = kb * 64 + nt * 8 + (lane & 3) * 2;
                if (c > r0)         sacc[nt][0] = -1e30f;
                if (c + 1 > r0)     sacc[nt][1] = -1e30f;
                if (c > r0 + 8)     sacc[nt][2] = -1e30f;
                if (c + 1 > r0 + 8) sacc[nt][3] = -1e30f;
            }
        }

        // ---- online softmax ----
        float rmax[2] = {-1e30f, -1e30f};
        #pragma unroll
        for (int nt = 0; nt < 8; nt++) {
            rmax[0] = fmaxf(rmax[0], fmaxf(sacc[nt][0], sacc[nt][1]));
            rmax[1] = fmaxf(rmax[1], fmaxf(sacc[nt][2], sacc[nt][3]));
        }
        #pragma unroll
        for (int w = 1; w <= 2; w <<= 1) {
            rmax[0] = fmaxf(rmax[0], __shfl_xor_sync(0xffffffffu, rmax[0], w));
            rmax[1] = fmaxf(rmax[1], __shfl_xor_sync(0xffffffffu, rmax[1], w));
        }
        float nm0 = fmaxf(m[0], rmax[0]);
        float nm1 = fmaxf(m[1], rmax[1]);
        float c0 = __expf(m[0] - nm0);
        float c1 = __expf(m[1] - nm1);
        m[0] = nm0; m[1] = nm1;
        #pragma unroll
        for (int nt = 0; nt < 8; nt++) {
            oacc[nt][0] *= c0; oacc[nt][1] *= c0;
            oacc[nt][2] *= c1; oacc[nt][3] *= c1;
        }
        float sum0 = 0.f, sum1 = 0.f;
        uint32_t ph[8][2];
        #pragma unroll
        for (int nt = 0; nt < 8; nt++) {
            float p0 = __expf(sacc[nt][0] - nm0);
            float p1 = __expf(sacc[nt][1] - nm0);
            float p2 = __expf(sacc[nt][2] - nm1);
            float p3 = __expf(sacc[nt][3] - nm1);
            sum0 += p0 + p1; sum1 += p2 + p3;
            ph[nt][0] = pack_half(p0, p1);
            ph[nt][1] = pack_half(p2, p3);
        }
        #pragma unroll
        for (int w = 1; w <= 2; w <<= 1) {
            sum0 += __shfl_xor_sync(0xffffffffu, sum0, w);
            sum1 += __shfl_xor_sync(0xffffffffu, sum1, w);
        }
        l[0] = l[0] * c0 + sum0;
        l[1] = l[1] * c1 + sum1;

        // ---- O += P V (single fp16; V fragments via ldmatrix.trans) ----
        #pragma unroll
        for (int ks = 0; ks < 4; ks++) {
            uint32_t aph[4] = {ph[2*ks][0], ph[2*ks][1], ph[2*ks+1][0], ph[2*ks+1][1]};
            #pragma unroll
            for (int dg = 0; dg < 4; dg++) {
                uint32_t vb[4];
                LDSM4T(vb, svb + voff + (uint32_t)(ks * 16 * AST) + dg * 32);
                MMA16816F16(oacc[2*dg],   aph, vb[0], vb[1]);
                MMA16816F16(oacc[2*dg+1], aph, vb[2], vb[3]);
            }
        }
    }

    // ---- write O as single fp16 (O-proj A operand) ----
    float inv0 = 1.f / l[0];
    float inv1 = 1.f / l[1];
    size_t row = (size_t)(b * NN) + r0;
    #pragma unroll
    for (int nt = 0; nt < 8; nt++) {
        int col = head * HD + nt * 8 + (lane & 3) * 2;
        *(__half2*)(g_aht + row * DIMX + col) =
            __floats2half2_rn(oacc[nt][0] * inv0, oacc[nt][1] * inv0);
        *(__half2*)(g_aht + (row + 8) * DIMX + col) =
            __floats2half2_rn(oacc[nt][2] * inv1, oacc[nt][3] * inv1);
    }
}

// ---------------- launch ----------------
extern "C" void kernel_launch(void* const* d_in, const int* in_sizes, int n_in,
                              void* d_out, int out_size)
{
    const float* x   = (const float*)d_in[0];
    const float* Wq  = (const float*)d_in[1];
    const float* Wkv = (const float*)d_in[2];
    const float* Wo  = (const float*)d_in[3];
    const float* rc  = (const float*)d_in[4];
    const float* rs  = (const float*)d_in[5];
    float* out = (float*)d_out;

    __half *xh, *wqkvt, *woth, *aht, *qb, *kb, *v;
    cudaGetSymbolAddress((void**)&xh,    g_xh);
    cudaGetSymbolAddress((void**)&wqkvt, g_wqkvt);
    cudaGetSymbolAddress((void**)&woth,  g_woth);
    cudaGetSymbolAddress((void**)&aht,   g_aht);
    cudaGetSymbolAddress((void**)&qb,    g_qb);
    cudaGetSymbolAddress((void**)&kb,    g_kb);
    cudaGetSymbolAddress((void**)&v,     g_v);

    cudaFuncSetAttribute(mma_gemm64<0>, cudaFuncAttributeMaxDynamicSharedMemorySize, SM64);
    cudaFuncSetAttribute(mma_gemm64<1>, cudaFuncAttributeMaxDynamicSharedMemorySize, SM64);
    cudaFuncSetAttribute(flash_attn_mma, cudaFuncAttributeMaxDynamicSharedMemorySize, FLASH_SMEM);

    // 1. x -> single fp16
    int n4x = MM * DIMX / 4;
    cvt_half_kernel<<<(n4x + 255) / 256, 256>>>((const float4*)x, xh, n4x);

    // 2. weights: [Wq|Wkv] -> g_wqkvt; Wo -> g_woth
    transpose_half<<<dim3(DIMX / 32, DIMX / 32), dim3(32, 8)>>>(Wq,  wqkvt, DIMX, DIMX);
    transpose_half<<<dim3(KVW  / 32, DIMX / 32), dim3(32, 8)>>>(Wkv, wqkvt + (size_t)DIMX * DIMX, DIMX, KVW);
    transpose_half<<<dim3(DIMX / 32, DIMX / 32), dim3(32, 8)>>>(Wo,  woth, DIMX, DIMX);

    // 3. fused QKV projection (1-term fp16, BK=64, 3-stage, fused rope/scale epilogues)
    mma_gemm64<1><<<dim3(QKVW / 128, MM / 128), 256, SM64>>>(
        xh, wqkvt, nullptr, rc, rs, QKVW, DIMX);

    // 4. flash attention (V via ldmatrix.trans, no transpose pass)
    flash_attn_mma<<<dim3(NN / 128, NH, BB), 256, FLASH_SMEM>>>(qb, kb, v);

    // 5. output projection (1-term fp16, BK=64, 3-stage)
    mma_gemm64<0><<<dim3(DIMX / 128, MM / 128), 256, SM64>>>(
        aht, woth, out, nullptr, nullptr, DIMX, DIMX);
}